// round 3
// baseline (speedup 1.0000x reference)
#include <cuda_runtime.h>
#include <cuda_bf16.h>
#include <math.h>

// ---------------- problem constants ----------------
#define EPSBN 1e-3f
static const int NS_[3] = {40000, 20000, 8000};
static const int HS_[3] = {496, 248, 124};
static const int WS_[3] = {432, 216, 108};
#define BATCH 4
#define TPTS 32

#define HW0 (496*432)
#define HW1 (248*216)
#define HW2 (124*108)

// ---------------- device scratch (static, no runtime alloc) ----------------
__device__ float g_w1f[3*9*64];
__device__ float g_b1f[3*64];
__device__ float g_w2f[3*128*64];
__device__ float g_b2f[3*64];
__device__ float g_fwf[2*128*9*64];   // [layer][ic][k][oc] folded conv weights
__device__ float g_fbf[2*64];

__device__ float g_vf[40000*64];
__device__ int   g_win[BATCH*HW0];

__device__ float g_cat0[(size_t)BATCH*128*HW0];
__device__ float g_cat1[(size_t)BATCH*128*HW1];
__device__ float g_sf2 [(size_t)BATCH*64*HW2];
__device__ float g_f1  [(size_t)BATCH*64*HW1];

// ---------------- weight folding ----------------
__global__ void fold_kernel(const float* __restrict__ w1, const float* __restrict__ g1,
                            const float* __restrict__ b1, const float* __restrict__ rm1,
                            const float* __restrict__ rv1,
                            const float* __restrict__ w2, const float* __restrict__ g2,
                            const float* __restrict__ b2, const float* __restrict__ rm2,
                            const float* __restrict__ rv2,
                            const float* __restrict__ fw, const float* __restrict__ fg,
                            const float* __restrict__ fb, const float* __restrict__ fm,
                            const float* __restrict__ fv) {
    int idx = blockIdx.x * blockDim.x + threadIdx.x;
    if (idx < 1728) {
        int s = idx / 576; int d = idx % 64;
        float sc = g1[s*64+d] * rsqrtf(rv1[s*64+d] + EPSBN);
        g_w1f[idx] = w1[idx] * sc;
    }
    if (idx < 24576) {
        int s = idx / 8192; int d = idx % 64;
        float sc = g2[s*64+d] * rsqrtf(rv2[s*64+d] + EPSBN);
        g_w2f[idx] = w2[idx] * sc;
    }
    if (idx < 147456) {
        int l = idx / 73728; int r = idx % 73728;
        int ic = r / 576; int k = (r % 576) / 64; int oc = r % 64;
        float sc = fg[l*64+oc] * rsqrtf(fv[l*64+oc] + EPSBN);
        g_fwf[idx] = fw[(((size_t)(l*64+oc)*128 + ic)*9) + k] * sc;
    }
    if (idx < 192) {
        float sc1 = g1[idx] * rsqrtf(rv1[idx] + EPSBN);
        g_b1f[idx] = b1[idx] - rm1[idx] * sc1;
        float sc2 = g2[idx] * rsqrtf(rv2[idx] + EPSBN);
        g_b2f[idx] = b2[idx] - rm2[idx] * sc2;
    }
    if (idx < 128) {
        float sc = fg[idx] * rsqrtf(fv[idx] + EPSBN);
        g_fbf[idx] = fb[idx] - fm[idx] * sc;
    }
}

// ---------------- VFE: one block (64 threads) per voxel ----------------
__global__ void vfe_kernel(const float* __restrict__ voxels, const int* __restrict__ numpts,
                           const float* __restrict__ w1f, const float* __restrict__ b1f,
                           const float* __restrict__ w2f, const float* __restrict__ b2f,
                           float* __restrict__ vfout, int N) {
    __shared__ float w1s[576];
    __shared__ float w2s[8192];
    __shared__ float b1sm[64];
    __shared__ float b2sm[64];
    __shared__ float feat[288];    // [32][9]
    __shared__ float h1s[2048];    // [32][64]
    __shared__ float gmaxs[64];
    __shared__ float mean3[3];

    int v = blockIdx.x;
    if (v >= N) return;
    int t = threadIdx.x;  // 0..63

    for (int i = t; i < 576; i += 64)  w1s[i] = w1f[i];
    for (int i = t; i < 8192; i += 64) w2s[i] = w2f[i];
    if (t < 64) { b1sm[t] = b1f[t]; b2sm[t] = b2f[t]; }

    int np = numpts[v];

    float4 p = make_float4(0.f, 0.f, 0.f, 0.f);
    if (t < 32) {
        p = ((const float4*)voxels)[(size_t)v * TPTS + t];
        float sx = p.x, sy = p.y, sz = p.z;
        #pragma unroll
        for (int o = 16; o > 0; o >>= 1) {
            sx += __shfl_down_sync(0xffffffffu, sx, o);
            sy += __shfl_down_sync(0xffffffffu, sy, o);
            sz += __shfl_down_sync(0xffffffffu, sz, o);
        }
        if (t == 0) {
            float inv = 1.0f / (float)np;
            mean3[0] = sx * inv; mean3[1] = sy * inv; mean3[2] = sz * inv;
        }
    }
    __syncthreads();
    if (t < 32) {
        float mx = mean3[0], my = mean3[1], mz = mean3[2];
        float* f = &feat[t * 9];
        f[0] = p.x; f[1] = p.y; f[2] = p.z; f[3] = p.w;
        f[4] = p.x - mx; f[5] = p.y - my; f[6] = p.z - mz;
        f[7] = p.x - mx; f[8] = p.y - my;
    }
    __syncthreads();

    // layer 1 over ALL 32 points (unmasked, matches reference gmax semantics)
    int c = t;
    float b1v = b1sm[c];
    float gm = -1e30f;
    for (int tt = 0; tt < TPTS; tt++) {
        float a = b1v;
        #pragma unroll
        for (int k = 0; k < 9; k++) a = fmaf(feat[tt*9+k], w1s[k*64+c], a);
        a = fmaxf(a, 0.f);
        h1s[tt*64+c] = a;
        gm = fmaxf(gm, a);
    }
    gmaxs[c] = gm;
    __syncthreads();

    // gmax contribution of layer2 (constant over points)
    float gterm = b2sm[c];
    #pragma unroll 8
    for (int j = 0; j < 64; j++) gterm = fmaf(gmaxs[j], w2s[(64+j)*64+c], gterm);

    // layer 2 over valid points only; relu+mask+max == max-chain init 0
    float vmax = 0.f;
    int tt = 0;
    for (; tt + 4 <= np; tt += 4) {
        float a0 = gterm, a1 = gterm, a2 = gterm, a3 = gterm;
        const float* h0 = &h1s[tt*64];
        #pragma unroll 8
        for (int j = 0; j < 64; j++) {
            float w = w2s[j*64+c];
            a0 = fmaf(h0[j],       w, a0);
            a1 = fmaf(h0[64+j],    w, a1);
            a2 = fmaf(h0[128+j],   w, a2);
            a3 = fmaf(h0[192+j],   w, a3);
        }
        vmax = fmaxf(vmax, fmaxf(fmaxf(a0, a1), fmaxf(a2, a3)));
    }
    for (; tt < np; tt++) {
        float a = gterm;
        #pragma unroll 8
        for (int j = 0; j < 64; j++) a = fmaf(h1s[tt*64+j], w2s[j*64+c], a);
        vmax = fmaxf(vmax, a);
    }
    vfout[(size_t)v*64 + c] = vmax;
}

// ---------------- scatter ----------------
__global__ void fill_win_kernel(int* __restrict__ p, int n) {
    int i = blockIdx.x * blockDim.x + threadIdx.x;
    if (i < n) p[i] = -1;
}

__global__ void scatter_max_kernel(const int* __restrict__ coords, int* __restrict__ win,
                                   int N, int H, int W) {
    int v = blockIdx.x * blockDim.x + threadIdx.x;
    if (v >= N) return;
    int b = coords[v*4];
    int y = min(max(coords[v*4+2], 0), H-1);
    int x = min(max(coords[v*4+3], 0), W-1);
    atomicMax(&win[(b*H + y)*W + x], v);
}

__global__ void scatter_write_kernel(const int* __restrict__ coords, const int* __restrict__ win,
                                     const float* __restrict__ vf, float* __restrict__ dst,
                                     int H, int W, int CC) {
    int v = blockIdx.x;
    int c = threadIdx.x;  // 64
    int b = coords[v*4];
    int y = min(max(coords[v*4+2], 0), H-1);
    int x = min(max(coords[v*4+3], 0), W-1);
    if (win[(b*H + y)*W + x] != v) return;
    dst[((size_t)(b*CC + c)*H + y)*W + x] = vf[(size_t)v*64 + c];
}

// ---------------- zeroing ----------------
__global__ void zero_ch_kernel(float* __restrict__ base, size_t perBatchStride, size_t count, int nb) {
    size_t total = count * (size_t)nb;
    for (size_t i = (size_t)blockIdx.x * blockDim.x + threadIdx.x; i < total;
         i += (size_t)gridDim.x * blockDim.x) {
        size_t b = i / count;
        size_t off = i % count;
        base[b * perBatchStride + off] = 0.f;
    }
}

// ---------------- bilinear 2x upsample (jax half-pixel + edge renorm == clamp) ----------------
__global__ void upsample2x_kernel(const float* __restrict__ in, float* __restrict__ outbase,
                                  int Hi, int Wi, int Ho, int Wo, int outC, int chOff) {
    size_t total = (size_t)BATCH * 64 * Ho * Wo;
    for (size_t i = (size_t)blockIdx.x * blockDim.x + threadIdx.x; i < total;
         i += (size_t)gridDim.x * blockDim.x) {
        int x = (int)(i % Wo);
        int y = (int)((i / Wo) % Ho);
        int c = (int)((i / ((size_t)Wo * Ho)) % 64);
        int b = (int)(i / ((size_t)Wo * Ho * 64));
        float fy = fminf(fmaxf(y * 0.5f - 0.25f, 0.f), (float)(Hi - 1));
        float fx = fminf(fmaxf(x * 0.5f - 0.25f, 0.f), (float)(Wi - 1));
        int y0 = (int)fy; int x0 = (int)fx;
        float wy = fy - y0, wx = fx - x0;
        int y1 = min(y0 + 1, Hi - 1), x1 = min(x0 + 1, Wi - 1);
        const float* src = in + ((size_t)(b*64 + c) * Hi) * Wi;
        float v00 = src[(size_t)y0*Wi + x0], v01 = src[(size_t)y0*Wi + x1];
        float v10 = src[(size_t)y1*Wi + x0], v11 = src[(size_t)y1*Wi + x1];
        float val = (1.f-wy)*((1.f-wx)*v00 + wx*v01) + wy*((1.f-wx)*v10 + wx*v11);
        outbase[((size_t)(b*outC + chOff + c) * Ho + y) * Wo + x] = val;
    }
}

// ---------------- 3x3 conv 128->64 + folded BN + relu ----------------
__global__ __launch_bounds__(256, 2)
void conv3x3_kernel(const float* __restrict__ in, float* __restrict__ out,
                    int H, int W, const float* __restrict__ wfold, const float* __restrict__ bfold) {
    __shared__ float insm[8][18][18];
    __shared__ float wsm[8*9*64];

    int b = blockIdx.z;
    int ty0 = blockIdx.y * 16;
    int tx0 = blockIdx.x * 16;
    int t = threadIdx.x;
    int oc0 = (t & 15) * 4;
    int s = t >> 4;
    int sy0 = (s >> 2) * 4;
    int sx0 = (s & 3) * 4;

    float4 acc[16];
    #pragma unroll
    for (int u = 0; u < 16; u++) acc[u] = make_float4(0.f, 0.f, 0.f, 0.f);

    const float* inb = in + (size_t)b * 128 * H * W;

    for (int icb = 0; icb < 128; icb += 8) {
        __syncthreads();
        for (int i = t; i < 8*18*18; i += 256) {
            int ic = i / 324;
            int r = (i / 18) % 18;
            int cc = i % 18;
            int gy = ty0 + r - 1, gx = tx0 + cc - 1;
            float v = 0.f;
            if (gy >= 0 && gy < H && gx >= 0 && gx < W)
                v = inb[(size_t)(icb + ic) * H * W + (size_t)gy * W + gx];
            insm[ic][r][cc] = v;
        }
        const float* wsrc = wfold + (size_t)icb * 576;
        for (int i = t; i < 4608; i += 256) wsm[i] = wsrc[i];
        __syncthreads();

        for (int ic = 0; ic < 8; ic++) {
            #pragma unroll
            for (int ky = 0; ky < 3; ky++) {
                #pragma unroll
                for (int kx = 0; kx < 3; kx++) {
                    float4 w = *(const float4*)&wsm[(ic*9 + ky*3 + kx)*64 + oc0];
                    #pragma unroll
                    for (int uy = 0; uy < 4; uy++) {
                        #pragma unroll
                        for (int ux = 0; ux < 4; ux++) {
                            float iv = insm[ic][sy0+uy+ky][sx0+ux+kx];
                            float4& a = acc[uy*4+ux];
                            a.x = fmaf(w.x, iv, a.x);
                            a.y = fmaf(w.y, iv, a.y);
                            a.z = fmaf(w.z, iv, a.z);
                            a.w = fmaf(w.w, iv, a.w);
                        }
                    }
                }
            }
        }
    }

    float bias[4];
    #pragma unroll
    for (int j = 0; j < 4; j++) bias[j] = bfold[oc0 + j];
    int gx0 = tx0 + sx0;
    if (gx0 < W) {
        #pragma unroll
        for (int uy = 0; uy < 4; uy++) {
            int gy = ty0 + sy0 + uy;
            if (gy >= H) continue;
            #pragma unroll
            for (int j = 0; j < 4; j++) {
                float4 rowv;
                rowv.x = fmaxf(((const float*)&acc[uy*4+0])[j] + bias[j], 0.f);
                rowv.y = fmaxf(((const float*)&acc[uy*4+1])[j] + bias[j], 0.f);
                rowv.z = fmaxf(((const float*)&acc[uy*4+2])[j] + bias[j], 0.f);
                rowv.w = fmaxf(((const float*)&acc[uy*4+3])[j] + bias[j], 0.f);
                float* dst = out + ((size_t)(b*64 + oc0 + j) * H + gy) * W + gx0;
                *(float4*)dst = rowv;
            }
        }
    }
}

// ---------------- launch ----------------
extern "C" void kernel_launch(void* const* d_in, const int* in_sizes, int n_in,
                              void* d_out, int out_size) {
    (void)out_size;
    // Identify inputs by element count (robust to metadata ordering).
    const float* voxels[3] = {0,0,0};
    const int* numpts[3] = {0,0,0};
    const int* coordsp[3] = {0,0,0};
    const float *w1=0,*w2=0,*fw=0;
    const float* p192[8] = {0};
    const float* p128[4] = {0};
    int n192 = 0, n128 = 0;
    for (int i = 0; i < n_in; i++) {
        int sz = in_sizes[i];
        const void* p = d_in[i];
        switch (sz) {
            case 5120000: voxels[0] = (const float*)p; break;
            case 2560000: voxels[1] = (const float*)p; break;
            case 1024000: voxels[2] = (const float*)p; break;
            case 40000:   numpts[0] = (const int*)p; break;
            case 20000:   numpts[1] = (const int*)p; break;
            case 8000:    numpts[2] = (const int*)p; break;
            case 160000:  coordsp[0] = (const int*)p; break;
            case 80000:   coordsp[1] = (const int*)p; break;
            case 32000:   coordsp[2] = (const int*)p; break;
            case 1728:    w1 = (const float*)p; break;
            case 24576:   w2 = (const float*)p; break;
            case 147456:  fw = (const float*)p; break;
            case 192:     if (n192 < 8) p192[n192++] = (const float*)p; break;
            case 128:     if (n128 < 4) p128[n128++] = (const float*)p; break;
            default: break; // batch_size scalar
        }
    }
    // Relative order of equal-size params is g,b,rm,rv in both candidate orderings.
    const float *g1=p192[0], *b1=p192[1], *rm1=p192[2], *rv1=p192[3];
    const float *g2=p192[4], *b2=p192[5], *rm2=p192[6], *rv2=p192[7];
    const float *fg=p128[0], *fb=p128[1], *fm=p128[2], *fv=p128[3];

    float* cat0; cudaGetSymbolAddress((void**)&cat0, g_cat0);
    float* cat1; cudaGetSymbolAddress((void**)&cat1, g_cat1);
    float* sf2;  cudaGetSymbolAddress((void**)&sf2,  g_sf2);
    float* f1;   cudaGetSymbolAddress((void**)&f1,   g_f1);
    float* vf;   cudaGetSymbolAddress((void**)&vf,   g_vf);
    int*   win;  cudaGetSymbolAddress((void**)&win,  g_win);
    float* w1f;  cudaGetSymbolAddress((void**)&w1f,  g_w1f);
    float* b1f;  cudaGetSymbolAddress((void**)&b1f,  g_b1f);
    float* w2f;  cudaGetSymbolAddress((void**)&w2f,  g_w2f);
    float* b2f;  cudaGetSymbolAddress((void**)&b2f,  g_b2f);
    float* fwf;  cudaGetSymbolAddress((void**)&fwf,  g_fwf);
    float* fbf;  cudaGetSymbolAddress((void**)&fbf,  g_fbf);

    fold_kernel<<<576, 256>>>(w1, g1, b1, rm1, rv1, w2, g2, b2, rm2, rv2, fw, fg, fb, fm, fv);

    zero_ch_kernel<<<2048, 256>>>(cat0, (size_t)128*HW0, (size_t)64*HW0, BATCH);
    zero_ch_kernel<<<1024, 256>>>(cat1, (size_t)128*HW1, (size_t)64*HW1, BATCH);
    zero_ch_kernel<<<512, 256>>>(sf2, (size_t)BATCH*64*HW2, (size_t)BATCH*64*HW2, 1);

    float* dsts[3] = {cat0, cat1, sf2};
    int ccs[3] = {128, 128, 64};
    for (int s = 0; s < 3; s++) {
        int N = NS_[s], H = HS_[s], W = WS_[s];
        vfe_kernel<<<N, 64>>>(voxels[s], numpts[s], w1f + s*576, b1f + s*64,
                              w2f + s*8192, b2f + s*64, vf, N);
        int cells = BATCH * H * W;
        fill_win_kernel<<<(cells + 255)/256, 256>>>(win, cells);
        scatter_max_kernel<<<(N + 255)/256, 256>>>(coordsp[s], win, N, H, W);
        scatter_write_kernel<<<N, 64>>>(coordsp[s], win, vf, dsts[s], H, W, ccs[s]);
    }

    upsample2x_kernel<<<4096, 256>>>(sf2, cat1, 124, 108, 248, 216, 128, 64);

    {
        dim3 grid((216 + 15)/16, (248 + 15)/16, BATCH);
        conv3x3_kernel<<<grid, 256>>>(cat1, f1, 248, 216, fwf + 73728, fbf + 64);
    }

    upsample2x_kernel<<<8192, 256>>>(f1, cat0, 248, 216, 496, 432, 128, 64);

    {
        dim3 grid((432 + 15)/16, (496 + 15)/16, BATCH);
        conv3x3_kernel<<<grid, 256>>>(cat0, (float*)d_out, 496, 432, fwf, fbf);
    }
}

// round 4
// speedup vs baseline: 1.0010x; 1.0010x over previous
#include <cuda_runtime.h>
#include <cuda_bf16.h>
#include <math.h>

// ---------------- problem constants ----------------
#define EPSBN 1e-3f
static const int NS_[3] = {40000, 20000, 8000};
static const int HS_[3] = {496, 248, 124};
static const int WS_[3] = {432, 216, 108};
#define BATCH 4
#define TPTS 32

#define HW0 (496*432)
#define HW1 (248*216)
#define HW2 (124*108)

// ---------------- device scratch (static, no runtime alloc) ----------------
__device__ float g_w1f[3*9*64];
__device__ float g_b1f[3*64];
__device__ float g_w2f[3*128*64];
__device__ float g_b2f[3*64];
__device__ float g_fwf[2*128*9*64];   // [layer][ic][k][oc] folded conv weights
__device__ float g_fbf[2*64];

__device__ float g_vf[40000*64];
__device__ int   g_win[BATCH*HW0];

__device__ float g_cat0[(size_t)BATCH*128*HW0];
__device__ float g_cat1[(size_t)BATCH*128*HW1];
__device__ float g_sf2 [(size_t)BATCH*64*HW2];
__device__ float g_f1  [(size_t)BATCH*64*HW1];

// ---------------- weight folding ----------------
__global__ void fold_kernel(const float* __restrict__ w1, const float* __restrict__ g1,
                            const float* __restrict__ b1, const float* __restrict__ rm1,
                            const float* __restrict__ rv1,
                            const float* __restrict__ w2, const float* __restrict__ g2,
                            const float* __restrict__ b2, const float* __restrict__ rm2,
                            const float* __restrict__ rv2,
                            const float* __restrict__ fw, const float* __restrict__ fg,
                            const float* __restrict__ fb, const float* __restrict__ fm,
                            const float* __restrict__ fv) {
    int idx = blockIdx.x * blockDim.x + threadIdx.x;
    if (idx < 1728) {
        int s = idx / 576; int d = idx % 64;
        float sc = g1[s*64+d] * rsqrtf(rv1[s*64+d] + EPSBN);
        g_w1f[idx] = w1[idx] * sc;
    }
    if (idx < 24576) {
        int s = idx / 8192; int d = idx % 64;
        float sc = g2[s*64+d] * rsqrtf(rv2[s*64+d] + EPSBN);
        g_w2f[idx] = w2[idx] * sc;
    }
    if (idx < 147456) {
        int l = idx / 73728; int r = idx % 73728;
        int ic = r / 576; int k = (r % 576) / 64; int oc = r % 64;
        float sc = fg[l*64+oc] * rsqrtf(fv[l*64+oc] + EPSBN);
        g_fwf[idx] = fw[(((size_t)(l*64+oc)*128 + ic)*9) + k] * sc;
    }
    if (idx < 192) {
        float sc1 = g1[idx] * rsqrtf(rv1[idx] + EPSBN);
        g_b1f[idx] = b1[idx] - rm1[idx] * sc1;
        float sc2 = g2[idx] * rsqrtf(rv2[idx] + EPSBN);
        g_b2f[idx] = b2[idx] - rm2[idx] * sc2;
    }
    if (idx < 128) {
        float sc = fg[idx] * rsqrtf(fv[idx] + EPSBN);
        g_fbf[idx] = fb[idx] - fm[idx] * sc;
    }
}

// ---------------- VFE: one block (64 threads) per voxel ----------------
__global__ void vfe_kernel(const float* __restrict__ voxels, const int* __restrict__ numpts,
                           const float* __restrict__ w1f, const float* __restrict__ b1f,
                           const float* __restrict__ w2f, const float* __restrict__ b2f,
                           float* __restrict__ vfout, int N) {
    __shared__ float w1s[576];
    __shared__ float w2s[8192];
    __shared__ float b1sm[64];
    __shared__ float b2sm[64];
    __shared__ float feat[288];    // [32][9]
    __shared__ float h1s[2048];    // [32][64]
    __shared__ float gmaxs[64];
    __shared__ float mean3[3];

    int v = blockIdx.x;
    if (v >= N) return;
    int t = threadIdx.x;  // 0..63

    for (int i = t; i < 576; i += 64)  w1s[i] = w1f[i];
    for (int i = t; i < 8192; i += 64) w2s[i] = w2f[i];
    if (t < 64) { b1sm[t] = b1f[t]; b2sm[t] = b2f[t]; }

    int np = numpts[v];

    float4 p = make_float4(0.f, 0.f, 0.f, 0.f);
    if (t < 32) {
        p = ((const float4*)voxels)[(size_t)v * TPTS + t];
        float sx = p.x, sy = p.y, sz = p.z;
        #pragma unroll
        for (int o = 16; o > 0; o >>= 1) {
            sx += __shfl_down_sync(0xffffffffu, sx, o);
            sy += __shfl_down_sync(0xffffffffu, sy, o);
            sz += __shfl_down_sync(0xffffffffu, sz, o);
        }
        if (t == 0) {
            float inv = 1.0f / (float)np;
            mean3[0] = sx * inv; mean3[1] = sy * inv; mean3[2] = sz * inv;
        }
    }
    __syncthreads();
    if (t < 32) {
        float mx = mean3[0], my = mean3[1], mz = mean3[2];
        float* f = &feat[t * 9];
        f[0] = p.x; f[1] = p.y; f[2] = p.z; f[3] = p.w;
        f[4] = p.x - mx; f[5] = p.y - my; f[6] = p.z - mz;
        f[7] = p.x - mx; f[8] = p.y - my;
    }
    __syncthreads();

    // layer 1 over ALL 32 points (unmasked, matches reference gmax semantics)
    int c = t;
    float b1v = b1sm[c];
    float gm = -1e30f;
    for (int tt = 0; tt < TPTS; tt++) {
        float a = b1v;
        #pragma unroll
        for (int k = 0; k < 9; k++) a = fmaf(feat[tt*9+k], w1s[k*64+c], a);
        a = fmaxf(a, 0.f);
        h1s[tt*64+c] = a;
        gm = fmaxf(gm, a);
    }
    gmaxs[c] = gm;
    __syncthreads();

    // gmax contribution of layer2 (constant over points)
    float gterm = b2sm[c];
    #pragma unroll 8
    for (int j = 0; j < 64; j++) gterm = fmaf(gmaxs[j], w2s[(64+j)*64+c], gterm);

    // layer 2 over valid points only; relu+mask+max == max-chain init 0
    float vmax = 0.f;
    int tt = 0;
    for (; tt + 4 <= np; tt += 4) {
        float a0 = gterm, a1 = gterm, a2 = gterm, a3 = gterm;
        const float* h0 = &h1s[tt*64];
        #pragma unroll 8
        for (int j = 0; j < 64; j++) {
            float w = w2s[j*64+c];
            a0 = fmaf(h0[j],       w, a0);
            a1 = fmaf(h0[64+j],    w, a1);
            a2 = fmaf(h0[128+j],   w, a2);
            a3 = fmaf(h0[192+j],   w, a3);
        }
        vmax = fmaxf(vmax, fmaxf(fmaxf(a0, a1), fmaxf(a2, a3)));
    }
    for (; tt < np; tt++) {
        float a = gterm;
        #pragma unroll 8
        for (int j = 0; j < 64; j++) a = fmaf(h1s[tt*64+j], w2s[j*64+c], a);
        vmax = fmaxf(vmax, a);
    }
    vfout[(size_t)v*64 + c] = vmax;
}

// ---------------- scatter ----------------
__global__ void fill_win_kernel(int* __restrict__ p, int n) {
    int i = blockIdx.x * blockDim.x + threadIdx.x;
    if (i < n) p[i] = -1;
}

__global__ void scatter_max_kernel(const int* __restrict__ coords, int* __restrict__ win,
                                   int N, int H, int W) {
    int v = blockIdx.x * blockDim.x + threadIdx.x;
    if (v >= N) return;
    int b = coords[v*4];
    int y = min(max(coords[v*4+2], 0), H-1);
    int x = min(max(coords[v*4+3], 0), W-1);
    atomicMax(&win[(b*H + y)*W + x], v);
}

__global__ void scatter_write_kernel(const int* __restrict__ coords, const int* __restrict__ win,
                                     const float* __restrict__ vf, float* __restrict__ dst,
                                     int H, int W, int CC) {
    int v = blockIdx.x;
    int c = threadIdx.x;  // 64
    int b = coords[v*4];
    int y = min(max(coords[v*4+2], 0), H-1);
    int x = min(max(coords[v*4+3], 0), W-1);
    if (win[(b*H + y)*W + x] != v) return;
    dst[((size_t)(b*CC + c)*H + y)*W + x] = vf[(size_t)v*64 + c];
}

// ---------------- zeroing ----------------
__global__ void zero_ch_kernel(float* __restrict__ base, size_t perBatchStride, size_t count, int nb) {
    size_t total = count * (size_t)nb;
    for (size_t i = (size_t)blockIdx.x * blockDim.x + threadIdx.x; i < total;
         i += (size_t)gridDim.x * blockDim.x) {
        size_t b = i / count;
        size_t off = i % count;
        base[b * perBatchStride + off] = 0.f;
    }
}

// ---------------- bilinear 2x upsample (jax half-pixel + edge renorm == clamp) ----------------
__global__ void upsample2x_kernel(const float* __restrict__ in, float* __restrict__ outbase,
                                  int Hi, int Wi, int Ho, int Wo, int outC, int chOff) {
    size_t total = (size_t)BATCH * 64 * Ho * Wo;
    for (size_t i = (size_t)blockIdx.x * blockDim.x + threadIdx.x; i < total;
         i += (size_t)gridDim.x * blockDim.x) {
        int x = (int)(i % Wo);
        int y = (int)((i / Wo) % Ho);
        int c = (int)((i / ((size_t)Wo * Ho)) % 64);
        int b = (int)(i / ((size_t)Wo * Ho * 64));
        float fy = fminf(fmaxf(y * 0.5f - 0.25f, 0.f), (float)(Hi - 1));
        float fx = fminf(fmaxf(x * 0.5f - 0.25f, 0.f), (float)(Wi - 1));
        int y0 = (int)fy; int x0 = (int)fx;
        float wy = fy - y0, wx = fx - x0;
        int y1 = min(y0 + 1, Hi - 1), x1 = min(x0 + 1, Wi - 1);
        const float* src = in + ((size_t)(b*64 + c) * Hi) * Wi;
        float v00 = src[(size_t)y0*Wi + x0], v01 = src[(size_t)y0*Wi + x1];
        float v10 = src[(size_t)y1*Wi + x0], v11 = src[(size_t)y1*Wi + x1];
        float val = (1.f-wy)*((1.f-wx)*v00 + wx*v01) + wy*((1.f-wx)*v10 + wx*v11);
        outbase[((size_t)(b*outC + chOff + c) * Ho + y) * Wo + x] = val;
    }
}

// ---------------- 3x3 conv 128->64 + folded BN + relu ----------------
__global__ __launch_bounds__(256, 2)
void conv3x3_kernel(const float* __restrict__ in, float* __restrict__ out,
                    int H, int W, const float* __restrict__ wfold, const float* __restrict__ bfold) {
    __shared__ float insm[8][18][18];
    __shared__ float wsm[8*9*64];

    int b = blockIdx.z;
    int ty0 = blockIdx.y * 16;
    int tx0 = blockIdx.x * 16;
    int t = threadIdx.x;
    int oc0 = (t & 15) * 4;
    int s = t >> 4;
    int sy0 = (s >> 2) * 4;
    int sx0 = (s & 3) * 4;

    float4 acc[16];
    #pragma unroll
    for (int u = 0; u < 16; u++) acc[u] = make_float4(0.f, 0.f, 0.f, 0.f);

    const float* inb = in + (size_t)b * 128 * H * W;

    for (int icb = 0; icb < 128; icb += 8) {
        __syncthreads();
        for (int i = t; i < 8*18*18; i += 256) {
            int ic = i / 324;
            int r = (i / 18) % 18;
            int cc = i % 18;
            int gy = ty0 + r - 1, gx = tx0 + cc - 1;
            float v = 0.f;
            if (gy >= 0 && gy < H && gx >= 0 && gx < W)
                v = inb[(size_t)(icb + ic) * H * W + (size_t)gy * W + gx];
            insm[ic][r][cc] = v;
        }
        const float* wsrc = wfold + (size_t)icb * 576;
        for (int i = t; i < 4608; i += 256) wsm[i] = wsrc[i];
        __syncthreads();

        for (int ic = 0; ic < 8; ic++) {
            #pragma unroll
            for (int ky = 0; ky < 3; ky++) {
                #pragma unroll
                for (int kx = 0; kx < 3; kx++) {
                    float4 w = *(const float4*)&wsm[(ic*9 + ky*3 + kx)*64 + oc0];
                    #pragma unroll
                    for (int uy = 0; uy < 4; uy++) {
                        #pragma unroll
                        for (int ux = 0; ux < 4; ux++) {
                            float iv = insm[ic][sy0+uy+ky][sx0+ux+kx];
                            float4& a = acc[uy*4+ux];
                            a.x = fmaf(w.x, iv, a.x);
                            a.y = fmaf(w.y, iv, a.y);
                            a.z = fmaf(w.z, iv, a.z);
                            a.w = fmaf(w.w, iv, a.w);
                        }
                    }
                }
            }
        }
    }

    float bias[4];
    #pragma unroll
    for (int j = 0; j < 4; j++) bias[j] = bfold[oc0 + j];
    int gx0 = tx0 + sx0;
    if (gx0 < W) {
        #pragma unroll
        for (int uy = 0; uy < 4; uy++) {
            int gy = ty0 + sy0 + uy;
            if (gy >= H) continue;
            #pragma unroll
            for (int j = 0; j < 4; j++) {
                float4 rowv;
                rowv.x = fmaxf(((const float*)&acc[uy*4+0])[j] + bias[j], 0.f);
                rowv.y = fmaxf(((const float*)&acc[uy*4+1])[j] + bias[j], 0.f);
                rowv.z = fmaxf(((const float*)&acc[uy*4+2])[j] + bias[j], 0.f);
                rowv.w = fmaxf(((const float*)&acc[uy*4+3])[j] + bias[j], 0.f);
                float* dst = out + ((size_t)(b*64 + oc0 + j) * H + gy) * W + gx0;
                *(float4*)dst = rowv;
            }
        }
    }
}

// ---------------- launch ----------------
extern "C" void kernel_launch(void* const* d_in, const int* in_sizes, int n_in,
                              void* d_out, int out_size) {
    (void)out_size;
    // Identify inputs by element count (robust to metadata ordering).
    const float* voxels[3] = {0,0,0};
    const int* numpts[3] = {0,0,0};
    const int* coordsp[3] = {0,0,0};
    const float *w1=0,*w2=0,*fw=0;
    const float* p192[8] = {0};
    const float* p128[4] = {0};
    int n192 = 0, n128 = 0;
    for (int i = 0; i < n_in; i++) {
        int sz = in_sizes[i];
        const void* p = d_in[i];
        switch (sz) {
            case 5120000: voxels[0] = (const float*)p; break;
            case 2560000: voxels[1] = (const float*)p; break;
            case 1024000: voxels[2] = (const float*)p; break;
            case 40000:   numpts[0] = (const int*)p; break;
            case 20000:   numpts[1] = (const int*)p; break;
            case 8000:    numpts[2] = (const int*)p; break;
            case 160000:  coordsp[0] = (const int*)p; break;
            case 80000:   coordsp[1] = (const int*)p; break;
            case 32000:   coordsp[2] = (const int*)p; break;
            case 1728:    w1 = (const float*)p; break;
            case 24576:   w2 = (const float*)p; break;
            case 147456:  fw = (const float*)p; break;
            case 192:     if (n192 < 8) p192[n192++] = (const float*)p; break;
            case 128:     if (n128 < 4) p128[n128++] = (const float*)p; break;
            default: break; // batch_size scalar
        }
    }
    // Relative order of equal-size params is g,b,rm,rv in both candidate orderings.
    const float *g1=p192[0], *b1=p192[1], *rm1=p192[2], *rv1=p192[3];
    const float *g2=p192[4], *b2=p192[5], *rm2=p192[6], *rv2=p192[7];
    const float *fg=p128[0], *fb=p128[1], *fm=p128[2], *fv=p128[3];

    float* cat0; cudaGetSymbolAddress((void**)&cat0, g_cat0);
    float* cat1; cudaGetSymbolAddress((void**)&cat1, g_cat1);
    float* sf2;  cudaGetSymbolAddress((void**)&sf2,  g_sf2);
    float* f1;   cudaGetSymbolAddress((void**)&f1,   g_f1);
    float* vf;   cudaGetSymbolAddress((void**)&vf,   g_vf);
    int*   win;  cudaGetSymbolAddress((void**)&win,  g_win);
    float* w1f;  cudaGetSymbolAddress((void**)&w1f,  g_w1f);
    float* b1f;  cudaGetSymbolAddress((void**)&b1f,  g_b1f);
    float* w2f;  cudaGetSymbolAddress((void**)&w2f,  g_w2f);
    float* b2f;  cudaGetSymbolAddress((void**)&b2f,  g_b2f);
    float* fwf;  cudaGetSymbolAddress((void**)&fwf,  g_fwf);
    float* fbf;  cudaGetSymbolAddress((void**)&fbf,  g_fbf);

    fold_kernel<<<576, 256>>>(w1, g1, b1, rm1, rv1, w2, g2, b2, rm2, rv2, fw, fg, fb, fm, fv);

    zero_ch_kernel<<<2048, 256>>>(cat0, (size_t)128*HW0, (size_t)64*HW0, BATCH);
    zero_ch_kernel<<<1024, 256>>>(cat1, (size_t)128*HW1, (size_t)64*HW1, BATCH);
    zero_ch_kernel<<<512, 256>>>(sf2, (size_t)BATCH*64*HW2, (size_t)BATCH*64*HW2, 1);

    float* dsts[3] = {cat0, cat1, sf2};
    int ccs[3] = {128, 128, 64};
    for (int s = 0; s < 3; s++) {
        int N = NS_[s], H = HS_[s], W = WS_[s];
        vfe_kernel<<<N, 64>>>(voxels[s], numpts[s], w1f + s*576, b1f + s*64,
                              w2f + s*8192, b2f + s*64, vf, N);
        int cells = BATCH * H * W;
        fill_win_kernel<<<(cells + 255)/256, 256>>>(win, cells);
        scatter_max_kernel<<<(N + 255)/256, 256>>>(coordsp[s], win, N, H, W);
        scatter_write_kernel<<<N, 64>>>(coordsp[s], win, vf, dsts[s], H, W, ccs[s]);
    }

    upsample2x_kernel<<<4096, 256>>>(sf2, cat1, 124, 108, 248, 216, 128, 64);

    {
        dim3 grid((216 + 15)/16, (248 + 15)/16, BATCH);
        conv3x3_kernel<<<grid, 256>>>(cat1, f1, 248, 216, fwf + 73728, fbf + 64);
    }

    upsample2x_kernel<<<8192, 256>>>(f1, cat0, 248, 216, 496, 432, 128, 64);

    {
        dim3 grid((432 + 15)/16, (496 + 15)/16, BATCH);
        conv3x3_kernel<<<grid, 256>>>(cat0, (float*)d_out, 496, 432, fwf, fbf);
    }
}

// round 8
// speedup vs baseline: 1.6746x; 1.6730x over previous
#include <cuda_runtime.h>
#include <cuda_bf16.h>
#include <math.h>
#include <stdint.h>

#define EPSBN 1e-3f
static const int NS_[3] = {40000, 20000, 8000};
#define BATCH 4
#define TPTS 32
#define H0 496
#define W0 432
#define H1 248
#define W1 216
#define H2 124
#define W2 108
#define HW0 (H0*W0)
#define HW1 (H1*W1)
#define HW2 (H2*W2)
#define WP0 (W0+2)
#define Q0 ((H0+2)*WP0)
#define WP1 (W1+2)
#define Q1 ((H1+2)*WP1)
#define MR_F 512
#define MR_B 1024
#define P0 (MR_F + Q0 + MR_B)
#define P1 (MR_F + Q1 + MR_B)
#define PE0 ((size_t)P0*64)
#define PE1 ((size_t)P1*64)

__device__ float g_w1f[3*9*64];
__device__ float g_b1f[3*64];
__device__ float g_w2f[3*128*64];
__device__ float g_b2f[3*64];
__device__ float g_fbf[2*64];
__device__ unsigned char g_wimg[2*9*2*2*8192];
__device__ float g_vf[40000*64];
__device__ int   g_win[BATCH*HW0];
__device__ __nv_bfloat16 g_cat0t[16*PE0];
__device__ __nv_bfloat16 g_cat1t[16*PE1];
__device__ float g_sf2[(size_t)BATCH*64*HW2];
__device__ float g_f1 [(size_t)BATCH*64*HW1];

__device__ __forceinline__ void mma_bf16(float* c, const uint32_t* a, const uint32_t* b) {
    asm volatile("mma.sync.aligned.m16n8k16.row.col.f32.bf16.bf16.f32 "
                 "{%0,%1,%2,%3}, {%4,%5,%6,%7}, {%8,%9}, {%0,%1,%2,%3};"
                 : "+f"(c[0]), "+f"(c[1]), "+f"(c[2]), "+f"(c[3])
                 : "r"(a[0]), "r"(a[1]), "r"(a[2]), "r"(a[3]), "r"(b[0]), "r"(b[1]));
}
#define SWZ(o) ((o) ^ (((o) >> 3) & 0x70))

#define OFF_AHI 0
#define OFF_ALO 32768
#define OFF_BHI 65536
#define OFF_BLO 73728
#define CONV_SMEM 81920

__global__ void fold_kernel(const float* __restrict__ w1, const float* __restrict__ g1,
                            const float* __restrict__ b1, const float* __restrict__ rm1,
                            const float* __restrict__ rv1,
                            const float* __restrict__ w2, const float* __restrict__ g2,
                            const float* __restrict__ b2, const float* __restrict__ rm2,
                            const float* __restrict__ rv2,
                            const float* __restrict__ fw, const float* __restrict__ fg,
                            const float* __restrict__ fb, const float* __restrict__ fm,
                            const float* __restrict__ fv) {
    int idx = blockIdx.x * blockDim.x + threadIdx.x;
    if (idx < 1728) {
        int s = idx / 576; int d = idx % 64;
        g_w1f[idx] = w1[idx] * g1[s*64+d] * rsqrtf(rv1[s*64+d] + EPSBN);
    }
    if (idx < 24576) {
        int s = idx / 8192; int d = idx % 64;
        g_w2f[idx] = w2[idx] * g2[s*64+d] * rsqrtf(rv2[s*64+d] + EPSBN);
    }
    if (idx < 147456) {   // 2 layers x 64 oc x 128 ic x 9 taps; writes hi AND lo
        int l = idx / 73728; int r = idx % 73728;
        int oc = r / 1152; int rem = r % 1152;
        int ic = rem / 9; int tap = rem % 9;
        float sc = fg[l*64+oc] * rsqrtf(fv[l*64+oc] + EPSBN);
        float w = fw[(((size_t)(l*64+oc)*128 + ic)*9) + tap] * sc;
        __nv_bfloat16 hi = __float2bfloat16(w);
        __nv_bfloat16 lo = __float2bfloat16(w - __bfloat162float(hi));
        int chunk = ic >> 6, chl = ic & 63;
        size_t tb = (size_t)l*294912 + (size_t)((tap*2+chunk)*2)*8192;
        uint32_t so = SWZ((uint32_t)(oc*128 + chl*2));
        *(__nv_bfloat16*)(g_wimg + tb + so) = hi;
        *(__nv_bfloat16*)(g_wimg + tb + 8192 + so) = lo;
    }
    if (idx < 192) {
        g_b1f[idx] = b1[idx] - rm1[idx] * g1[idx] * rsqrtf(rv1[idx] + EPSBN);
        g_b2f[idx] = b2[idx] - rm2[idx] * g2[idx] * rsqrtf(rv2[idx] + EPSBN);
    }
    if (idx < 128) {
        g_fbf[idx] = fb[idx] - fm[idx] * fg[idx] * rsqrtf(fv[idx] + EPSBN);
    }
}

__global__ void vfe_kernel(const float* __restrict__ voxels, const int* __restrict__ numpts,
                           const float* __restrict__ w1f, const float* __restrict__ b1f,
                           const float* __restrict__ w2f, const float* __restrict__ b2f,
                           float* __restrict__ vfout, int N) {
    __shared__ float w1s[576], w2s[8192], b1sm[64], b2sm[64];
    __shared__ float feat[288], h1s[2048], gmaxs[64], mean3[3];
    int v = blockIdx.x;
    if (v >= N) return;
    int t = threadIdx.x;
    for (int i = t; i < 576; i += 64)  w1s[i] = w1f[i];
    for (int i = t; i < 8192; i += 64) w2s[i] = w2f[i];
    if (t < 64) { b1sm[t] = b1f[t]; b2sm[t] = b2f[t]; }
    int np = numpts[v];
    float4 p = make_float4(0.f,0.f,0.f,0.f);
    if (t < 32) {
        p = ((const float4*)voxels)[(size_t)v * TPTS + t];
        float sx = p.x, sy = p.y, sz = p.z;
        #pragma unroll
        for (int o = 16; o > 0; o >>= 1) {
            sx += __shfl_down_sync(0xffffffffu, sx, o);
            sy += __shfl_down_sync(0xffffffffu, sy, o);
            sz += __shfl_down_sync(0xffffffffu, sz, o);
        }
        if (t == 0) {
            float inv = 1.0f / (float)np;
            mean3[0] = sx*inv; mean3[1] = sy*inv; mean3[2] = sz*inv;
        }
    }
    __syncthreads();
    if (t < 32) {
        float mx = mean3[0], my = mean3[1], mz = mean3[2];
        float* f = &feat[t*9];
        f[0]=p.x; f[1]=p.y; f[2]=p.z; f[3]=p.w;
        f[4]=p.x-mx; f[5]=p.y-my; f[6]=p.z-mz; f[7]=p.x-mx; f[8]=p.y-my;
    }
    __syncthreads();
    int c = t;
    float b1v = b1sm[c], gm = -1e30f;
    for (int tt = 0; tt < TPTS; tt++) {
        float a = b1v;
        #pragma unroll
        for (int k = 0; k < 9; k++) a = fmaf(feat[tt*9+k], w1s[k*64+c], a);
        a = fmaxf(a, 0.f);
        h1s[tt*64+c] = a;
        gm = fmaxf(gm, a);
    }
    gmaxs[c] = gm;
    __syncthreads();
    float gterm = b2sm[c];
    #pragma unroll 8
    for (int j = 0; j < 64; j++) gterm = fmaf(gmaxs[j], w2s[(64+j)*64+c], gterm);
    float vmax = 0.f;
    int tt = 0;
    for (; tt + 4 <= np; tt += 4) {
        float a0=gterm,a1=gterm,a2=gterm,a3=gterm;
        const float* h0 = &h1s[tt*64];
        #pragma unroll 8
        for (int j = 0; j < 64; j++) {
            float w = w2s[j*64+c];
            a0 = fmaf(h0[j],w,a0); a1 = fmaf(h0[64+j],w,a1);
            a2 = fmaf(h0[128+j],w,a2); a3 = fmaf(h0[192+j],w,a3);
        }
        vmax = fmaxf(vmax, fmaxf(fmaxf(a0,a1), fmaxf(a2,a3)));
    }
    for (; tt < np; tt++) {
        float a = gterm;
        #pragma unroll 8
        for (int j = 0; j < 64; j++) a = fmaf(h1s[tt*64+j], w2s[j*64+c], a);
        vmax = fmaxf(vmax, a);
    }
    vfout[(size_t)v*64 + c] = vmax;
}

__global__ void fill_win_kernel(int* __restrict__ p, int n) {
    int i = blockIdx.x * blockDim.x + threadIdx.x;
    if (i < n) p[i] = -1;
}
__global__ void scatter_max_kernel(const int* __restrict__ coords, int* __restrict__ win,
                                   int N, int H, int W) {
    int v = blockIdx.x * blockDim.x + threadIdx.x;
    if (v >= N) return;
    int b = coords[v*4];
    int y = min(max(coords[v*4+2], 0), H-1);
    int x = min(max(coords[v*4+3], 0), W-1);
    atomicMax(&win[(b*H + y)*W + x], v);
}
__global__ void scatter_write_bf16(const int* __restrict__ coords, const int* __restrict__ win,
                                   const float* __restrict__ vf, __nv_bfloat16* __restrict__ cat,
                                   size_t PE, int H, int W, int Wp) {
    int v = blockIdx.x, c = threadIdx.x;
    int b = coords[v*4];
    int y = min(max(coords[v*4+2], 0), H-1);
    int x = min(max(coords[v*4+3], 0), W-1);
    if (win[(b*H + y)*W + x] != v) return;
    float val = vf[(size_t)v*64 + c];
    __nv_bfloat16 hi = __float2bfloat16(val);
    __nv_bfloat16 lo = __float2bfloat16(val - __bfloat162float(hi));
    size_t base = (size_t)(b*4)*PE + (size_t)MR_F*64 + (size_t)((y+1)*Wp + (x+1))*64 + c;
    cat[base] = hi;
    cat[base + PE] = lo;
}
__global__ void scatter_write_f32(const int* __restrict__ coords, const int* __restrict__ win,
                                  const float* __restrict__ vf, float* __restrict__ dst,
                                  int H, int W) {
    int v = blockIdx.x, c = threadIdx.x;
    int b = coords[v*4];
    int y = min(max(coords[v*4+2], 0), H-1);
    int x = min(max(coords[v*4+3], 0), W-1);
    if (win[(b*H + y)*W + x] != v) return;
    dst[((size_t)(b*64 + c)*H + y)*W + x] = vf[(size_t)v*64 + c];
}
__global__ void zero_u4(uint4* __restrict__ p, size_t n) {
    uint4 z = make_uint4(0,0,0,0);
    for (size_t i = (size_t)blockIdx.x*blockDim.x + threadIdx.x; i < n;
         i += (size_t)gridDim.x*blockDim.x) p[i] = z;
}

__global__ void ups_kernel(const float* __restrict__ src, __nv_bfloat16* __restrict__ cat,
                           size_t PE, int Hi, int Wi, int Ho, int Wo, int Wp) {
    __shared__ float s[2*64*67];
    int b = blockIdx.z, y = blockIdx.y;
    int X0 = blockIdx.x * 128;
    int t = threadIdx.x;
    float fy = fminf(fmaxf(y*0.5f - 0.25f, 0.f), (float)(Hi-1));
    int y0 = (int)fy; float wy = fy - y0;
    int y1 = min(y0+1, Hi-1);
    int xb = (int)fmaxf(X0*0.5f - 0.25f, 0.f);
    const float* sb = src + (size_t)b*64*Hi*Wi;
    for (int i = t; i < 2*64*66; i += 256) {
        int xi = i % 66, c = (i/66) % 64, r = i/(66*64);
        int gx = min(xb + xi, Wi-1);
        int gy = r ? y1 : y0;
        s[(r*64 + c)*67 + xi] = sb[((size_t)c*Hi + gy)*Wi + gx];
    }
    __syncthreads();
    int co = t & 63, xg = t >> 6;
    __nv_bfloat16* hiP = cat + (size_t)(4*b+2)*PE + (size_t)MR_F*64;
    __nv_bfloat16* loP = hiP + PE;
    for (int k = 0; k < 32; k++) {
        int xo = X0 + xg*32 + k;
        if (xo >= Wo) break;
        float fx = fminf(fmaxf(xo*0.5f - 0.25f, 0.f), (float)(Wi-1));
        int x0 = (int)fx; float wx = fx - x0;
        int xi = x0 - xb;
        float v0 = (1.f-wx)*s[co*67+xi]      + wx*s[co*67+xi+1];
        float v1 = (1.f-wx)*s[(64+co)*67+xi] + wx*s[(64+co)*67+xi+1];
        float val = (1.f-wy)*v0 + wy*v1;
        __nv_bfloat16 hi = __float2bfloat16(val);
        __nv_bfloat16 lo = __float2bfloat16(val - __bfloat162float(hi));
        size_t q = (size_t)(y+1)*Wp + (xo+1);
        hiP[q*64 + co] = hi;
        loP[q*64 + co] = lo;
    }
}

// HMMA conv: CTA = 256 rows x 64 oc; 8 warps x (32 rows x 64 oc); bf16 3-term split.
__global__ __launch_bounds__(256)
void conv_mma_kernel(const __nv_bfloat16* __restrict__ cat, size_t PE,
                     int Wp, int H, int W,
                     const uint4* __restrict__ wimg, const float* __restrict__ bias,
                     float* __restrict__ out) {
    extern __shared__ __align__(16) char sm[];
    int t = threadIdx.x, lane = t & 31, w = t >> 5;
    int b = blockIdx.y;
    int q0 = blockIdx.x * 256;
    const __nv_bfloat16* pl[2][2];
    #pragma unroll
    for (int c = 0; c < 2; c++)
        #pragma unroll
        for (int s = 0; s < 2; s++)
            pl[c][s] = cat + (size_t)(4*b + 2*c + s)*PE + (size_t)MR_F*64;

    float acc[2][8][4];
    #pragma unroll
    for (int mt = 0; mt < 2; mt++)
        #pragma unroll
        for (int nt = 0; nt < 8; nt++)
            #pragma unroll
            for (int k = 0; k < 4; k++) acc[mt][nt][k] = 0.f;

    int g = lane >> 2;
    int tg = lane & 3;

    for (int tap = 0; tap < 9; tap++) {
        int off = (tap/3 - 1)*Wp + (tap%3 - 1);
        for (int ch = 0; ch < 2; ch++) {
            __syncthreads();
            {
                const uint4* shi = (const uint4*)(pl[ch][0] + (long long)(q0 + off)*64);
                const uint4* slo = (const uint4*)(pl[ch][1] + (long long)(q0 + off)*64);
                for (int i = t; i < 2048; i += 256) {
                    int r = i >> 3, cb = i & 7;
                    uint32_t so = (uint32_t)(r*128 + ((cb ^ (r & 7)) << 4));
                    *(uint4*)(sm + OFF_AHI + so) = shi[i];
                    *(uint4*)(sm + OFF_ALO + so) = slo[i];
                }
                const uint4* ws = wimg + (size_t)((tap*2 + ch)*2)*512;
                for (int i = t; i < 512; i += 256) {
                    *(uint4*)(sm + OFF_BHI + i*16) = ws[i];
                    *(uint4*)(sm + OFF_BLO + i*16) = ws[512 + i];
                }
            }
            __syncthreads();
            #pragma unroll
            for (int ks = 0; ks < 4; ks++) {
                uint32_t aH[2][4], aL[2][4];
                #pragma unroll
                for (int mt = 0; mt < 2; mt++) {
                    int row0 = w*32 + mt*16 + g;
                    #pragma unroll
                    for (int j = 0; j < 4; j++) {
                        int row = row0 + (j & 1)*8;
                        int u = ks*2 + (j >> 1);
                        uint32_t addr = (uint32_t)(row*128 + ((u ^ (row & 7)) << 4) + tg*4);
                        aH[mt][j] = *(const uint32_t*)(sm + OFF_AHI + addr);
                        aL[mt][j] = *(const uint32_t*)(sm + OFF_ALO + addr);
                    }
                }
                uint32_t bHf[8][2], bLf[8][2];
                #pragma unroll
                for (int nt = 0; nt < 8; nt++) {
                    int n = nt*8 + g;
                    #pragma unroll
                    for (int j = 0; j < 2; j++) {
                        int u = ks*2 + j;
                        uint32_t addr = (uint32_t)(n*128 + ((u ^ (n & 7)) << 4) + tg*4);
                        bHf[nt][j] = *(const uint32_t*)(sm + OFF_BHI + addr);
                        bLf[nt][j] = *(const uint32_t*)(sm + OFF_BLO + addr);
                    }
                }
                #pragma unroll
                for (int mt = 0; mt < 2; mt++)
                    #pragma unroll
                    for (int nt = 0; nt < 8; nt++) {
                        mma_bf16(acc[mt][nt], aH[mt], bHf[nt]);
                        mma_bf16(acc[mt][nt], aL[mt], bHf[nt]);
                        mma_bf16(acc[mt][nt], aH[mt], bLf[nt]);
                    }
            }
        }
    }

    __syncthreads();
    float* smf = (float*)sm;
    #pragma unroll
    for (int mt = 0; mt < 2; mt++) {
        int rb = w*32 + mt*16 + g;
        #pragma unroll
        for (int nt = 0; nt < 8; nt++) {
            int cb = nt*8 + tg*2;
            smf[(cb+0)*257 + rb]     = acc[mt][nt][0];
            smf[(cb+1)*257 + rb]     = acc[mt][nt][1];
            smf[(cb+0)*257 + rb + 8] = acc[mt][nt][2];
            smf[(cb+1)*257 + rb + 8] = acc[mt][nt][3];
        }
    }
    __syncthreads();
    for (int i = t; i < 16384; i += 256) {
        int oc = i >> 8, r = i & 255;
        int q = q0 + r;
        int y = q / Wp, x = q % Wp;
        if (y >= 1 && y <= H && x >= 1 && x <= W)
            out[((size_t)(b*64 + oc)*H + (y-1))*W + (x-1)] =
                fmaxf(smf[oc*257 + r] + bias[oc], 0.f);
    }
}

extern "C" void kernel_launch(void* const* d_in, const int* in_sizes, int n_in,
                              void* d_out, int out_size) {
    (void)out_size;
    const float* voxels[3] = {0,0,0};
    const int* numpts[3] = {0,0,0};
    const int* coordsp[3] = {0,0,0};
    const float *w1=0,*w2=0,*fw=0;
    const float* p192[8] = {0};
    const float* p128[4] = {0};
    int n192 = 0, n128 = 0;
    for (int i = 0; i < n_in; i++) {
        int sz = in_sizes[i];
        const void* p = d_in[i];
        switch (sz) {
            case 5120000: voxels[0] = (const float*)p; break;
            case 2560000: voxels[1] = (const float*)p; break;
            case 1024000: voxels[2] = (const float*)p; break;
            case 40000:   numpts[0] = (const int*)p; break;
            case 20000:   numpts[1] = (const int*)p; break;
            case 8000:    numpts[2] = (const int*)p; break;
            case 160000:  coordsp[0] = (const int*)p; break;
            case 80000:   coordsp[1] = (const int*)p; break;
            case 32000:   coordsp[2] = (const int*)p; break;
            case 1728:    w1 = (const float*)p; break;
            case 24576:   w2 = (const float*)p; break;
            case 147456:  fw = (const float*)p; break;
            case 192:     if (n192 < 8) p192[n192++] = (const float*)p; break;
            case 128:     if (n128 < 4) p128[n128++] = (const float*)p; break;
            default: break;
        }
    }
    const float *g1=p192[0], *b1=p192[1], *rm1=p192[2], *rv1=p192[3];
    const float *g2=p192[4], *b2=p192[5], *rm2=p192[6], *rv2=p192[7];
    const float *fg=p128[0], *fb=p128[1], *fm=p128[2], *fv=p128[3];

    __nv_bfloat16 *cat0, *cat1;
    cudaGetSymbolAddress((void**)&cat0, g_cat0t);
    cudaGetSymbolAddress((void**)&cat1, g_cat1t);
    float *sf2, *f1, *vf, *w1f, *b1f, *w2f, *b2f, *fbf;
    int* win;
    unsigned char* wimg;
    cudaGetSymbolAddress((void**)&sf2, g_sf2);
    cudaGetSymbolAddress((void**)&f1,  g_f1);
    cudaGetSymbolAddress((void**)&vf,  g_vf);
    cudaGetSymbolAddress((void**)&win, g_win);
    cudaGetSymbolAddress((void**)&w1f, g_w1f);
    cudaGetSymbolAddress((void**)&b1f, g_b1f);
    cudaGetSymbolAddress((void**)&w2f, g_w2f);
    cudaGetSymbolAddress((void**)&b2f, g_b2f);
    cudaGetSymbolAddress((void**)&fbf, g_fbf);
    cudaGetSymbolAddress((void**)&wimg, g_wimg);

    cudaFuncSetAttribute(conv_mma_kernel, cudaFuncAttributeMaxDynamicSharedMemorySize, CONV_SMEM);

    fold_kernel<<<1152, 256>>>(w1, g1, b1, rm1, rv1, w2, g2, b2, rm2, rv2, fw, fg, fb, fm, fv);

    zero_u4<<<4096, 256>>>((uint4*)cat0, (size_t)2*PE0);
    zero_u4<<<2048, 256>>>((uint4*)cat1, (size_t)2*PE1);
    zero_u4<<<512, 256>>>((uint4*)sf2, (size_t)BATCH*64*HW2/4);

    vfe_kernel<<<NS_[0], 64>>>(voxels[0], numpts[0], w1f, b1f, w2f, b2f, vf, NS_[0]);
    fill_win_kernel<<<(BATCH*HW0 + 255)/256, 256>>>(win, BATCH*HW0);
    scatter_max_kernel<<<(NS_[0] + 255)/256, 256>>>(coordsp[0], win, NS_[0], H0, W0);
    scatter_write_bf16<<<NS_[0], 64>>>(coordsp[0], win, vf, cat0, PE0, H0, W0, WP0);

    vfe_kernel<<<NS_[1], 64>>>(voxels[1], numpts[1], w1f + 576, b1f + 64, w2f + 8192, b2f + 64, vf, NS_[1]);
    fill_win_kernel<<<(BATCH*HW1 + 255)/256, 256>>>(win, BATCH*HW1);
    scatter_max_kernel<<<(NS_[1] + 255)/256, 256>>>(coordsp[1], win, NS_[1], H1, W1);
    scatter_write_bf16<<<NS_[1], 64>>>(coordsp[1], win, vf, cat1, PE1, H1, W1, WP1);

    vfe_kernel<<<NS_[2], 64>>>(voxels[2], numpts[2], w1f + 1152, b1f + 128, w2f + 16384, b2f + 128, vf, NS_[2]);
    fill_win_kernel<<<(BATCH*HW2 + 255)/256, 256>>>(win, BATCH*HW2);
    scatter_max_kernel<<<(NS_[2] + 255)/256, 256>>>(coordsp[2], win, NS_[2], H2, W2);
    scatter_write_f32<<<NS_[2], 64>>>(coordsp[2], win, vf, sf2, H2, W2);

    {
        dim3 g((W1 + 127)/128, H1, BATCH);
        ups_kernel<<<g, 256>>>(sf2, cat1, PE1, H2, W2, H1, W1, WP1);
    }
    {
        dim3 g((Q1 + 255)/256, BATCH);
        conv_mma_kernel<<<g, 256, CONV_SMEM>>>(cat1, PE1, WP1, H1, W1,
            (const uint4*)(wimg + 294912), fbf + 64, f1);
    }
    {
        dim3 g((W0 + 127)/128, H0, BATCH);
        ups_kernel<<<g, 256>>>(f1, cat0, PE0, H1, W1, H0, W0, WP0);
    }
    {
        dim3 g((Q0 + 255)/256, BATCH);
        conv_mma_kernel<<<g, 256, CONV_SMEM>>>(cat0, PE0, WP0, H0, W0,
            (const uint4*)wimg, fbf, (float*)d_out);
    }
}

// round 10
// speedup vs baseline: 1.9628x; 1.1720x over previous
#include <cuda_runtime.h>
#include <cuda_bf16.h>
#include <math.h>
#include <stdint.h>

#define EPSBN 1e-3f
static const int NS_[3] = {40000, 20000, 8000};
#define BATCH 4
#define TPTS 32
#define H0 496
#define W0 432
#define H1 248
#define W1 216
#define H2 124
#define W2 108
#define HW0 (H0*W0)
#define HW1 (H1*W1)
#define HW2 (H2*W2)
#define WP0 (W0+2)
#define Q0 ((H0+2)*WP0)
#define WP1 (W1+2)
#define Q1 ((H1+2)*WP1)
#define MR_F 512
#define MR_B 1024
#define P0 (MR_F + Q0 + MR_B)
#define P1 (MR_F + Q1 + MR_B)
#define PE0 ((size_t)P0*64)
#define PE1 ((size_t)P1*64)

__device__ float g_w1f[3*9*64];
__device__ float g_b1f[3*64];
__device__ float g_w2f[3*128*64];
__device__ float g_b2f[3*64];
__device__ float g_fbf[2*64];
__device__ unsigned char g_wimg[2*9*2*2*8192];
__device__ float g_vf[40000*64];
__device__ int   g_win[BATCH*HW0];
__device__ __nv_bfloat16 g_cat0t[16*PE0];
__device__ __nv_bfloat16 g_cat1t[16*PE1];
__device__ float g_sf2[(size_t)BATCH*64*HW2];
__device__ float g_f1 [(size_t)BATCH*64*HW1];

__device__ __forceinline__ uint32_t smem_u32(const void* p) {
    uint32_t a;
    asm("{ .reg .u64 t; cvta.to.shared.u64 t, %1; cvt.u32.u64 %0, t; }" : "=r"(a) : "l"(p));
    return a;
}
__device__ __forceinline__ void mma_bf16(float* c, const uint32_t* a, const uint32_t* b) {
    asm volatile("mma.sync.aligned.m16n8k16.row.col.f32.bf16.bf16.f32 "
                 "{%0,%1,%2,%3}, {%4,%5,%6,%7}, {%8,%9}, {%0,%1,%2,%3};"
                 : "+f"(c[0]), "+f"(c[1]), "+f"(c[2]), "+f"(c[3])
                 : "r"(a[0]), "r"(a[1]), "r"(a[2]), "r"(a[3]), "r"(b[0]), "r"(b[1]));
}
__device__ __forceinline__ void ldm_x4(uint32_t* r, uint32_t addr) {
    asm volatile("ldmatrix.sync.aligned.m8n8.x4.shared.b16 {%0,%1,%2,%3}, [%4];"
                 : "=r"(r[0]), "=r"(r[1]), "=r"(r[2]), "=r"(r[3]) : "r"(addr));
}
__device__ __forceinline__ void cp16(uint32_t d, const void* s) {
    asm volatile("cp.async.cg.shared.global [%0], [%1], 16;" :: "r"(d), "l"(s));
}
#define CP_COMMIT() asm volatile("cp.async.commit_group;" ::: "memory")
#define CP_WAIT1()  asm volatile("cp.async.wait_group 1;" ::: "memory")
#define CP_WAIT0()  asm volatile("cp.async.wait_group 0;" ::: "memory")
#define SWZ(o) ((o) ^ (((o) >> 3) & 0x70))

#define OFF_AHI 0
#define OFF_ALO 32768
#define OFF_BHI 65536
#define OFF_BLO 73728
#define STAGE_BYTES 81920
#define CONV_SMEM (2*STAGE_BYTES)

__global__ void fold_kernel(const float* __restrict__ w1, const float* __restrict__ g1,
                            const float* __restrict__ b1, const float* __restrict__ rm1,
                            const float* __restrict__ rv1,
                            const float* __restrict__ w2, const float* __restrict__ g2,
                            const float* __restrict__ b2, const float* __restrict__ rm2,
                            const float* __restrict__ rv2,
                            const float* __restrict__ fw, const float* __restrict__ fg,
                            const float* __restrict__ fb, const float* __restrict__ fm,
                            const float* __restrict__ fv) {
    int idx = blockIdx.x * blockDim.x + threadIdx.x;
    if (idx < 1728) {
        int s = idx / 576; int d = idx % 64;
        g_w1f[idx] = w1[idx] * g1[s*64+d] * rsqrtf(rv1[s*64+d] + EPSBN);
    }
    if (idx < 24576) {
        int s = idx / 8192; int d = idx % 64;
        g_w2f[idx] = w2[idx] * g2[s*64+d] * rsqrtf(rv2[s*64+d] + EPSBN);
    }
    if (idx < 147456) {
        int l = idx / 73728; int r = idx % 73728;
        int oc = r / 1152; int rem = r % 1152;
        int ic = rem / 9; int tap = rem % 9;
        float sc = fg[l*64+oc] * rsqrtf(fv[l*64+oc] + EPSBN);
        float w = fw[(((size_t)(l*64+oc)*128 + ic)*9) + tap] * sc;
        __nv_bfloat16 hi = __float2bfloat16(w);
        __nv_bfloat16 lo = __float2bfloat16(w - __bfloat162float(hi));
        int chunk = ic >> 6, chl = ic & 63;
        size_t tb = (size_t)l*294912 + (size_t)((tap*2+chunk)*2)*8192;
        uint32_t so = SWZ((uint32_t)(oc*128 + chl*2));
        *(__nv_bfloat16*)(g_wimg + tb + so) = hi;
        *(__nv_bfloat16*)(g_wimg + tb + 8192 + so) = lo;
    }
    if (idx < 192) {
        g_b1f[idx] = b1[idx] - rm1[idx] * g1[idx] * rsqrtf(rv1[idx] + EPSBN);
        g_b2f[idx] = b2[idx] - rm2[idx] * g2[idx] * rsqrtf(rv2[idx] + EPSBN);
    }
    if (idx < 128) {
        g_fbf[idx] = fb[idx] - fm[idx] * fg[idx] * rsqrtf(fv[idx] + EPSBN);
    }
}

__global__ void vfe_kernel(const float* __restrict__ voxels, const int* __restrict__ numpts,
                           const float* __restrict__ w1f, const float* __restrict__ b1f,
                           const float* __restrict__ w2f, const float* __restrict__ b2f,
                           float* __restrict__ vfout, int N) {
    __shared__ float w1s[576], w2s[8192], b1sm[64], b2sm[64];
    __shared__ float feat[288], h1s[2048], gmaxs[64], mean3[3];
    int v = blockIdx.x;
    if (v >= N) return;
    int t = threadIdx.x;
    for (int i = t; i < 576; i += 64)  w1s[i] = w1f[i];
    for (int i = t; i < 8192; i += 64) w2s[i] = w2f[i];
    if (t < 64) { b1sm[t] = b1f[t]; b2sm[t] = b2f[t]; }
    int np = numpts[v];
    float4 p = make_float4(0.f,0.f,0.f,0.f);
    if (t < 32) {
        p = ((const float4*)voxels)[(size_t)v * TPTS + t];
        float sx = p.x, sy = p.y, sz = p.z;
        #pragma unroll
        for (int o = 16; o > 0; o >>= 1) {
            sx += __shfl_down_sync(0xffffffffu, sx, o);
            sy += __shfl_down_sync(0xffffffffu, sy, o);
            sz += __shfl_down_sync(0xffffffffu, sz, o);
        }
        if (t == 0) {
            float inv = 1.0f / (float)np;
            mean3[0] = sx*inv; mean3[1] = sy*inv; mean3[2] = sz*inv;
        }
    }
    __syncthreads();
    if (t < 32) {
        float mx = mean3[0], my = mean3[1], mz = mean3[2];
        float* f = &feat[t*9];
        f[0]=p.x; f[1]=p.y; f[2]=p.z; f[3]=p.w;
        f[4]=p.x-mx; f[5]=p.y-my; f[6]=p.z-mz; f[7]=p.x-mx; f[8]=p.y-my;
    }
    __syncthreads();
    int c = t;
    float b1v = b1sm[c], gm = -1e30f;
    for (int tt = 0; tt < TPTS; tt++) {
        float a = b1v;
        #pragma unroll
        for (int k = 0; k < 9; k++) a = fmaf(feat[tt*9+k], w1s[k*64+c], a);
        a = fmaxf(a, 0.f);
        h1s[tt*64+c] = a;
        gm = fmaxf(gm, a);
    }
    gmaxs[c] = gm;
    __syncthreads();
    float gterm = b2sm[c];
    #pragma unroll 8
    for (int j = 0; j < 64; j++) gterm = fmaf(gmaxs[j], w2s[(64+j)*64+c], gterm);
    float vmax = 0.f;
    int tt = 0;
    for (; tt + 4 <= np; tt += 4) {
        float a0=gterm,a1=gterm,a2=gterm,a3=gterm;
        const float* h0 = &h1s[tt*64];
        #pragma unroll 8
        for (int j = 0; j < 64; j++) {
            float w = w2s[j*64+c];
            a0 = fmaf(h0[j],w,a0); a1 = fmaf(h0[64+j],w,a1);
            a2 = fmaf(h0[128+j],w,a2); a3 = fmaf(h0[192+j],w,a3);
        }
        vmax = fmaxf(vmax, fmaxf(fmaxf(a0,a1), fmaxf(a2,a3)));
    }
    for (; tt < np; tt++) {
        float a = gterm;
        #pragma unroll 8
        for (int j = 0; j < 64; j++) a = fmaf(h1s[tt*64+j], w2s[j*64+c], a);
        vmax = fmaxf(vmax, a);
    }
    vfout[(size_t)v*64 + c] = vmax;
}

__global__ void fill_win_kernel(int* __restrict__ p, int n) {
    int i = blockIdx.x * blockDim.x + threadIdx.x;
    if (i < n) p[i] = -1;
}
__global__ void scatter_max_kernel(const int* __restrict__ coords, int* __restrict__ win,
                                   int N, int H, int W) {
    int v = blockIdx.x * blockDim.x + threadIdx.x;
    if (v >= N) return;
    int b = coords[v*4];
    int y = min(max(coords[v*4+2], 0), H-1);
    int x = min(max(coords[v*4+3], 0), W-1);
    atomicMax(&win[(b*H + y)*W + x], v);
}
__global__ void scatter_write_bf16(const int* __restrict__ coords, const int* __restrict__ win,
                                   const float* __restrict__ vf, __nv_bfloat16* __restrict__ cat,
                                   size_t PE, int H, int W, int Wp) {
    int v = blockIdx.x, c = threadIdx.x;
    int b = coords[v*4];
    int y = min(max(coords[v*4+2], 0), H-1);
    int x = min(max(coords[v*4+3], 0), W-1);
    if (win[(b*H + y)*W + x] != v) return;
    float val = vf[(size_t)v*64 + c];
    __nv_bfloat16 hi = __float2bfloat16(val);
    __nv_bfloat16 lo = __float2bfloat16(val - __bfloat162float(hi));
    size_t base = (size_t)(b*4)*PE + (size_t)MR_F*64 + (size_t)((y+1)*Wp + (x+1))*64 + c;
    cat[base] = hi;
    cat[base + PE] = lo;
}
__global__ void scatter_write_f32(const int* __restrict__ coords, const int* __restrict__ win,
                                  const float* __restrict__ vf, float* __restrict__ dst,
                                  int H, int W) {
    int v = blockIdx.x, c = threadIdx.x;
    int b = coords[v*4];
    int y = min(max(coords[v*4+2], 0), H-1);
    int x = min(max(coords[v*4+3], 0), W-1);
    if (win[(b*H + y)*W + x] != v) return;
    dst[((size_t)(b*64 + c)*H + y)*W + x] = vf[(size_t)v*64 + c];
}
__global__ void zero_u4(uint4* __restrict__ p, size_t n) {
    uint4 z = make_uint4(0,0,0,0);
    for (size_t i = (size_t)blockIdx.x*blockDim.x + threadIdx.x; i < n;
         i += (size_t)gridDim.x*blockDim.x) p[i] = z;
}

__global__ void ups_kernel(const float* __restrict__ src, __nv_bfloat16* __restrict__ cat,
                           size_t PE, int Hi, int Wi, int Ho, int Wo, int Wp) {
    __shared__ float s[2*64*67];
    int b = blockIdx.z, y = blockIdx.y;
    int X0 = blockIdx.x * 128;
    int t = threadIdx.x;
    float fy = fminf(fmaxf(y*0.5f - 0.25f, 0.f), (float)(Hi-1));
    int y0 = (int)fy; float wy = fy - y0;
    int y1 = min(y0+1, Hi-1);
    int xb = (int)fmaxf(X0*0.5f - 0.25f, 0.f);
    const float* sb = src + (size_t)b*64*Hi*Wi;
    for (int i = t; i < 2*64*66; i += 256) {
        int xi = i % 66, c = (i/66) % 64, r = i/(66*64);
        int gx = min(xb + xi, Wi-1);
        int gy = r ? y1 : y0;
        s[(r*64 + c)*67 + xi] = sb[((size_t)c*Hi + gy)*Wi + gx];
    }
    __syncthreads();
    int co = t & 63, xg = t >> 6;
    __nv_bfloat16* hiP = cat + (size_t)(4*b+2)*PE + (size_t)MR_F*64;
    __nv_bfloat16* loP = hiP + PE;
    for (int k = 0; k < 32; k++) {
        int xo = X0 + xg*32 + k;
        if (xo >= Wo) break;
        float fx = fminf(fmaxf(xo*0.5f - 0.25f, 0.f), (float)(Wi-1));
        int x0 = (int)fx; float wx = fx - x0;
        int xi = x0 - xb;
        float v0 = (1.f-wx)*s[co*67+xi]      + wx*s[co*67+xi+1];
        float v1 = (1.f-wx)*s[(64+co)*67+xi] + wx*s[(64+co)*67+xi+1];
        float val = (1.f-wy)*v0 + wy*v1;
        __nv_bfloat16 hi = __float2bfloat16(val);
        __nv_bfloat16 lo = __float2bfloat16(val - __bfloat162float(hi));
        size_t q = (size_t)(y+1)*Wp + (xo+1);
        hiP[q*64 + co] = hi;
        loP[q*64 + co] = lo;
    }
}

// Pipelined HMMA conv: 512 threads, 16 warps x (16 rows x 64 oc); cp.async 2-stage; ldmatrix frags
__global__ __launch_bounds__(512)
void conv_mma_kernel(const __nv_bfloat16* __restrict__ cat, size_t PE,
                     int Wp, int H, int W,
                     const uint4* __restrict__ wimg, const float* __restrict__ bias,
                     float* __restrict__ out) {
    extern __shared__ __align__(16) char sm[];
    uint32_t smb = smem_u32(sm);
    int t = threadIdx.x, lane = t & 31, w = t >> 5;   // w: 0..15
    int b = blockIdx.y;
    int q0 = blockIdx.x * 256;
    const __nv_bfloat16* pl[2][2];
    #pragma unroll
    for (int c = 0; c < 2; c++)
        #pragma unroll
        for (int s = 0; s < 2; s++)
            pl[c][s] = cat + (size_t)(4*b + 2*c + s)*PE + (size_t)MR_F*64;

    float acc[8][4];
    #pragma unroll
    for (int nt = 0; nt < 8; nt++)
        #pragma unroll
        for (int k = 0; k < 4; k++) acc[nt][k] = 0.f;

    // ldmatrix lane addressing (verified mapping)
    int arow_l = (lane & 7) + ((lane >> 3) & 1) * 8;
    int au = (lane >> 4);
    int brow_l = (lane & 7) + ((lane >> 4) & 1) * 8;
    int bu = (lane >> 3) & 1;

    // prefetch helper (inlined twice)
    #define PREFETCH(S) do {                                                     \
        int tap_ = (S) / 2, ch_ = (S) & 1;                                       \
        int off_ = (tap_/3 - 1)*Wp + (tap_%3 - 1);                               \
        uint32_t sb_ = smb + ((S) & 1)*STAGE_BYTES;                              \
        const uint4* shi_ = (const uint4*)(pl[ch_][0] + (long long)(q0 + off_)*64); \
        const uint4* slo_ = (const uint4*)(pl[ch_][1] + (long long)(q0 + off_)*64); \
        for (int i = t; i < 2048; i += 512) {                                    \
            int r_ = i >> 3, cb_ = i & 7;                                        \
            uint32_t so_ = (uint32_t)(r_*128 + ((cb_ ^ (r_ & 7)) << 4));         \
            cp16(sb_ + OFF_AHI + so_, shi_ + i);                                 \
            cp16(sb_ + OFF_ALO + so_, slo_ + i);                                 \
        }                                                                        \
        const uint4* ws_ = wimg + (size_t)((tap_*2 + ch_)*2)*512;                \
        cp16(sb_ + OFF_BHI + t*16, ws_ + t);                                     \
        cp16(sb_ + OFF_BLO + t*16, ws_ + 512 + t);                               \
        CP_COMMIT();                                                             \
    } while (0)

    PREFETCH(0);
    for (int s = 0; s < 18; s++) {
        if (s < 17) { PREFETCH(s + 1); CP_WAIT1(); } else { CP_WAIT0(); }
        __syncthreads();
        uint32_t stb = smb + (s & 1)*STAGE_BYTES;
        #pragma unroll
        for (int ks = 0; ks < 4; ks++) {
            uint32_t aH[4], aL[4];
            {
                int row = w*16 + arow_l;
                int u = ks*2 + au;
                uint32_t soff = (uint32_t)(row*128 + ((u ^ (row & 7)) << 4));
                ldm_x4(aH, stb + OFF_AHI + soff);
                ldm_x4(aL, stb + OFF_ALO + soff);
            }
            uint32_t bHf[8][2], bLf[8][2];
            #pragma unroll
            for (int npair = 0; npair < 4; npair++) {
                int r = npair*16 + brow_l;
                int u = ks*2 + bu;
                uint32_t soff = (uint32_t)(r*128 + ((u ^ (r & 7)) << 4));
                uint32_t tmp[4];
                ldm_x4(tmp, stb + OFF_BHI + soff);
                bHf[npair*2][0]=tmp[0]; bHf[npair*2][1]=tmp[1];
                bHf[npair*2+1][0]=tmp[2]; bHf[npair*2+1][1]=tmp[3];
                ldm_x4(tmp, stb + OFF_BLO + soff);
                bLf[npair*2][0]=tmp[0]; bLf[npair*2][1]=tmp[1];
                bLf[npair*2+1][0]=tmp[2]; bLf[npair*2+1][1]=tmp[3];
            }
            #pragma unroll
            for (int nt = 0; nt < 8; nt++) {
                mma_bf16(acc[nt], aH, bHf[nt]);
                mma_bf16(acc[nt], aL, bHf[nt]);
                mma_bf16(acc[nt], aH, bLf[nt]);
            }
        }
        __syncthreads();
    }
    #undef PREFETCH

    // epilogue: transpose via smem -> coalesced NCHW stores
    int g = lane >> 2, tg = lane & 3;
    float* smf = (float*)sm;
    int rb = w*16 + g;
    #pragma unroll
    for (int nt = 0; nt < 8; nt++) {
        int cb = nt*8 + tg*2;
        smf[(cb+0)*257 + rb]     = acc[nt][0];
        smf[(cb+1)*257 + rb]     = acc[nt][1];
        smf[(cb+0)*257 + rb + 8] = acc[nt][2];
        smf[(cb+1)*257 + rb + 8] = acc[nt][3];
    }
    __syncthreads();
    for (int i = t; i < 16384; i += 512) {
        int oc = i >> 8, r = i & 255;
        int q = q0 + r;
        int y = q / Wp, x = q % Wp;
        if (y >= 1 && y <= H && x >= 1 && x <= W)
            out[((size_t)(b*64 + oc)*H + (y-1))*W + (x-1)] =
                fmaxf(smf[oc*257 + r] + bias[oc], 0.f);
    }
}

extern "C" void kernel_launch(void* const* d_in, const int* in_sizes, int n_in,
                              void* d_out, int out_size) {
    (void)out_size;
    const float* voxels[3] = {0,0,0};
    const int* numpts[3] = {0,0,0};
    const int* coordsp[3] = {0,0,0};
    const float *w1=0,*w2=0,*fw=0;
    const float* p192[8] = {0};
    const float* p128[4] = {0};
    int n192 = 0, n128 = 0;
    for (int i = 0; i < n_in; i++) {
        int sz = in_sizes[i];
        const void* p = d_in[i];
        switch (sz) {
            case 5120000: voxels[0] = (const float*)p; break;
            case 2560000: voxels[1] = (const float*)p; break;
            case 1024000: voxels[2] = (const float*)p; break;
            case 40000:   numpts[0] = (const int*)p; break;
            case 20000:   numpts[1] = (const int*)p; break;
            case 8000:    numpts[2] = (const int*)p; break;
            case 160000:  coordsp[0] = (const int*)p; break;
            case 80000:   coordsp[1] = (const int*)p; break;
            case 32000:   coordsp[2] = (const int*)p; break;
            case 1728:    w1 = (const float*)p; break;
            case 24576:   w2 = (const float*)p; break;
            case 147456:  fw = (const float*)p; break;
            case 192:     if (n192 < 8) p192[n192++] = (const float*)p; break;
            case 128:     if (n128 < 4) p128[n128++] = (const float*)p; break;
            default: break;
        }
    }
    const float *g1=p192[0], *b1=p192[1], *rm1=p192[2], *rv1=p192[3];
    const float *g2=p192[4], *b2=p192[5], *rm2=p192[6], *rv2=p192[7];
    const float *fg=p128[0], *fb=p128[1], *fm=p128[2], *fv=p128[3];

    __nv_bfloat16 *cat0, *cat1;
    cudaGetSymbolAddress((void**)&cat0, g_cat0t);
    cudaGetSymbolAddress((void**)&cat1, g_cat1t);
    float *sf2, *f1, *vf, *w1f, *b1f, *w2f, *b2f, *fbf;
    int* win;
    unsigned char* wimg;
    cudaGetSymbolAddress((void**)&sf2, g_sf2);
    cudaGetSymbolAddress((void**)&f1,  g_f1);
    cudaGetSymbolAddress((void**)&vf,  g_vf);
    cudaGetSymbolAddress((void**)&win, g_win);
    cudaGetSymbolAddress((void**)&w1f, g_w1f);
    cudaGetSymbolAddress((void**)&b1f, g_b1f);
    cudaGetSymbolAddress((void**)&w2f, g_w2f);
    cudaGetSymbolAddress((void**)&b2f, g_b2f);
    cudaGetSymbolAddress((void**)&fbf, g_fbf);
    cudaGetSymbolAddress((void**)&wimg, g_wimg);

    cudaFuncSetAttribute(conv_mma_kernel, cudaFuncAttributeMaxDynamicSharedMemorySize, CONV_SMEM);

    fold_kernel<<<1152, 256>>>(w1, g1, b1, rm1, rv1, w2, g2, b2, rm2, rv2, fw, fg, fb, fm, fv);

    zero_u4<<<4096, 256>>>((uint4*)cat0, (size_t)2*PE0);
    zero_u4<<<2048, 256>>>((uint4*)cat1, (size_t)2*PE1);
    zero_u4<<<512, 256>>>((uint4*)sf2, (size_t)BATCH*64*HW2/4);

    vfe_kernel<<<NS_[0], 64>>>(voxels[0], numpts[0], w1f, b1f, w2f, b2f, vf, NS_[0]);
    fill_win_kernel<<<(BATCH*HW0 + 255)/256, 256>>>(win, BATCH*HW0);
    scatter_max_kernel<<<(NS_[0] + 255)/256, 256>>>(coordsp[0], win, NS_[0], H0, W0);
    scatter_write_bf16<<<NS_[0], 64>>>(coordsp[0], win, vf, cat0, PE0, H0, W0, WP0);

    vfe_kernel<<<NS_[1], 64>>>(voxels[1], numpts[1], w1f + 576, b1f + 64, w2f + 8192, b2f + 64, vf, NS_[1]);
    fill_win_kernel<<<(BATCH*HW1 + 255)/256, 256>>>(win, BATCH*HW1);
    scatter_max_kernel<<<(NS_[1] + 255)/256, 256>>>(coordsp[1], win, NS_[1], H1, W1);
    scatter_write_bf16<<<NS_[1], 64>>>(coordsp[1], win, vf, cat1, PE1, H1, W1, WP1);

    vfe_kernel<<<NS_[2], 64>>>(voxels[2], numpts[2], w1f + 1152, b1f + 128, w2f + 16384, b2f + 128, vf, NS_[2]);
    fill_win_kernel<<<(BATCH*HW2 + 255)/256, 256>>>(win, BATCH*HW2);
    scatter_max_kernel<<<(NS_[2] + 255)/256, 256>>>(coordsp[2], win, NS_[2], H2, W2);
    scatter_write_f32<<<NS_[2], 64>>>(coordsp[2], win, vf, sf2, H2, W2);

    {
        dim3 g((W1 + 127)/128, H1, BATCH);
        ups_kernel<<<g, 256>>>(sf2, cat1, PE1, H2, W2, H1, W1, WP1);
    }
    {
        dim3 g((Q1 + 255)/256, BATCH);
        conv_mma_kernel<<<g, 512, CONV_SMEM>>>(cat1, PE1, WP1, H1, W1,
            (const uint4*)(wimg + 294912), fbf + 64, f1);
    }
    {
        dim3 g((W0 + 127)/128, H0, BATCH);
        ups_kernel<<<g, 256>>>(f1, cat0, PE0, H1, W1, H0, W0, WP0);
    }
    {
        dim3 g((Q0 + 255)/256, BATCH);
        conv_mma_kernel<<<g, 512, CONV_SMEM>>>(cat0, PE0, WP0, H0, W0,
            (const uint4*)wimg, fbf, (float*)d_out);
    }
}

// round 11
// speedup vs baseline: 3.2344x; 1.6479x over previous
#include <cuda_runtime.h>
#include <cuda_bf16.h>
#include <cuda_fp16.h>
#include <math.h>
#include <stdint.h>

#define EPSBN 1e-3f
static const int NS_[3] = {40000, 20000, 8000};
#define BATCH 4
#define TPTS 32
#define H0 496
#define W0 432
#define H1 248
#define W1 216
#define H2 124
#define W2 108
#define HW0 (H0*W0)
#define HW1 (H1*W1)
#define HW2 (H2*W2)
#define WP0 (W0+2)
#define Q0 ((H0+2)*WP0)
#define WP1 (W1+2)
#define Q1 ((H1+2)*WP1)
#define MR_F 512
#define MR_B 1024
#define P0 (MR_F + Q0 + MR_B)
#define P1 (MR_F + Q1 + MR_B)
#define PE0 ((size_t)P0*64)
#define PE1 ((size_t)P1*64)

__device__ float g_w1f[3*9*64];
__device__ float g_b1f[3*64];
__device__ float g_w2f[3*128*64];
__device__ float g_b2f[3*64];
__device__ float g_fbf[2*64];
__device__ unsigned char g_wimg[2*9*2*2*8192];   // [l][tap*2+chunk][hi/lo] 8KB fp16 tiles
__device__ float g_vf[40000*64];
__device__ int   g_win[BATCH*HW0];
__device__ __half g_cat0t[8*PE0];   // [b][chunk] fp16 planes
__device__ __half g_cat1t[8*PE1];
__device__ float g_sf2[(size_t)BATCH*64*HW2];
__device__ float g_f1 [(size_t)BATCH*64*HW1];

__device__ __forceinline__ uint32_t smem_u32(const void* p) {
    uint32_t a;
    asm("{ .reg .u64 t; cvta.to.shared.u64 t, %1; cvt.u32.u64 %0, t; }" : "=r"(a) : "l"(p));
    return a;
}
__device__ __forceinline__ void mma_f16(float* c, const uint32_t* a, const uint32_t* b) {
    asm volatile("mma.sync.aligned.m16n8k16.row.col.f32.f16.f16.f32 "
                 "{%0,%1,%2,%3}, {%4,%5,%6,%7}, {%8,%9}, {%0,%1,%2,%3};"
                 : "+f"(c[0]), "+f"(c[1]), "+f"(c[2]), "+f"(c[3])
                 : "r"(a[0]), "r"(a[1]), "r"(a[2]), "r"(a[3]), "r"(b[0]), "r"(b[1]));
}
__device__ __forceinline__ void ldm_x4(uint32_t* r, uint32_t addr) {
    asm volatile("ldmatrix.sync.aligned.m8n8.x4.shared.b16 {%0,%1,%2,%3}, [%4];"
                 : "=r"(r[0]), "=r"(r[1]), "=r"(r[2]), "=r"(r[3]) : "r"(addr));
}
__device__ __forceinline__ void cp16(uint32_t d, const void* s) {
    asm volatile("cp.async.cg.shared.global [%0], [%1], 16;" :: "r"(d), "l"(s));
}
#define CP_COMMIT() asm volatile("cp.async.commit_group;" ::: "memory")
#define CP_WAIT1()  asm volatile("cp.async.wait_group 1;" ::: "memory")
#define CP_WAIT0()  asm volatile("cp.async.wait_group 0;" ::: "memory")
#define SWZ(o) ((o) ^ (((o) >> 3) & 0x70))

#define OFF_A  0
#define OFF_BH 32768
#define OFF_BL 40960
#define STAGE_BYTES 49152
#define CONV_SMEM (2*STAGE_BYTES)
#define VFE_SMEM (18512*4)

__global__ void fold_kernel(const float* __restrict__ w1, const float* __restrict__ g1,
                            const float* __restrict__ b1, const float* __restrict__ rm1,
                            const float* __restrict__ rv1,
                            const float* __restrict__ w2, const float* __restrict__ g2,
                            const float* __restrict__ b2, const float* __restrict__ rm2,
                            const float* __restrict__ rv2,
                            const float* __restrict__ fw, const float* __restrict__ fg,
                            const float* __restrict__ fb, const float* __restrict__ fm,
                            const float* __restrict__ fv) {
    int idx = blockIdx.x * blockDim.x + threadIdx.x;
    if (idx < 1728) {
        int s = idx / 576; int d = idx % 64;
        g_w1f[idx] = w1[idx] * g1[s*64+d] * rsqrtf(rv1[s*64+d] + EPSBN);
    }
    if (idx < 24576) {
        int s = idx / 8192; int d = idx % 64;
        g_w2f[idx] = w2[idx] * g2[s*64+d] * rsqrtf(rv2[s*64+d] + EPSBN);
    }
    if (idx < 147456) {
        int l = idx / 73728; int r = idx % 73728;
        int oc = r / 1152; int rem = r % 1152;
        int ic = rem / 9; int tap = rem % 9;
        float sc = fg[l*64+oc] * rsqrtf(fv[l*64+oc] + EPSBN);
        float w = fw[(((size_t)(l*64+oc)*128 + ic)*9) + tap] * sc;
        __half hi = __float2half_rn(w);
        __half lo = __float2half_rn(w - __half2float(hi));
        int chunk = ic >> 6, chl = ic & 63;
        size_t tb = (size_t)l*294912 + (size_t)((tap*2+chunk)*2)*8192;
        uint32_t so = SWZ((uint32_t)(oc*128 + chl*2));
        *(__half*)(g_wimg + tb + so) = hi;
        *(__half*)(g_wimg + tb + 8192 + so) = lo;
    }
    if (idx < 192) {
        g_b1f[idx] = b1[idx] - rm1[idx] * g1[idx] * rsqrtf(rv1[idx] + EPSBN);
        g_b2f[idx] = b2[idx] - rm2[idx] * g2[idx] * rsqrtf(rv2[idx] + EPSBN);
    }
    if (idx < 128) {
        g_fbf[idx] = fb[idx] - fm[idx] * fg[idx] * rsqrtf(fv[idx] + EPSBN);
    }
}

// VFE: 4 voxels per 256-thread block; weights loaded once per block
__global__ void vfe_kernel(const float* __restrict__ voxels, const int* __restrict__ numpts,
                           const float* __restrict__ w1f, const float* __restrict__ b1f,
                           const float* __restrict__ w2f, const float* __restrict__ b2f,
                           float* __restrict__ vfout, int N) {
    extern __shared__ float smf[];
    float* w1s = smf;            // 576
    float* w2s = smf + 576;      // 8192
    float* b1s = smf + 8768;     // 64
    float* b2s = smf + 8832;     // 64
    int t = threadIdx.x;
    int grp = t >> 6, lt = t & 63;
    float* gb   = smf + 8896 + grp*2404;
    float* feat = gb;            // 288
    float* h1s  = gb + 288;      // 2048
    float* gmaxs= gb + 2336;     // 64
    float* mean3= gb + 2400;     // 3

    for (int i = t; i < 576; i += 256)  w1s[i] = w1f[i];
    for (int i = t; i < 8192; i += 256) w2s[i] = w2f[i];
    if (t < 64) b1s[t] = b1f[t];
    else if (t < 128) b2s[t-64] = b2f[t-64];

    int v = blockIdx.x*4 + grp;
    bool valid = v < N;
    int np = valid ? numpts[v] : 1;

    float4 p = make_float4(0.f,0.f,0.f,0.f);
    if (lt < 32) {
        if (valid) p = ((const float4*)voxels)[(size_t)v * TPTS + lt];
        float sx = p.x, sy = p.y, sz = p.z;
        #pragma unroll
        for (int o = 16; o > 0; o >>= 1) {
            sx += __shfl_down_sync(0xffffffffu, sx, o);
            sy += __shfl_down_sync(0xffffffffu, sy, o);
            sz += __shfl_down_sync(0xffffffffu, sz, o);
        }
        if (lt == 0) {
            float inv = 1.0f / (float)np;
            mean3[0] = sx*inv; mean3[1] = sy*inv; mean3[2] = sz*inv;
        }
    }
    __syncthreads();
    if (lt < 32) {
        float mx = mean3[0], my = mean3[1], mz = mean3[2];
        float* f = &feat[lt*9];
        f[0]=p.x; f[1]=p.y; f[2]=p.z; f[3]=p.w;
        f[4]=p.x-mx; f[5]=p.y-my; f[6]=p.z-mz; f[7]=p.x-mx; f[8]=p.y-my;
    }
    __syncthreads();
    int c = lt;
    float b1v = b1s[c], gm = -1e30f;
    for (int tt = 0; tt < TPTS; tt++) {
        float a = b1v;
        #pragma unroll
        for (int k = 0; k < 9; k++) a = fmaf(feat[tt*9+k], w1s[k*64+c], a);
        a = fmaxf(a, 0.f);
        h1s[tt*64+c] = a;
        gm = fmaxf(gm, a);
    }
    gmaxs[c] = gm;
    __syncthreads();
    float gterm = b2s[c];
    #pragma unroll 8
    for (int j = 0; j < 64; j++) gterm = fmaf(gmaxs[j], w2s[(64+j)*64+c], gterm);
    float vmax = 0.f;
    int tt = 0;
    for (; tt + 4 <= np; tt += 4) {
        float a0=gterm,a1=gterm,a2=gterm,a3=gterm;
        const float* h0 = &h1s[tt*64];
        #pragma unroll 8
        for (int j = 0; j < 64; j++) {
            float w = w2s[j*64+c];
            a0 = fmaf(h0[j],w,a0); a1 = fmaf(h0[64+j],w,a1);
            a2 = fmaf(h0[128+j],w,a2); a3 = fmaf(h0[192+j],w,a3);
        }
        vmax = fmaxf(vmax, fmaxf(fmaxf(a0,a1), fmaxf(a2,a3)));
    }
    for (; tt < np; tt++) {
        float a = gterm;
        #pragma unroll 8
        for (int j = 0; j < 64; j++) a = fmaf(h1s[tt*64+j], w2s[j*64+c], a);
        vmax = fmaxf(vmax, a);
    }
    if (valid) vfout[(size_t)v*64 + c] = vmax;
}

__global__ void fill_win_kernel(int* __restrict__ p, int n) {
    int i = blockIdx.x * blockDim.x + threadIdx.x;
    if (i < n) p[i] = -1;
}
__global__ void scatter_max_kernel(const int* __restrict__ coords, int* __restrict__ win,
                                   int N, int H, int W) {
    int v = blockIdx.x * blockDim.x + threadIdx.x;
    if (v >= N) return;
    int b = coords[v*4];
    int y = min(max(coords[v*4+2], 0), H-1);
    int x = min(max(coords[v*4+3], 0), W-1);
    atomicMax(&win[(b*H + y)*W + x], v);
}
__global__ void scatter_write_f16(const int* __restrict__ coords, const int* __restrict__ win,
                                  const float* __restrict__ vf, __half* __restrict__ cat,
                                  size_t PE, int H, int W, int Wp) {
    int v = blockIdx.x, c = threadIdx.x;
    int b = coords[v*4];
    int y = min(max(coords[v*4+2], 0), H-1);
    int x = min(max(coords[v*4+3], 0), W-1);
    if (win[(b*H + y)*W + x] != v) return;
    float val = vf[(size_t)v*64 + c];
    cat[(size_t)(b*2)*PE + (size_t)MR_F*64 + (size_t)((y+1)*Wp + (x+1))*64 + c] = __float2half_rn(val);
}
__global__ void scatter_write_f32(const int* __restrict__ coords, const int* __restrict__ win,
                                  const float* __restrict__ vf, float* __restrict__ dst,
                                  int H, int W) {
    int v = blockIdx.x, c = threadIdx.x;
    int b = coords[v*4];
    int y = min(max(coords[v*4+2], 0), H-1);
    int x = min(max(coords[v*4+3], 0), W-1);
    if (win[(b*H + y)*W + x] != v) return;
    dst[((size_t)(b*64 + c)*H + y)*W + x] = vf[(size_t)v*64 + c];
}
__global__ void zero_u4(uint4* __restrict__ p, size_t n) {
    uint4 z = make_uint4(0,0,0,0);
    for (size_t i = (size_t)blockIdx.x*blockDim.x + threadIdx.x; i < n;
         i += (size_t)gridDim.x*blockDim.x) p[i] = z;
}

__global__ void ups_kernel(const float* __restrict__ src, __half* __restrict__ cat,
                           size_t PE, int Hi, int Wi, int Ho, int Wo, int Wp) {
    __shared__ float s[2*64*67];
    int b = blockIdx.z, y = blockIdx.y;
    int X0 = blockIdx.x * 128;
    int t = threadIdx.x;
    float fy = fminf(fmaxf(y*0.5f - 0.25f, 0.f), (float)(Hi-1));
    int y0 = (int)fy; float wy = fy - y0;
    int y1 = min(y0+1, Hi-1);
    int xb = (int)fmaxf(X0*0.5f - 0.25f, 0.f);
    const float* sb = src + (size_t)b*64*Hi*Wi;
    for (int i = t; i < 2*64*66; i += 256) {
        int xi = i % 66, c = (i/66) % 64, r = i/(66*64);
        int gx = min(xb + xi, Wi-1);
        int gy = r ? y1 : y0;
        s[(r*64 + c)*67 + xi] = sb[((size_t)c*Hi + gy)*Wi + gx];
    }
    __syncthreads();
    int co = t & 63, xg = t >> 6;
    __half* plane = cat + (size_t)(2*b+1)*PE + (size_t)MR_F*64;
    for (int k = 0; k < 32; k++) {
        int xo = X0 + xg*32 + k;
        if (xo >= Wo) break;
        float fx = fminf(fmaxf(xo*0.5f - 0.25f, 0.f), (float)(Wi-1));
        int x0 = (int)fx; float wx = fx - x0;
        int xi = x0 - xb;
        float v0 = (1.f-wx)*s[co*67+xi]      + wx*s[co*67+xi+1];
        float v1 = (1.f-wx)*s[(64+co)*67+xi] + wx*s[(64+co)*67+xi+1];
        float val = (1.f-wy)*v0 + wy*v1;
        plane[((size_t)(y+1)*Wp + (xo+1))*64 + co] = __float2half_rn(val);
    }
}

// Pipelined HMMA conv, fp16 2-term: 512 threads, 16 warps x (16 rows x 64 oc)
__global__ __launch_bounds__(512, 2)
void conv_mma_kernel(const __half* __restrict__ cat, size_t PE,
                     int Wp, int H, int W,
                     const uint4* __restrict__ wimg, const float* __restrict__ bias,
                     float* __restrict__ out) {
    extern __shared__ __align__(16) char sm[];
    uint32_t smb = smem_u32(sm);
    int t = threadIdx.x, lane = t & 31, w = t >> 5;
    int b = blockIdx.y;
    int q0 = blockIdx.x * 256;
    const __half* pl[2];
    #pragma unroll
    for (int c = 0; c < 2; c++)
        pl[c] = cat + (size_t)(2*b + c)*PE + (size_t)MR_F*64;

    float acc[8][4];
    #pragma unroll
    for (int nt = 0; nt < 8; nt++)
        #pragma unroll
        for (int k = 0; k < 4; k++) acc[nt][k] = 0.f;

    int arow_l = (lane & 7) + ((lane >> 3) & 1) * 8;
    int au = (lane >> 4);
    int brow_l = (lane & 7) + ((lane >> 4) & 1) * 8;
    int bu = (lane >> 3) & 1;

    #define PREFETCH(S) do {                                                      \
        int tap_ = (S) / 2, ch_ = (S) & 1;                                        \
        int off_ = (tap_/3 - 1)*Wp + (tap_%3 - 1);                                \
        uint32_t sb_ = smb + ((S) & 1)*STAGE_BYTES;                               \
        const uint4* sa_ = (const uint4*)(pl[ch_] + (long long)(q0 + off_)*64);   \
        for (int i = t; i < 2048; i += 512) {                                     \
            int r_ = i >> 3, cb_ = i & 7;                                         \
            uint32_t so_ = (uint32_t)(r_*128 + ((cb_ ^ (r_ & 7)) << 4));          \
            cp16(sb_ + OFF_A + so_, sa_ + i);                                     \
        }                                                                         \
        const uint4* ws_ = wimg + (size_t)((tap_*2 + ch_)*2)*512;                 \
        cp16(sb_ + OFF_BH + t*16, ws_ + t);                                       \
        cp16(sb_ + OFF_BL + t*16, ws_ + 512 + t);                                 \
        CP_COMMIT();                                                              \
    } while (0)

    PREFETCH(0);
    for (int s = 0; s < 18; s++) {
        if (s < 17) { PREFETCH(s + 1); CP_WAIT1(); } else { CP_WAIT0(); }
        __syncthreads();
        uint32_t stb = smb + (s & 1)*STAGE_BYTES;
        #pragma unroll
        for (int ks = 0; ks < 4; ks++) {
            uint32_t aH[4];
            {
                int row = w*16 + arow_l;
                int u = ks*2 + au;
                ldm_x4(aH, stb + OFF_A + (uint32_t)(row*128 + ((u ^ (row & 7)) << 4)));
            }
            uint32_t bHf[8][2], bLf[8][2];
            #pragma unroll
            for (int npair = 0; npair < 4; npair++) {
                int r = npair*16 + brow_l;
                int u = ks*2 + bu;
                uint32_t soff = (uint32_t)(r*128 + ((u ^ (r & 7)) << 4));
                uint32_t tmp[4];
                ldm_x4(tmp, stb + OFF_BH + soff);
                bHf[npair*2][0]=tmp[0]; bHf[npair*2][1]=tmp[1];
                bHf[npair*2+1][0]=tmp[2]; bHf[npair*2+1][1]=tmp[3];
                ldm_x4(tmp, stb + OFF_BL + soff);
                bLf[npair*2][0]=tmp[0]; bLf[npair*2][1]=tmp[1];
                bLf[npair*2+1][0]=tmp[2]; bLf[npair*2+1][1]=tmp[3];
            }
            #pragma unroll
            for (int nt = 0; nt < 8; nt++) {
                mma_f16(acc[nt], aH, bHf[nt]);
                mma_f16(acc[nt], aH, bLf[nt]);
            }
        }
        __syncthreads();
    }
    #undef PREFETCH

    int g = lane >> 2, tg = lane & 3;
    float* smf = (float*)sm;
    int rb = w*16 + g;
    #pragma unroll
    for (int nt = 0; nt < 8; nt++) {
        int cb = nt*8 + tg*2;
        smf[(cb+0)*257 + rb]     = acc[nt][0];
        smf[(cb+1)*257 + rb]     = acc[nt][1];
        smf[(cb+0)*257 + rb + 8] = acc[nt][2];
        smf[(cb+1)*257 + rb + 8] = acc[nt][3];
    }
    __syncthreads();
    for (int i = t; i < 16384; i += 512) {
        int oc = i >> 8, r = i & 255;
        int q = q0 + r;
        int y = q / Wp, x = q % Wp;
        if (y >= 1 && y <= H && x >= 1 && x <= W)
            out[((size_t)(b*64 + oc)*H + (y-1))*W + (x-1)] =
                fmaxf(smf[oc*257 + r] + bias[oc], 0.f);
    }
}

extern "C" void kernel_launch(void* const* d_in, const int* in_sizes, int n_in,
                              void* d_out, int out_size) {
    (void)out_size;
    const float* voxels[3] = {0,0,0};
    const int* numpts[3] = {0,0,0};
    const int* coordsp[3] = {0,0,0};
    const float *w1=0,*w2=0,*fw=0;
    const float* p192[8] = {0};
    const float* p128[4] = {0};
    int n192 = 0, n128 = 0;
    for (int i = 0; i < n_in; i++) {
        int sz = in_sizes[i];
        const void* p = d_in[i];
        switch (sz) {
            case 5120000: voxels[0] = (const float*)p; break;
            case 2560000: voxels[1] = (const float*)p; break;
            case 1024000: voxels[2] = (const float*)p; break;
            case 40000:   numpts[0] = (const int*)p; break;
            case 20000:   numpts[1] = (const int*)p; break;
            case 8000:    numpts[2] = (const int*)p; break;
            case 160000:  coordsp[0] = (const int*)p; break;
            case 80000:   coordsp[1] = (const int*)p; break;
            case 32000:   coordsp[2] = (const int*)p; break;
            case 1728:    w1 = (const float*)p; break;
            case 24576:   w2 = (const float*)p; break;
            case 147456:  fw = (const float*)p; break;
            case 192:     if (n192 < 8) p192[n192++] = (const float*)p; break;
            case 128:     if (n128 < 4) p128[n128++] = (const float*)p; break;
            default: break;
        }
    }
    const float *g1=p192[0], *b1=p192[1], *rm1=p192[2], *rv1=p192[3];
    const float *g2=p192[4], *b2=p192[5], *rm2=p192[6], *rv2=p192[7];
    const float *fg=p128[0], *fb=p128[1], *fm=p128[2], *fv=p128[3];

    __half *cat0, *cat1;
    cudaGetSymbolAddress((void**)&cat0, g_cat0t);
    cudaGetSymbolAddress((void**)&cat1, g_cat1t);
    float *sf2, *f1, *vf, *w1f, *b1f, *w2f, *b2f, *fbf;
    int* win;
    unsigned char* wimg;
    cudaGetSymbolAddress((void**)&sf2, g_sf2);
    cudaGetSymbolAddress((void**)&f1,  g_f1);
    cudaGetSymbolAddress((void**)&vf,  g_vf);
    cudaGetSymbolAddress((void**)&win, g_win);
    cudaGetSymbolAddress((void**)&w1f, g_w1f);
    cudaGetSymbolAddress((void**)&b1f, g_b1f);
    cudaGetSymbolAddress((void**)&w2f, g_w2f);
    cudaGetSymbolAddress((void**)&b2f, g_b2f);
    cudaGetSymbolAddress((void**)&fbf, g_fbf);
    cudaGetSymbolAddress((void**)&wimg, g_wimg);

    cudaFuncSetAttribute(conv_mma_kernel, cudaFuncAttributeMaxDynamicSharedMemorySize, CONV_SMEM);
    cudaFuncSetAttribute(vfe_kernel, cudaFuncAttributeMaxDynamicSharedMemorySize, VFE_SMEM);

    fold_kernel<<<1152, 256>>>(w1, g1, b1, rm1, rv1, w2, g2, b2, rm2, rv2, fw, fg, fb, fm, fv);

    zero_u4<<<2048, 256>>>((uint4*)cat0, PE0);
    zero_u4<<<1024, 256>>>((uint4*)cat1, PE1);
    zero_u4<<<512, 256>>>((uint4*)sf2, (size_t)BATCH*64*HW2/4);

    vfe_kernel<<<(NS_[0]+3)/4, 256, VFE_SMEM>>>(voxels[0], numpts[0], w1f, b1f, w2f, b2f, vf, NS_[0]);
    fill_win_kernel<<<(BATCH*HW0 + 255)/256, 256>>>(win, BATCH*HW0);
    scatter_max_kernel<<<(NS_[0] + 255)/256, 256>>>(coordsp[0], win, NS_[0], H0, W0);
    scatter_write_f16<<<NS_[0], 64>>>(coordsp[0], win, vf, cat0, PE0, H0, W0, WP0);

    vfe_kernel<<<(NS_[1]+3)/4, 256, VFE_SMEM>>>(voxels[1], numpts[1], w1f + 576, b1f + 64, w2f + 8192, b2f + 64, vf, NS_[1]);
    fill_win_kernel<<<(BATCH*HW1 + 255)/256, 256>>>(win, BATCH*HW1);
    scatter_max_kernel<<<(NS_[1] + 255)/256, 256>>>(coordsp[1], win, NS_[1], H1, W1);
    scatter_write_f16<<<NS_[1], 64>>>(coordsp[1], win, vf, cat1, PE1, H1, W1, WP1);

    vfe_kernel<<<(NS_[2]+3)/4, 256, VFE_SMEM>>>(voxels[2], numpts[2], w1f + 1152, b1f + 128, w2f + 16384, b2f + 128, vf, NS_[2]);
    fill_win_kernel<<<(BATCH*HW2 + 255)/256, 256>>>(win, BATCH*HW2);
    scatter_max_kernel<<<(NS_[2] + 255)/256, 256>>>(coordsp[2], win, NS_[2], H2, W2);
    scatter_write_f32<<<NS_[2], 64>>>(coordsp[2], win, vf, sf2, H2, W2);

    {
        dim3 g((W1 + 127)/128, H1, BATCH);
        ups_kernel<<<g, 256>>>(sf2, cat1, PE1, H2, W2, H1, W1, WP1);
    }
    {
        dim3 g((Q1 + 255)/256, BATCH);
        conv_mma_kernel<<<g, 512, CONV_SMEM>>>(cat1, PE1, WP1, H1, W1,
            (const uint4*)(wimg + 294912), fbf + 64, f1);
    }
    {
        dim3 g((W0 + 127)/128, H0, BATCH);
        ups_kernel<<<g, 256>>>(f1, cat0, PE0, H1, W1, H0, W0, WP0);
    }
    {
        dim3 g((Q0 + 255)/256, BATCH);
        conv_mma_kernel<<<g, 512, CONV_SMEM>>>(cat0, PE0, WP0, H0, W0,
            (const uint4*)wimg, fbf, (float*)d_out);
    }
}

// round 12
// speedup vs baseline: 3.8272x; 1.1833x over previous
#include <cuda_runtime.h>
#include <cuda_bf16.h>
#include <cuda_fp16.h>
#include <math.h>
#include <stdint.h>

#define EPSBN 1e-3f
static const int NS_[3] = {40000, 20000, 8000};
#define BATCH 4
#define TPTS 32
#define H0 496
#define W0 432
#define H1 248
#define W1 216
#define H2 124
#define W2 108
#define HW0 (H0*W0)
#define HW1 (H1*W1)
#define HW2 (H2*W2)
#define WP0 (W0+2)
#define Q0 ((H0+2)*WP0)
#define WP1 (W1+2)
#define Q1 ((H1+2)*WP1)
#define MR_F 512
#define MR_B 1024
#define P0 (MR_F + Q0 + MR_B)
#define P1 (MR_F + Q1 + MR_B)
#define PE0 ((size_t)P0*64)
#define PE1 ((size_t)P1*64)

__device__ float g_w1f[3*9*64];
__device__ float g_b1f[3*64];
__device__ float g_w2f[3*128*64];
__device__ float g_b2f[3*64];
__device__ float g_fbf[2*64];
__device__ unsigned char g_wimg[2*9*2*8192];   // [l][tap*2+chunk] 8KB fp16 tiles (single-term)
__device__ float g_vf[40000*64];
__device__ int   g_win[BATCH*HW0];
__device__ __half g_cat0t[8*PE0];
__device__ __half g_cat1t[8*PE1];
__device__ float g_sf2[(size_t)BATCH*64*HW2];
__device__ float g_f1 [(size_t)BATCH*64*HW1];

__device__ __forceinline__ uint32_t smem_u32(const void* p) {
    uint32_t a;
    asm("{ .reg .u64 t; cvta.to.shared.u64 t, %1; cvt.u32.u64 %0, t; }" : "=r"(a) : "l"(p));
    return a;
}
__device__ __forceinline__ void mma_f16(float* c, const uint32_t* a, const uint32_t* b) {
    asm volatile("mma.sync.aligned.m16n8k16.row.col.f32.f16.f16.f32 "
                 "{%0,%1,%2,%3}, {%4,%5,%6,%7}, {%8,%9}, {%0,%1,%2,%3};"
                 : "+f"(c[0]), "+f"(c[1]), "+f"(c[2]), "+f"(c[3])
                 : "r"(a[0]), "r"(a[1]), "r"(a[2]), "r"(a[3]), "r"(b[0]), "r"(b[1]));
}
__device__ __forceinline__ void ldm_x4(uint32_t* r, uint32_t addr) {
    asm volatile("ldmatrix.sync.aligned.m8n8.x4.shared.b16 {%0,%1,%2,%3}, [%4];"
                 : "=r"(r[0]), "=r"(r[1]), "=r"(r[2]), "=r"(r[3]) : "r"(addr));
}
__device__ __forceinline__ void cp16(uint32_t d, const void* s) {
    asm volatile("cp.async.cg.shared.global [%0], [%1], 16;" :: "r"(d), "l"(s));
}
#define CP_COMMIT() asm volatile("cp.async.commit_group;" ::: "memory")
#define CP_WAIT1()  asm volatile("cp.async.wait_group 1;" ::: "memory")
#define CP_WAIT0()  asm volatile("cp.async.wait_group 0;" ::: "memory")
#define SWZ(o) ((o) ^ (((o) >> 3) & 0x70))

#define OFF_A  0
#define OFF_BH 32768
#define STAGE_BYTES 40960
#define CONV_SMEM (2*STAGE_BYTES)
#define VFE_SMEM (18512*4)

__global__ void fold_kernel(const float* __restrict__ w1, const float* __restrict__ g1,
                            const float* __restrict__ b1, const float* __restrict__ rm1,
                            const float* __restrict__ rv1,
                            const float* __restrict__ w2, const float* __restrict__ g2,
                            const float* __restrict__ b2, const float* __restrict__ rm2,
                            const float* __restrict__ rv2,
                            const float* __restrict__ fw, const float* __restrict__ fg,
                            const float* __restrict__ fb, const float* __restrict__ fm,
                            const float* __restrict__ fv) {
    int idx = blockIdx.x * blockDim.x + threadIdx.x;
    if (idx < 1728) {
        int s = idx / 576; int d = idx % 64;
        g_w1f[idx] = w1[idx] * g1[s*64+d] * rsqrtf(rv1[s*64+d] + EPSBN);
    }
    if (idx < 24576) {
        int s = idx / 8192; int d = idx % 64;
        g_w2f[idx] = w2[idx] * g2[s*64+d] * rsqrtf(rv2[s*64+d] + EPSBN);
    }
    if (idx < 147456) {
        int l = idx / 73728; int r = idx % 73728;
        int oc = r / 1152; int rem = r % 1152;
        int ic = rem / 9; int tap = rem % 9;
        float sc = fg[l*64+oc] * rsqrtf(fv[l*64+oc] + EPSBN);
        float w = fw[(((size_t)(l*64+oc)*128 + ic)*9) + tap] * sc;
        int chunk = ic >> 6, chl = ic & 63;
        size_t tb = (size_t)l*147456 + (size_t)(tap*2+chunk)*8192;
        uint32_t so = SWZ((uint32_t)(oc*128 + chl*2));
        *(__half*)(g_wimg + tb + so) = __float2half_rn(w);
    }
    if (idx < 192) {
        g_b1f[idx] = b1[idx] - rm1[idx] * g1[idx] * rsqrtf(rv1[idx] + EPSBN);
        g_b2f[idx] = b2[idx] - rm2[idx] * g2[idx] * rsqrtf(rv2[idx] + EPSBN);
    }
    if (idx < 128) {
        g_fbf[idx] = fb[idx] - fm[idx] * fg[idx] * rsqrtf(fv[idx] + EPSBN);
    }
}

// VFE: 4 voxels per 256-thread block; weights loaded once per block
__global__ void vfe_kernel(const float* __restrict__ voxels, const int* __restrict__ numpts,
                           const float* __restrict__ w1f, const float* __restrict__ b1f,
                           const float* __restrict__ w2f, const float* __restrict__ b2f,
                           float* __restrict__ vfout, int N) {
    extern __shared__ float smf[];
    float* w1s = smf;
    float* w2s = smf + 576;
    float* b1s = smf + 8768;
    float* b2s = smf + 8832;
    int t = threadIdx.x;
    int grp = t >> 6, lt = t & 63;
    float* gb   = smf + 8896 + grp*2404;
    float* feat = gb;
    float* h1s  = gb + 288;
    float* gmaxs= gb + 2336;
    float* mean3= gb + 2400;

    for (int i = t; i < 576; i += 256)  w1s[i] = w1f[i];
    for (int i = t; i < 8192; i += 256) w2s[i] = w2f[i];
    if (t < 64) b1s[t] = b1f[t];
    else if (t < 128) b2s[t-64] = b2f[t-64];

    int v = blockIdx.x*4 + grp;
    bool valid = v < N;
    int np = valid ? numpts[v] : 1;

    float4 p = make_float4(0.f,0.f,0.f,0.f);
    if (lt < 32) {
        if (valid) p = ((const float4*)voxels)[(size_t)v * TPTS + lt];
        float sx = p.x, sy = p.y, sz = p.z;
        #pragma unroll
        for (int o = 16; o > 0; o >>= 1) {
            sx += __shfl_down_sync(0xffffffffu, sx, o);
            sy += __shfl_down_sync(0xffffffffu, sy, o);
            sz += __shfl_down_sync(0xffffffffu, sz, o);
        }
        if (lt == 0) {
            float inv = 1.0f / (float)np;
            mean3[0] = sx*inv; mean3[1] = sy*inv; mean3[2] = sz*inv;
        }
    }
    __syncthreads();
    if (lt < 32) {
        float mx = mean3[0], my = mean3[1], mz = mean3[2];
        float* f = &feat[lt*9];
        f[0]=p.x; f[1]=p.y; f[2]=p.z; f[3]=p.w;
        f[4]=p.x-mx; f[5]=p.y-my; f[6]=p.z-mz; f[7]=p.x-mx; f[8]=p.y-my;
    }
    __syncthreads();
    int c = lt;
    float b1v = b1s[c], gm = -1e30f;
    for (int tt = 0; tt < TPTS; tt++) {
        float a = b1v;
        #pragma unroll
        for (int k = 0; k < 9; k++) a = fmaf(feat[tt*9+k], w1s[k*64+c], a);
        a = fmaxf(a, 0.f);
        h1s[tt*64+c] = a;
        gm = fmaxf(gm, a);
    }
    gmaxs[c] = gm;
    __syncthreads();
    float gterm = b2s[c];
    #pragma unroll 8
    for (int j = 0; j < 64; j++) gterm = fmaf(gmaxs[j], w2s[(64+j)*64+c], gterm);
    float vmax = 0.f;
    int tt = 0;
    for (; tt + 4 <= np; tt += 4) {
        float a0=gterm,a1=gterm,a2=gterm,a3=gterm;
        const float* h0 = &h1s[tt*64];
        #pragma unroll 8
        for (int j = 0; j < 64; j++) {
            float w = w2s[j*64+c];
            a0 = fmaf(h0[j],w,a0); a1 = fmaf(h0[64+j],w,a1);
            a2 = fmaf(h0[128+j],w,a2); a3 = fmaf(h0[192+j],w,a3);
        }
        vmax = fmaxf(vmax, fmaxf(fmaxf(a0,a1), fmaxf(a2,a3)));
    }
    for (; tt < np; tt++) {
        float a = gterm;
        #pragma unroll 8
        for (int j = 0; j < 64; j++) a = fmaf(h1s[tt*64+j], w2s[j*64+c], a);
        vmax = fmaxf(vmax, a);
    }
    if (valid) vfout[(size_t)v*64 + c] = vmax;
}

__global__ void fill_win_kernel(int* __restrict__ p, int n) {
    int i = blockIdx.x * blockDim.x + threadIdx.x;
    if (i < n) p[i] = -1;
}
__global__ void scatter_max_kernel(const int* __restrict__ coords, int* __restrict__ win,
                                   int N, int H, int W) {
    int v = blockIdx.x * blockDim.x + threadIdx.x;
    if (v >= N) return;
    int b = coords[v*4];
    int y = min(max(coords[v*4+2], 0), H-1);
    int x = min(max(coords[v*4+3], 0), W-1);
    atomicMax(&win[(b*H + y)*W + x], v);
}
__global__ void scatter_write_f16(const int* __restrict__ coords, const int* __restrict__ win,
                                  const float* __restrict__ vf, __half* __restrict__ cat,
                                  size_t PE, int H, int W, int Wp) {
    int v = blockIdx.x, c = threadIdx.x;
    int b = coords[v*4];
    int y = min(max(coords[v*4+2], 0), H-1);
    int x = min(max(coords[v*4+3], 0), W-1);
    if (win[(b*H + y)*W + x] != v) return;
    float val = vf[(size_t)v*64 + c];
    cat[(size_t)(b*2)*PE + (size_t)MR_F*64 + (size_t)((y+1)*Wp + (x+1))*64 + c] = __float2half_rn(val);
}
__global__ void scatter_write_f32(const int* __restrict__ coords, const int* __restrict__ win,
                                  const float* __restrict__ vf, float* __restrict__ dst,
                                  int H, int W) {
    int v = blockIdx.x, c = threadIdx.x;
    int b = coords[v*4];
    int y = min(max(coords[v*4+2], 0), H-1);
    int x = min(max(coords[v*4+3], 0), W-1);
    if (win[(b*H + y)*W + x] != v) return;
    dst[((size_t)(b*64 + c)*H + y)*W + x] = vf[(size_t)v*64 + c];
}
__global__ void zero_u4(uint4* __restrict__ p, size_t n) {
    uint4 z = make_uint4(0,0,0,0);
    for (size_t i = (size_t)blockIdx.x*blockDim.x + threadIdx.x; i < n;
         i += (size_t)gridDim.x*blockDim.x) p[i] = z;
}

__global__ void ups_kernel(const float* __restrict__ src, __half* __restrict__ cat,
                           size_t PE, int Hi, int Wi, int Ho, int Wo, int Wp) {
    __shared__ float s[2*64*67];
    int b = blockIdx.z, y = blockIdx.y;
    int X0 = blockIdx.x * 128;
    int t = threadIdx.x;
    float fy = fminf(fmaxf(y*0.5f - 0.25f, 0.f), (float)(Hi-1));
    int y0 = (int)fy; float wy = fy - y0;
    int y1 = min(y0+1, Hi-1);
    int xb = (int)fmaxf(X0*0.5f - 0.25f, 0.f);
    const float* sb = src + (size_t)b*64*Hi*Wi;
    for (int i = t; i < 2*64*66; i += 256) {
        int xi = i % 66, c = (i/66) % 64, r = i/(66*64);
        int gx = min(xb + xi, Wi-1);
        int gy = r ? y1 : y0;
        s[(r*64 + c)*67 + xi] = sb[((size_t)c*Hi + gy)*Wi + gx];
    }
    __syncthreads();
    int co = t & 63, xg = t >> 6;
    __half* plane = cat + (size_t)(2*b+1)*PE + (size_t)MR_F*64;
    for (int k = 0; k < 32; k++) {
        int xo = X0 + xg*32 + k;
        if (xo >= Wo) break;
        float fx = fminf(fmaxf(xo*0.5f - 0.25f, 0.f), (float)(Wi-1));
        int x0 = (int)fx; float wx = fx - x0;
        int xi = x0 - xb;
        float v0 = (1.f-wx)*s[co*67+xi]      + wx*s[co*67+xi+1];
        float v1 = (1.f-wx)*s[(64+co)*67+xi] + wx*s[(64+co)*67+xi+1];
        float val = (1.f-wy)*v0 + wy*v1;
        plane[((size_t)(y+1)*Wp + (xo+1))*64 + co] = __float2half_rn(val);
    }
}

// Pipelined HMMA conv, fp16 single-term: 512 threads, 16 warps x (16 rows x 64 oc)
__global__ __launch_bounds__(512, 2)
void conv_mma_kernel(const __half* __restrict__ cat, size_t PE,
                     int Wp, int H, int W,
                     const uint4* __restrict__ wimg, const float* __restrict__ bias,
                     float* __restrict__ out) {
    extern __shared__ __align__(16) char sm[];
    uint32_t smb = smem_u32(sm);
    int t = threadIdx.x, lane = t & 31, w = t >> 5;
    int b = blockIdx.y;
    int q0 = blockIdx.x * 256;
    const __half* pl[2];
    #pragma unroll
    for (int c = 0; c < 2; c++)
        pl[c] = cat + (size_t)(2*b + c)*PE + (size_t)MR_F*64;

    float acc[8][4];
    #pragma unroll
    for (int nt = 0; nt < 8; nt++)
        #pragma unroll
        for (int k = 0; k < 4; k++) acc[nt][k] = 0.f;

    int arow_l = (lane & 7) + ((lane >> 3) & 1) * 8;
    int au = (lane >> 4);
    int brow_l = (lane & 7) + ((lane >> 4) & 1) * 8;
    int bu = (lane >> 3) & 1;

    #define PREFETCH(S) do {                                                      \
        int tap_ = (S) / 2, ch_ = (S) & 1;                                        \
        int off_ = (tap_/3 - 1)*Wp + (tap_%3 - 1);                                \
        uint32_t sb_ = smb + ((S) & 1)*STAGE_BYTES;                               \
        const uint4* sa_ = (const uint4*)(pl[ch_] + (long long)(q0 + off_)*64);   \
        for (int i = t; i < 2048; i += 512) {                                     \
            int r_ = i >> 3, cb_ = i & 7;                                         \
            uint32_t so_ = (uint32_t)(r_*128 + ((cb_ ^ (r_ & 7)) << 4));          \
            cp16(sb_ + OFF_A + so_, sa_ + i);                                     \
        }                                                                         \
        const uint4* ws_ = wimg + (size_t)(tap_*2 + ch_)*512;                     \
        cp16(sb_ + OFF_BH + t*16, ws_ + t);                                       \
        CP_COMMIT();                                                              \
    } while (0)

    PREFETCH(0);
    for (int s = 0; s < 18; s++) {
        if (s < 17) { PREFETCH(s + 1); CP_WAIT1(); } else { CP_WAIT0(); }
        __syncthreads();
        uint32_t stb = smb + (s & 1)*STAGE_BYTES;
        #pragma unroll
        for (int ks = 0; ks < 4; ks++) {
            uint32_t aH[4];
            {
                int row = w*16 + arow_l;
                int u = ks*2 + au;
                ldm_x4(aH, stb + OFF_A + (uint32_t)(row*128 + ((u ^ (row & 7)) << 4)));
            }
            uint32_t bHf[8][2];
            #pragma unroll
            for (int npair = 0; npair < 4; npair++) {
                int r = npair*16 + brow_l;
                int u = ks*2 + bu;
                uint32_t soff = (uint32_t)(r*128 + ((u ^ (r & 7)) << 4));
                uint32_t tmp[4];
                ldm_x4(tmp, stb + OFF_BH + soff);
                bHf[npair*2][0]=tmp[0]; bHf[npair*2][1]=tmp[1];
                bHf[npair*2+1][0]=tmp[2]; bHf[npair*2+1][1]=tmp[3];
            }
            #pragma unroll
            for (int nt = 0; nt < 8; nt++)
                mma_f16(acc[nt], aH, bHf[nt]);
        }
        __syncthreads();
    }
    #undef PREFETCH

    int g = lane >> 2, tg = lane & 3;
    float* smf = (float*)sm;
    int rb = w*16 + g;
    #pragma unroll
    for (int nt = 0; nt < 8; nt++) {
        int cb = nt*8 + tg*2;
        smf[(cb+0)*257 + rb]     = acc[nt][0];
        smf[(cb+1)*257 + rb]     = acc[nt][1];
        smf[(cb+0)*257 + rb + 8] = acc[nt][2];
        smf[(cb+1)*257 + rb + 8] = acc[nt][3];
    }
    __syncthreads();
    for (int i = t; i < 16384; i += 512) {
        int oc = i >> 8, r = i & 255;
        int q = q0 + r;
        int y = q / Wp, x = q % Wp;
        if (y >= 1 && y <= H && x >= 1 && x <= W)
            out[((size_t)(b*64 + oc)*H + (y-1))*W + (x-1)] =
                fmaxf(smf[oc*257 + r] + bias[oc], 0.f);
    }
}

extern "C" void kernel_launch(void* const* d_in, const int* in_sizes, int n_in,
                              void* d_out, int out_size) {
    (void)out_size;
    const float* voxels[3] = {0,0,0};
    const int* numpts[3] = {0,0,0};
    const int* coordsp[3] = {0,0,0};
    const float *w1=0,*w2=0,*fw=0;
    const float* p192[8] = {0};
    const float* p128[4] = {0};
    int n192 = 0, n128 = 0;
    for (int i = 0; i < n_in; i++) {
        int sz = in_sizes[i];
        const void* p = d_in[i];
        switch (sz) {
            case 5120000: voxels[0] = (const float*)p; break;
            case 2560000: voxels[1] = (const float*)p; break;
            case 1024000: voxels[2] = (const float*)p; break;
            case 40000:   numpts[0] = (const int*)p; break;
            case 20000:   numpts[1] = (const int*)p; break;
            case 8000:    numpts[2] = (const int*)p; break;
            case 160000:  coordsp[0] = (const int*)p; break;
            case 80000:   coordsp[1] = (const int*)p; break;
            case 32000:   coordsp[2] = (const int*)p; break;
            case 1728:    w1 = (const float*)p; break;
            case 24576:   w2 = (const float*)p; break;
            case 147456:  fw = (const float*)p; break;
            case 192:     if (n192 < 8) p192[n192++] = (const float*)p; break;
            case 128:     if (n128 < 4) p128[n128++] = (const float*)p; break;
            default: break;
        }
    }
    const float *g1=p192[0], *b1=p192[1], *rm1=p192[2], *rv1=p192[3];
    const float *g2=p192[4], *b2=p192[5], *rm2=p192[6], *rv2=p192[7];
    const float *fg=p128[0], *fb=p128[1], *fm=p128[2], *fv=p128[3];

    __half *cat0, *cat1;
    cudaGetSymbolAddress((void**)&cat0, g_cat0t);
    cudaGetSymbolAddress((void**)&cat1, g_cat1t);
    float *sf2, *f1, *vf, *w1f, *b1f, *w2f, *b2f, *fbf;
    int* win;
    unsigned char* wimg;
    cudaGetSymbolAddress((void**)&sf2, g_sf2);
    cudaGetSymbolAddress((void**)&f1,  g_f1);
    cudaGetSymbolAddress((void**)&vf,  g_vf);
    cudaGetSymbolAddress((void**)&win, g_win);
    cudaGetSymbolAddress((void**)&w1f, g_w1f);
    cudaGetSymbolAddress((void**)&b1f, g_b1f);
    cudaGetSymbolAddress((void**)&w2f, g_w2f);
    cudaGetSymbolAddress((void**)&b2f, g_b2f);
    cudaGetSymbolAddress((void**)&fbf, g_fbf);
    cudaGetSymbolAddress((void**)&wimg, g_wimg);

    cudaFuncSetAttribute(conv_mma_kernel, cudaFuncAttributeMaxDynamicSharedMemorySize, CONV_SMEM);
    cudaFuncSetAttribute(vfe_kernel, cudaFuncAttributeMaxDynamicSharedMemorySize, VFE_SMEM);

    fold_kernel<<<1152, 256>>>(w1, g1, b1, rm1, rv1, w2, g2, b2, rm2, rv2, fw, fg, fb, fm, fv);

    zero_u4<<<2048, 256>>>((uint4*)cat0, PE0);
    zero_u4<<<1024, 256>>>((uint4*)cat1, PE1);
    zero_u4<<<512, 256>>>((uint4*)sf2, (size_t)BATCH*64*HW2/4);

    vfe_kernel<<<(NS_[0]+3)/4, 256, VFE_SMEM>>>(voxels[0], numpts[0], w1f, b1f, w2f, b2f, vf, NS_[0]);
    fill_win_kernel<<<(BATCH*HW0 + 255)/256, 256>>>(win, BATCH*HW0);
    scatter_max_kernel<<<(NS_[0] + 255)/256, 256>>>(coordsp[0], win, NS_[0], H0, W0);
    scatter_write_f16<<<NS_[0], 64>>>(coordsp[0], win, vf, cat0, PE0, H0, W0, WP0);

    vfe_kernel<<<(NS_[1]+3)/4, 256, VFE_SMEM>>>(voxels[1], numpts[1], w1f + 576, b1f + 64, w2f + 8192, b2f + 64, vf, NS_[1]);
    fill_win_kernel<<<(BATCH*HW1 + 255)/256, 256>>>(win, BATCH*HW1);
    scatter_max_kernel<<<(NS_[1] + 255)/256, 256>>>(coordsp[1], win, NS_[1], H1, W1);
    scatter_write_f16<<<NS_[1], 64>>>(coordsp[1], win, vf, cat1, PE1, H1, W1, WP1);

    vfe_kernel<<<(NS_[2]+3)/4, 256, VFE_SMEM>>>(voxels[2], numpts[2], w1f + 1152, b1f + 128, w2f + 16384, b2f + 128, vf, NS_[2]);
    fill_win_kernel<<<(BATCH*HW2 + 255)/256, 256>>>(win, BATCH*HW2);
    scatter_max_kernel<<<(NS_[2] + 255)/256, 256>>>(coordsp[2], win, NS_[2], H2, W2);
    scatter_write_f32<<<NS_[2], 64>>>(coordsp[2], win, vf, sf2, H2, W2);

    {
        dim3 g((W1 + 127)/128, H1, BATCH);
        ups_kernel<<<g, 256>>>(sf2, cat1, PE1, H2, W2, H1, W1, WP1);
    }
    {
        dim3 g((Q1 + 255)/256, BATCH);
        conv_mma_kernel<<<g, 512, CONV_SMEM>>>(cat1, PE1, WP1, H1, W1,
            (const uint4*)(wimg + 147456), fbf + 64, f1);
    }
    {
        dim3 g((W0 + 127)/128, H0, BATCH);
        ups_kernel<<<g, 256>>>(f1, cat0, PE0, H1, W1, H0, W0, WP0);
    }
    {
        dim3 g((Q0 + 255)/256, BATCH);
        conv_mma_kernel<<<g, 512, CONV_SMEM>>>(cat0, PE0, WP0, H0, W0,
            (const uint4*)wimg, fbf, (float*)d_out);
    }
}

// round 13
// speedup vs baseline: 3.9778x; 1.0393x over previous
#include <cuda_runtime.h>
#include <cuda_bf16.h>
#include <cuda_fp16.h>
#include <math.h>
#include <stdint.h>

#define EPSBN 1e-3f
static const int NS_[3] = {40000, 20000, 8000};
#define BATCH 4
#define TPTS 32
#define H0 496
#define W0 432
#define H1 248
#define W1 216
#define H2 124
#define W2 108
#define HW0 (H0*W0)
#define HW1 (H1*W1)
#define HW2 (H2*W2)
#define WP0 (W0+2)
#define Q0 ((H0+2)*WP0)
#define WP1 (W1+2)
#define Q1 ((H1+2)*WP1)
#define MR_F 512
#define MR_B 1024
#define P0 (MR_F + Q0 + MR_B)
#define P1 (MR_F + Q1 + MR_B)
#define PE0 ((size_t)P0*64)
#define PE1 ((size_t)P1*64)

__device__ float g_w1f[3*9*64];
__device__ float g_b1f[3*64];
__device__ float g_w2f[3*128*64];
__device__ float g_b2f[3*64];
__device__ float g_fbf[2*64];
__device__ unsigned char g_wimg[2*9*2*8192];
__device__ float g_vf0[40000*64];
__device__ float g_vf1[20000*64];
__device__ float g_vf2[8000*64];
__device__ int   g_win0[BATCH*HW0];
__device__ int   g_win1[BATCH*HW1];
__device__ int   g_win2[BATCH*HW2];
__device__ __half g_cat0t[8*PE0];
__device__ __half g_cat1t[8*PE1];
__device__ float g_sf2[(size_t)BATCH*64*HW2];
__device__ float g_f1 [(size_t)BATCH*64*HW1];

__device__ __forceinline__ uint32_t smem_u32(const void* p) {
    uint32_t a;
    asm("{ .reg .u64 t; cvta.to.shared.u64 t, %1; cvt.u32.u64 %0, t; }" : "=r"(a) : "l"(p));
    return a;
}
__device__ __forceinline__ void mma_f16(float* c, const uint32_t* a, const uint32_t* b) {
    asm volatile("mma.sync.aligned.m16n8k16.row.col.f32.f16.f16.f32 "
                 "{%0,%1,%2,%3}, {%4,%5,%6,%7}, {%8,%9}, {%0,%1,%2,%3};"
                 : "+f"(c[0]), "+f"(c[1]), "+f"(c[2]), "+f"(c[3])
                 : "r"(a[0]), "r"(a[1]), "r"(a[2]), "r"(a[3]), "r"(b[0]), "r"(b[1]));
}
__device__ __forceinline__ void ldm_x4(uint32_t* r, uint32_t addr) {
    asm volatile("ldmatrix.sync.aligned.m8n8.x4.shared.b16 {%0,%1,%2,%3}, [%4];"
                 : "=r"(r[0]), "=r"(r[1]), "=r"(r[2]), "=r"(r[3]) : "r"(addr));
}
__device__ __forceinline__ void cp16(uint32_t d, const void* s) {
    asm volatile("cp.async.cg.shared.global [%0], [%1], 16;" :: "r"(d), "l"(s));
}
#define CP_COMMIT() asm volatile("cp.async.commit_group;" ::: "memory")
#define CP_WAIT1()  asm volatile("cp.async.wait_group 1;" ::: "memory")
#define CP_WAIT0()  asm volatile("cp.async.wait_group 0;" ::: "memory")
#define SWZ(o) ((o) ^ (((o) >> 3) & 0x70))

#define OFF_A  0
#define OFF_BH 32768
#define STAGE_BYTES 40960
#define CONV_SMEM (2*STAGE_BYTES)
#define VFE_SMEM (18512*4)

__global__ void fold_kernel(const float* __restrict__ w1, const float* __restrict__ g1,
                            const float* __restrict__ b1, const float* __restrict__ rm1,
                            const float* __restrict__ rv1,
                            const float* __restrict__ w2, const float* __restrict__ g2,
                            const float* __restrict__ b2, const float* __restrict__ rm2,
                            const float* __restrict__ rv2,
                            const float* __restrict__ fw, const float* __restrict__ fg,
                            const float* __restrict__ fb, const float* __restrict__ fm,
                            const float* __restrict__ fv) {
    int idx = blockIdx.x * blockDim.x + threadIdx.x;
    if (idx < 1728) {
        int s = idx / 576; int d = idx % 64;
        g_w1f[idx] = w1[idx] * g1[s*64+d] * rsqrtf(rv1[s*64+d] + EPSBN);
    }
    if (idx < 24576) {
        int s = idx / 8192; int d = idx % 64;
        g_w2f[idx] = w2[idx] * g2[s*64+d] * rsqrtf(rv2[s*64+d] + EPSBN);
    }
    if (idx < 147456) {
        int l = idx / 73728; int r = idx % 73728;
        int oc = r / 1152; int rem = r % 1152;
        int ic = rem / 9; int tap = rem % 9;
        float sc = fg[l*64+oc] * rsqrtf(fv[l*64+oc] + EPSBN);
        float w = fw[(((size_t)(l*64+oc)*128 + ic)*9) + tap] * sc;
        int chunk = ic >> 6, chl = ic & 63;
        size_t tb = (size_t)l*147456 + (size_t)(tap*2+chunk)*8192;
        uint32_t so = SWZ((uint32_t)(oc*128 + chl*2));
        *(__half*)(g_wimg + tb + so) = __float2half_rn(w);
    }
    if (idx < 192) {
        g_b1f[idx] = b1[idx] - rm1[idx] * g1[idx] * rsqrtf(rv1[idx] + EPSBN);
        g_b2f[idx] = b2[idx] - rm2[idx] * g2[idx] * rsqrtf(rv2[idx] + EPSBN);
    }
    if (idx < 128) {
        g_fbf[idx] = fb[idx] - fm[idx] * fg[idx] * rsqrtf(fv[idx] + EPSBN);
    }
}

__global__ void vfe_kernel(const float* __restrict__ voxels, const int* __restrict__ numpts,
                           const float* __restrict__ w1f, const float* __restrict__ b1f,
                           const float* __restrict__ w2f, const float* __restrict__ b2f,
                           float* __restrict__ vfout, int N) {
    extern __shared__ float smf[];
    float* w1s = smf;
    float* w2s = smf + 576;
    float* b1s = smf + 8768;
    float* b2s = smf + 8832;
    int t = threadIdx.x;
    int grp = t >> 6, lt = t & 63;
    float* gb   = smf + 8896 + grp*2404;
    float* feat = gb;
    float* h1s  = gb + 288;
    float* gmaxs= gb + 2336;
    float* mean3= gb + 2400;

    for (int i = t; i < 576; i += 256)  w1s[i] = w1f[i];
    for (int i = t; i < 8192; i += 256) w2s[i] = w2f[i];
    if (t < 64) b1s[t] = b1f[t];
    else if (t < 128) b2s[t-64] = b2f[t-64];

    int v = blockIdx.x*4 + grp;
    bool valid = v < N;
    int np = valid ? numpts[v] : 1;

    float4 p = make_float4(0.f,0.f,0.f,0.f);
    if (lt < 32) {
        if (valid) p = ((const float4*)voxels)[(size_t)v * TPTS + lt];
        float sx = p.x, sy = p.y, sz = p.z;
        #pragma unroll
        for (int o = 16; o > 0; o >>= 1) {
            sx += __shfl_down_sync(0xffffffffu, sx, o);
            sy += __shfl_down_sync(0xffffffffu, sy, o);
            sz += __shfl_down_sync(0xffffffffu, sz, o);
        }
        if (lt == 0) {
            float inv = 1.0f / (float)np;
            mean3[0] = sx*inv; mean3[1] = sy*inv; mean3[2] = sz*inv;
        }
    }
    __syncthreads();
    if (lt < 32) {
        float mx = mean3[0], my = mean3[1], mz = mean3[2];
        float* f = &feat[lt*9];
        f[0]=p.x; f[1]=p.y; f[2]=p.z; f[3]=p.w;
        f[4]=p.x-mx; f[5]=p.y-my; f[6]=p.z-mz; f[7]=p.x-mx; f[8]=p.y-my;
    }
    __syncthreads();
    int c = lt;
    float b1v = b1s[c], gm = -1e30f;
    for (int tt = 0; tt < TPTS; tt++) {
        float a = b1v;
        #pragma unroll
        for (int k = 0; k < 9; k++) a = fmaf(feat[tt*9+k], w1s[k*64+c], a);
        a = fmaxf(a, 0.f);
        h1s[tt*64+c] = a;
        gm = fmaxf(gm, a);
    }
    gmaxs[c] = gm;
    __syncthreads();
    float gterm = b2s[c];
    #pragma unroll 8
    for (int j = 0; j < 64; j++) gterm = fmaf(gmaxs[j], w2s[(64+j)*64+c], gterm);
    float vmax = 0.f;
    int tt = 0;
    for (; tt + 4 <= np; tt += 4) {
        float a0=gterm,a1=gterm,a2=gterm,a3=gterm;
        const float* h0 = &h1s[tt*64];
        #pragma unroll 8
        for (int j = 0; j < 64; j++) {
            float w = w2s[j*64+c];
            a0 = fmaf(h0[j],w,a0); a1 = fmaf(h0[64+j],w,a1);
            a2 = fmaf(h0[128+j],w,a2); a3 = fmaf(h0[192+j],w,a3);
        }
        vmax = fmaxf(vmax, fmaxf(fmaxf(a0,a1), fmaxf(a2,a3)));
    }
    for (; tt < np; tt++) {
        float a = gterm;
        #pragma unroll 8
        for (int j = 0; j < 64; j++) a = fmaf(h1s[tt*64+j], w2s[j*64+c], a);
        vmax = fmaxf(vmax, a);
    }
    if (valid) vfout[(size_t)v*64 + c] = vmax;
}

__global__ void fill_win_kernel(int* __restrict__ p, int n) {
    int i = blockIdx.x * blockDim.x + threadIdx.x;
    if (i < n) p[i] = -1;
}
__global__ void scatter_max_kernel(const int* __restrict__ coords, int* __restrict__ win,
                                   int N, int H, int W) {
    int v = blockIdx.x * blockDim.x + threadIdx.x;
    if (v >= N) return;
    int b = coords[v*4];
    int y = min(max(coords[v*4+2], 0), H-1);
    int x = min(max(coords[v*4+3], 0), W-1);
    atomicMax(&win[(b*H + y)*W + x], v);
}
__global__ void scatter_write_f16(const int* __restrict__ coords, const int* __restrict__ win,
                                  const float* __restrict__ vf, __half* __restrict__ cat,
                                  size_t PE, int H, int W, int Wp) {
    int v = blockIdx.x, c = threadIdx.x;
    int b = coords[v*4];
    int y = min(max(coords[v*4+2], 0), H-1);
    int x = min(max(coords[v*4+3], 0), W-1);
    if (win[(b*H + y)*W + x] != v) return;
    float val = vf[(size_t)v*64 + c];
    cat[(size_t)(b*2)*PE + (size_t)MR_F*64 + (size_t)((y+1)*Wp + (x+1))*64 + c] = __float2half_rn(val);
}
__global__ void scatter_write_f32(const int* __restrict__ coords, const int* __restrict__ win,
                                  const float* __restrict__ vf, float* __restrict__ dst,
                                  int H, int W) {
    int v = blockIdx.x, c = threadIdx.x;
    int b = coords[v*4];
    int y = min(max(coords[v*4+2], 0), H-1);
    int x = min(max(coords[v*4+3], 0), W-1);
    if (win[(b*H + y)*W + x] != v) return;
    dst[((size_t)(b*64 + c)*H + y)*W + x] = vf[(size_t)v*64 + c];
}
__global__ void zero_u4(uint4* __restrict__ p, size_t n) {
    uint4 z = make_uint4(0,0,0,0);
    for (size_t i = (size_t)blockIdx.x*blockDim.x + threadIdx.x; i < n;
         i += (size_t)gridDim.x*blockDim.x) p[i] = z;
}

__global__ void ups_kernel(const float* __restrict__ src, __half* __restrict__ cat,
                           size_t PE, int Hi, int Wi, int Ho, int Wo, int Wp) {
    __shared__ float s[2*64*67];
    int b = blockIdx.z, y = blockIdx.y;
    int X0 = blockIdx.x * 128;
    int t = threadIdx.x;
    float fy = fminf(fmaxf(y*0.5f - 0.25f, 0.f), (float)(Hi-1));
    int y0 = (int)fy; float wy = fy - y0;
    int y1 = min(y0+1, Hi-1);
    int xb = (int)fmaxf(X0*0.5f - 0.25f, 0.f);
    const float* sb = src + (size_t)b*64*Hi*Wi;
    for (int i = t; i < 2*64*66; i += 256) {
        int xi = i % 66, c = (i/66) % 64, r = i/(66*64);
        int gx = min(xb + xi, Wi-1);
        int gy = r ? y1 : y0;
        s[(r*64 + c)*67 + xi] = sb[((size_t)c*Hi + gy)*Wi + gx];
    }
    __syncthreads();
    int co = t & 63, xg = t >> 6;
    __half* plane = cat + (size_t)(2*b+1)*PE + (size_t)MR_F*64;
    for (int k = 0; k < 32; k++) {
        int xo = X0 + xg*32 + k;
        if (xo >= Wo) break;
        float fx = fminf(fmaxf(xo*0.5f - 0.25f, 0.f), (float)(Wi-1));
        int x0 = (int)fx; float wx = fx - x0;
        int xi = x0 - xb;
        float v0 = (1.f-wx)*s[co*67+xi]      + wx*s[co*67+xi+1];
        float v1 = (1.f-wx)*s[(64+co)*67+xi] + wx*s[(64+co)*67+xi+1];
        float val = (1.f-wy)*v0 + wy*v1;
        plane[((size_t)(y+1)*Wp + (xo+1))*64 + co] = __float2half_rn(val);
    }
}

__global__ __launch_bounds__(512, 2)
void conv_mma_kernel(const __half* __restrict__ cat, size_t PE,
                     int Wp, int H, int W,
                     const uint4* __restrict__ wimg, const float* __restrict__ bias,
                     float* __restrict__ out) {
    extern __shared__ __align__(16) char sm[];
    uint32_t smb = smem_u32(sm);
    int t = threadIdx.x, lane = t & 31, w = t >> 5;
    int b = blockIdx.y;
    int q0 = blockIdx.x * 256;
    const __half* pl[2];
    #pragma unroll
    for (int c = 0; c < 2; c++)
        pl[c] = cat + (size_t)(2*b + c)*PE + (size_t)MR_F*64;

    float acc[8][4];
    #pragma unroll
    for (int nt = 0; nt < 8; nt++)
        #pragma unroll
        for (int k = 0; k < 4; k++) acc[nt][k] = 0.f;

    int arow_l = (lane & 7) + ((lane >> 3) & 1) * 8;
    int au = (lane >> 4);
    int brow_l = (lane & 7) + ((lane >> 4) & 1) * 8;
    int bu = (lane >> 3) & 1;

    #define PREFETCH(S) do {                                                      \
        int tap_ = (S) / 2, ch_ = (S) & 1;                                        \
        int off_ = (tap_/3 - 1)*Wp + (tap_%3 - 1);                                \
        uint32_t sb_ = smb + ((S) & 1)*STAGE_BYTES;                               \
        const uint4* sa_ = (const uint4*)(pl[ch_] + (long long)(q0 + off_)*64);   \
        for (int i = t; i < 2048; i += 512) {                                     \
            int r_ = i >> 3, cb_ = i & 7;                                         \
            uint32_t so_ = (uint32_t)(r_*128 + ((cb_ ^ (r_ & 7)) << 4));          \
            cp16(sb_ + OFF_A + so_, sa_ + i);                                     \
        }                                                                         \
        const uint4* ws_ = wimg + (size_t)(tap_*2 + ch_)*512;                     \
        cp16(sb_ + OFF_BH + t*16, ws_ + t);                                       \
        CP_COMMIT();                                                              \
    } while (0)

    PREFETCH(0);
    for (int s = 0; s < 18; s++) {
        if (s < 17) { PREFETCH(s + 1); CP_WAIT1(); } else { CP_WAIT0(); }
        __syncthreads();
        uint32_t stb = smb + (s & 1)*STAGE_BYTES;
        #pragma unroll
        for (int ks = 0; ks < 4; ks++) {
            uint32_t aH[4];
            {
                int row = w*16 + arow_l;
                int u = ks*2 + au;
                ldm_x4(aH, stb + OFF_A + (uint32_t)(row*128 + ((u ^ (row & 7)) << 4)));
            }
            uint32_t bHf[8][2];
            #pragma unroll
            for (int npair = 0; npair < 4; npair++) {
                int r = npair*16 + brow_l;
                int u = ks*2 + bu;
                uint32_t soff = (uint32_t)(r*128 + ((u ^ (r & 7)) << 4));
                uint32_t tmp[4];
                ldm_x4(tmp, stb + OFF_BH + soff);
                bHf[npair*2][0]=tmp[0]; bHf[npair*2][1]=tmp[1];
                bHf[npair*2+1][0]=tmp[2]; bHf[npair*2+1][1]=tmp[3];
            }
            #pragma unroll
            for (int nt = 0; nt < 8; nt++)
                mma_f16(acc[nt], aH, bHf[nt]);
        }
        __syncthreads();
    }
    #undef PREFETCH

    int g = lane >> 2, tg = lane & 3;
    float* smf = (float*)sm;
    int rb = w*16 + g;
    #pragma unroll
    for (int nt = 0; nt < 8; nt++) {
        int cb = nt*8 + tg*2;
        smf[(cb+0)*257 + rb]     = acc[nt][0];
        smf[(cb+1)*257 + rb]     = acc[nt][1];
        smf[(cb+0)*257 + rb + 8] = acc[nt][2];
        smf[(cb+1)*257 + rb + 8] = acc[nt][3];
    }
    __syncthreads();
    for (int i = t; i < 16384; i += 512) {
        int oc = i >> 8, r = i & 255;
        int q = q0 + r;
        int y = q / Wp, x = q % Wp;
        if (y >= 1 && y <= H && x >= 1 && x <= W)
            out[((size_t)(b*64 + oc)*H + (y-1))*W + (x-1)] =
                fmaxf(smf[oc*257 + r] + bias[oc], 0.f);
    }
}

extern "C" void kernel_launch(void* const* d_in, const int* in_sizes, int n_in,
                              void* d_out, int out_size) {
    (void)out_size;
    const float* voxels[3] = {0,0,0};
    const int* numpts[3] = {0,0,0};
    const int* coordsp[3] = {0,0,0};
    const float *w1=0,*w2=0,*fw=0;
    const float* p192[8] = {0};
    const float* p128[4] = {0};
    int n192 = 0, n128 = 0;
    for (int i = 0; i < n_in; i++) {
        int sz = in_sizes[i];
        const void* p = d_in[i];
        switch (sz) {
            case 5120000: voxels[0] = (const float*)p; break;
            case 2560000: voxels[1] = (const float*)p; break;
            case 1024000: voxels[2] = (const float*)p; break;
            case 40000:   numpts[0] = (const int*)p; break;
            case 20000:   numpts[1] = (const int*)p; break;
            case 8000:    numpts[2] = (const int*)p; break;
            case 160000:  coordsp[0] = (const int*)p; break;
            case 80000:   coordsp[1] = (const int*)p; break;
            case 32000:   coordsp[2] = (const int*)p; break;
            case 1728:    w1 = (const float*)p; break;
            case 24576:   w2 = (const float*)p; break;
            case 147456:  fw = (const float*)p; break;
            case 192:     if (n192 < 8) p192[n192++] = (const float*)p; break;
            case 128:     if (n128 < 4) p128[n128++] = (const float*)p; break;
            default: break;
        }
    }
    const float *g1=p192[0], *b1=p192[1], *rm1=p192[2], *rv1=p192[3];
    const float *g2=p192[4], *b2=p192[5], *rm2=p192[6], *rv2=p192[7];
    const float *fg=p128[0], *fb=p128[1], *fm=p128[2], *fv=p128[3];

    __half *cat0, *cat1;
    cudaGetSymbolAddress((void**)&cat0, g_cat0t);
    cudaGetSymbolAddress((void**)&cat1, g_cat1t);
    float *sf2, *f1, *vf0, *vf1, *vf2, *w1f, *b1f, *w2f, *b2f, *fbf;
    int *win0, *win1, *win2;
    unsigned char* wimg;
    cudaGetSymbolAddress((void**)&sf2, g_sf2);
    cudaGetSymbolAddress((void**)&f1,  g_f1);
    cudaGetSymbolAddress((void**)&vf0, g_vf0);
    cudaGetSymbolAddress((void**)&vf1, g_vf1);
    cudaGetSymbolAddress((void**)&vf2, g_vf2);
    cudaGetSymbolAddress((void**)&win0, g_win0);
    cudaGetSymbolAddress((void**)&win1, g_win1);
    cudaGetSymbolAddress((void**)&win2, g_win2);
    cudaGetSymbolAddress((void**)&w1f, g_w1f);
    cudaGetSymbolAddress((void**)&b1f, g_b1f);
    cudaGetSymbolAddress((void**)&w2f, g_w2f);
    cudaGetSymbolAddress((void**)&b2f, g_b2f);
    cudaGetSymbolAddress((void**)&fbf, g_fbf);
    cudaGetSymbolAddress((void**)&wimg, g_wimg);

    static cudaStream_t s1 = 0, s2 = 0;
    static cudaEvent_t eInit = 0, e0 = 0, e1 = 0;
    static int inited = 0;
    if (!inited) {
        cudaStreamCreateWithFlags(&s1, cudaStreamNonBlocking);
        cudaStreamCreateWithFlags(&s2, cudaStreamNonBlocking);
        cudaEventCreateWithFlags(&eInit, cudaEventDisableTiming);
        cudaEventCreateWithFlags(&e0, cudaEventDisableTiming);
        cudaEventCreateWithFlags(&e1, cudaEventDisableTiming);
        cudaFuncSetAttribute(conv_mma_kernel, cudaFuncAttributeMaxDynamicSharedMemorySize, CONV_SMEM);
        cudaFuncSetAttribute(vfe_kernel, cudaFuncAttributeMaxDynamicSharedMemorySize, VFE_SMEM);
        inited = 1;
    }

    // ---- main stream: fold + zeros, then fork ----
    fold_kernel<<<1152, 256>>>(w1, g1, b1, rm1, rv1, w2, g2, b2, rm2, rv2, fw, fg, fb, fm, fv);
    zero_u4<<<2048, 256>>>((uint4*)cat0, PE0);
    zero_u4<<<1024, 256>>>((uint4*)cat1, PE1);
    zero_u4<<<512, 256>>>((uint4*)sf2, (size_t)BATCH*64*HW2/4);
    cudaEventRecord(eInit, 0);

    // ---- branch s1: scale 1 -> cat1 chunk0 ----
    cudaStreamWaitEvent(s1, eInit, 0);
    vfe_kernel<<<(NS_[1]+3)/4, 256, VFE_SMEM, s1>>>(voxels[1], numpts[1], w1f + 576, b1f + 64, w2f + 8192, b2f + 64, vf1, NS_[1]);
    fill_win_kernel<<<(BATCH*HW1 + 255)/256, 256, 0, s1>>>(win1, BATCH*HW1);
    scatter_max_kernel<<<(NS_[1] + 255)/256, 256, 0, s1>>>(coordsp[1], win1, NS_[1], H1, W1);
    scatter_write_f16<<<NS_[1], 64, 0, s1>>>(coordsp[1], win1, vf1, cat1, PE1, H1, W1, WP1);
    cudaEventRecord(e1, s1);

    // ---- branch s2: scale 0 -> cat0 chunk0 ----
    cudaStreamWaitEvent(s2, eInit, 0);
    vfe_kernel<<<(NS_[0]+3)/4, 256, VFE_SMEM, s2>>>(voxels[0], numpts[0], w1f, b1f, w2f, b2f, vf0, NS_[0]);
    fill_win_kernel<<<(BATCH*HW0 + 255)/256, 256, 0, s2>>>(win0, BATCH*HW0);
    scatter_max_kernel<<<(NS_[0] + 255)/256, 256, 0, s2>>>(coordsp[0], win0, NS_[0], H0, W0);
    scatter_write_f16<<<NS_[0], 64, 0, s2>>>(coordsp[0], win0, vf0, cat0, PE0, H0, W0, WP0);
    cudaEventRecord(e0, s2);

    // ---- main stream: scale 2 (critical path) ----
    vfe_kernel<<<(NS_[2]+3)/4, 256, VFE_SMEM>>>(voxels[2], numpts[2], w1f + 1152, b1f + 128, w2f + 16384, b2f + 128, vf2, NS_[2]);
    fill_win_kernel<<<(BATCH*HW2 + 255)/256, 256>>>(win2, BATCH*HW2);
    scatter_max_kernel<<<(NS_[2] + 255)/256, 256>>>(coordsp[2], win2, NS_[2], H2, W2);
    scatter_write_f32<<<NS_[2], 64>>>(coordsp[2], win2, vf2, sf2, H2, W2);

    {
        dim3 g((W1 + 127)/128, H1, BATCH);
        ups_kernel<<<g, 256>>>(sf2, cat1, PE1, H2, W2, H1, W1, WP1);
    }
    cudaStreamWaitEvent(0, e1, 0);
    {
        dim3 g((Q1 + 255)/256, BATCH);
        conv_mma_kernel<<<g, 512, CONV_SMEM>>>(cat1, PE1, WP1, H1, W1,
            (const uint4*)(wimg + 147456), fbf + 64, f1);
    }
    {
        dim3 g((W0 + 127)/128, H0, BATCH);
        ups_kernel<<<g, 256>>>(f1, cat0, PE0, H1, W1, H0, W0, WP0);
    }
    cudaStreamWaitEvent(0, e0, 0);
    {
        dim3 g((Q0 + 255)/256, BATCH);
        conv_mma_kernel<<<g, 512, CONV_SMEM>>>(cat0, PE0, WP0, H0, W0,
            (const uint4*)wimg, fbf, (float*)d_out);
    }
}

// round 14
// speedup vs baseline: 4.1953x; 1.0547x over previous
#include <cuda_runtime.h>
#include <cuda_bf16.h>
#include <cuda_fp16.h>
#include <math.h>
#include <stdint.h>

#define EPSBN 1e-3f
static const int NS_[3] = {40000, 20000, 8000};
#define BATCH 4
#define TPTS 32
#define H0 496
#define W0 432
#define H1 248
#define W1 216
#define H2 124
#define W2 108
#define HW0 (H0*W0)
#define HW1 (H1*W1)
#define HW2 (H2*W2)
#define WP0 (W0+2)
#define Q0 ((H0+2)*WP0)
#define WP1 (W1+2)
#define Q1 ((H1+2)*WP1)
#define MR_F 512
#define MR_B 2048
#define P0 (MR_F + Q0 + MR_B)
#define P1 (MR_F + Q1 + MR_B)
#define PE0 ((size_t)P0*64)
#define PE1 ((size_t)P1*64)

__device__ float g_w1f[3*9*64];
__device__ float g_b1f[3*64];
__device__ float g_w2f[3*128*64];
__device__ float g_b2f[3*64];
__device__ float g_fbf[2*64];
__device__ unsigned char g_wimg[2*9*2*8192];
__device__ float g_vf0[40000*64];
__device__ float g_vf1[20000*64];
__device__ float g_vf2[8000*64];
__device__ int   g_win0[BATCH*HW0];
__device__ int   g_win1[BATCH*HW1];
__device__ int   g_win2[BATCH*HW2];
__device__ __half g_cat0t[8*PE0];
__device__ __half g_cat1t[8*PE1];
__device__ float g_sf2[(size_t)BATCH*64*HW2];
__device__ float g_f1 [(size_t)BATCH*64*HW1];

__device__ __forceinline__ uint32_t smem_u32(const void* p) {
    uint32_t a;
    asm("{ .reg .u64 t; cvta.to.shared.u64 t, %1; cvt.u32.u64 %0, t; }" : "=r"(a) : "l"(p));
    return a;
}
__device__ __forceinline__ void mma_f16(float* c, const uint32_t* a, const uint32_t* b) {
    asm volatile("mma.sync.aligned.m16n8k16.row.col.f32.f16.f16.f32 "
                 "{%0,%1,%2,%3}, {%4,%5,%6,%7}, {%8,%9}, {%0,%1,%2,%3};"
                 : "+f"(c[0]), "+f"(c[1]), "+f"(c[2]), "+f"(c[3])
                 : "r"(a[0]), "r"(a[1]), "r"(a[2]), "r"(a[3]), "r"(b[0]), "r"(b[1]));
}
__device__ __forceinline__ void ldm_x4(uint32_t* r, uint32_t addr) {
    asm volatile("ldmatrix.sync.aligned.m8n8.x4.shared.b16 {%0,%1,%2,%3}, [%4];"
                 : "=r"(r[0]), "=r"(r[1]), "=r"(r[2]), "=r"(r[3]) : "r"(addr));
}
__device__ __forceinline__ void cp16(uint32_t d, const void* s) {
    asm volatile("cp.async.cg.shared.global [%0], [%1], 16;" :: "r"(d), "l"(s));
}
#define CP_COMMIT() asm volatile("cp.async.commit_group;" ::: "memory")
#define CP_WAIT1()  asm volatile("cp.async.wait_group 1;" ::: "memory")
#define CP_WAIT0()  asm volatile("cp.async.wait_group 0;" ::: "memory")
#define SWZ(o) ((o) ^ (((o) >> 3) & 0x70))

#define A_CHUNK_BYTES (324*128)
#define OFF_B (2*A_CHUNK_BYTES)        // 82944
#define CONV_SMEM (OFF_B + 3*8192)     // 107520
#define VFE_SMEM (18512*4)

__global__ void fold_kernel(const float* __restrict__ w1, const float* __restrict__ g1,
                            const float* __restrict__ b1, const float* __restrict__ rm1,
                            const float* __restrict__ rv1,
                            const float* __restrict__ w2, const float* __restrict__ g2,
                            const float* __restrict__ b2, const float* __restrict__ rm2,
                            const float* __restrict__ rv2,
                            const float* __restrict__ fw, const float* __restrict__ fg,
                            const float* __restrict__ fb, const float* __restrict__ fm,
                            const float* __restrict__ fv) {
    int idx = blockIdx.x * blockDim.x + threadIdx.x;
    if (idx < 1728) {
        int s = idx / 576; int d = idx % 64;
        g_w1f[idx] = w1[idx] * g1[s*64+d] * rsqrtf(rv1[s*64+d] + EPSBN);
    }
    if (idx < 24576) {
        int s = idx / 8192; int d = idx % 64;
        g_w2f[idx] = w2[idx] * g2[s*64+d] * rsqrtf(rv2[s*64+d] + EPSBN);
    }
    if (idx < 147456) {
        int l = idx / 73728; int r = idx % 73728;
        int oc = r / 1152; int rem = r % 1152;
        int ic = rem / 9; int tap = rem % 9;
        float sc = fg[l*64+oc] * rsqrtf(fv[l*64+oc] + EPSBN);
        float w = fw[(((size_t)(l*64+oc)*128 + ic)*9) + tap] * sc;
        int chunk = ic >> 6, chl = ic & 63;
        size_t tb = (size_t)l*147456 + (size_t)(tap*2+chunk)*8192;
        uint32_t so = SWZ((uint32_t)(oc*128 + chl*2));
        *(__half*)(g_wimg + tb + so) = __float2half_rn(w);
    }
    if (idx < 192) {
        g_b1f[idx] = b1[idx] - rm1[idx] * g1[idx] * rsqrtf(rv1[idx] + EPSBN);
        g_b2f[idx] = b2[idx] - rm2[idx] * g2[idx] * rsqrtf(rv2[idx] + EPSBN);
    }
    if (idx < 128) {
        g_fbf[idx] = fb[idx] - fm[idx] * fg[idx] * rsqrtf(fv[idx] + EPSBN);
    }
}

__global__ void vfe_kernel(const float* __restrict__ voxels, const int* __restrict__ numpts,
                           const float* __restrict__ w1f, const float* __restrict__ b1f,
                           const float* __restrict__ w2f, const float* __restrict__ b2f,
                           float* __restrict__ vfout, int N) {
    extern __shared__ float smf[];
    float* w1s = smf;
    float* w2s = smf + 576;
    float* b1s = smf + 8768;
    float* b2s = smf + 8832;
    int t = threadIdx.x;
    int grp = t >> 6, lt = t & 63;
    float* gb   = smf + 8896 + grp*2404;
    float* feat = gb;
    float* h1s  = gb + 288;
    float* gmaxs= gb + 2336;
    float* mean3= gb + 2400;

    for (int i = t; i < 576; i += 256)  w1s[i] = w1f[i];
    for (int i = t; i < 8192; i += 256) w2s[i] = w2f[i];
    if (t < 64) b1s[t] = b1f[t];
    else if (t < 128) b2s[t-64] = b2f[t-64];

    int v = blockIdx.x*4 + grp;
    bool valid = v < N;
    int np = valid ? numpts[v] : 1;

    float4 p = make_float4(0.f,0.f,0.f,0.f);
    if (lt < 32) {
        if (valid) p = ((const float4*)voxels)[(size_t)v * TPTS + lt];
        float sx = p.x, sy = p.y, sz = p.z;
        #pragma unroll
        for (int o = 16; o > 0; o >>= 1) {
            sx += __shfl_down_sync(0xffffffffu, sx, o);
            sy += __shfl_down_sync(0xffffffffu, sy, o);
            sz += __shfl_down_sync(0xffffffffu, sz, o);
        }
        if (lt == 0) {
            float inv = 1.0f / (float)np;
            mean3[0] = sx*inv; mean3[1] = sy*inv; mean3[2] = sz*inv;
        }
    }
    __syncthreads();
    if (lt < 32) {
        float mx = mean3[0], my = mean3[1], mz = mean3[2];
        float* f = &feat[lt*9];
        f[0]=p.x; f[1]=p.y; f[2]=p.z; f[3]=p.w;
        f[4]=p.x-mx; f[5]=p.y-my; f[6]=p.z-mz; f[7]=p.x-mx; f[8]=p.y-my;
    }
    __syncthreads();
    int c = lt;
    float b1v = b1s[c], gm = -1e30f;
    for (int tt = 0; tt < TPTS; tt++) {
        float a = b1v;
        #pragma unroll
        for (int k = 0; k < 9; k++) a = fmaf(feat[tt*9+k], w1s[k*64+c], a);
        a = fmaxf(a, 0.f);
        h1s[tt*64+c] = a;
        gm = fmaxf(gm, a);
    }
    gmaxs[c] = gm;
    __syncthreads();
    float gterm = b2s[c];
    #pragma unroll 8
    for (int j = 0; j < 64; j++) gterm = fmaf(gmaxs[j], w2s[(64+j)*64+c], gterm);
    float vmax = 0.f;
    int tt = 0;
    for (; tt + 4 <= np; tt += 4) {
        float a0=gterm,a1=gterm,a2=gterm,a3=gterm;
        const float* h0 = &h1s[tt*64];
        #pragma unroll 8
        for (int j = 0; j < 64; j++) {
            float w = w2s[j*64+c];
            a0 = fmaf(h0[j],w,a0); a1 = fmaf(h0[64+j],w,a1);
            a2 = fmaf(h0[128+j],w,a2); a3 = fmaf(h0[192+j],w,a3);
        }
        vmax = fmaxf(vmax, fmaxf(fmaxf(a0,a1), fmaxf(a2,a3)));
    }
    for (; tt < np; tt++) {
        float a = gterm;
        #pragma unroll 8
        for (int j = 0; j < 64; j++) a = fmaf(h1s[tt*64+j], w2s[j*64+c], a);
        vmax = fmaxf(vmax, a);
    }
    if (valid) vfout[(size_t)v*64 + c] = vmax;
}

__global__ void fill_win_kernel(int* __restrict__ p, int n) {
    int i = blockIdx.x * blockDim.x + threadIdx.x;
    if (i < n) p[i] = -1;
}
__global__ void scatter_max_kernel(const int* __restrict__ coords, int* __restrict__ win,
                                   int N, int H, int W) {
    int v = blockIdx.x * blockDim.x + threadIdx.x;
    if (v >= N) return;
    int b = coords[v*4];
    int y = min(max(coords[v*4+2], 0), H-1);
    int x = min(max(coords[v*4+3], 0), W-1);
    atomicMax(&win[(b*H + y)*W + x], v);
}
__global__ void scatter_write_f16(const int* __restrict__ coords, const int* __restrict__ win,
                                  const float* __restrict__ vf, __half* __restrict__ cat,
                                  size_t PE, int H, int W, int Wp) {
    int v = blockIdx.x, c = threadIdx.x;
    int b = coords[v*4];
    int y = min(max(coords[v*4+2], 0), H-1);
    int x = min(max(coords[v*4+3], 0), W-1);
    if (win[(b*H + y)*W + x] != v) return;
    float val = vf[(size_t)v*64 + c];
    cat[(size_t)(b*2)*PE + (size_t)MR_F*64 + (size_t)((y+1)*Wp + (x+1))*64 + c] = __float2half_rn(val);
}
__global__ void scatter_write_f32(const int* __restrict__ coords, const int* __restrict__ win,
                                  const float* __restrict__ vf, float* __restrict__ dst,
                                  int H, int W) {
    int v = blockIdx.x, c = threadIdx.x;
    int b = coords[v*4];
    int y = min(max(coords[v*4+2], 0), H-1);
    int x = min(max(coords[v*4+3], 0), W-1);
    if (win[(b*H + y)*W + x] != v) return;
    dst[((size_t)(b*64 + c)*H + y)*W + x] = vf[(size_t)v*64 + c];
}
__global__ void zero_u4(uint4* __restrict__ p, size_t n) {
    uint4 z = make_uint4(0,0,0,0);
    for (size_t i = (size_t)blockIdx.x*blockDim.x + threadIdx.x; i < n;
         i += (size_t)gridDim.x*blockDim.x) p[i] = z;
}

__global__ void ups_kernel(const float* __restrict__ src, __half* __restrict__ cat,
                           size_t PE, int Hi, int Wi, int Ho, int Wo, int Wp) {
    __shared__ float s[2*64*67];
    int b = blockIdx.z, y = blockIdx.y;
    int X0 = blockIdx.x * 128;
    int t = threadIdx.x;
    float fy = fminf(fmaxf(y*0.5f - 0.25f, 0.f), (float)(Hi-1));
    int y0 = (int)fy; float wy = fy - y0;
    int y1 = min(y0+1, Hi-1);
    int xb = (int)fmaxf(X0*0.5f - 0.25f, 0.f);
    const float* sb = src + (size_t)b*64*Hi*Wi;
    for (int i = t; i < 2*64*66; i += 256) {
        int xi = i % 66, c = (i/66) % 64, r = i/(66*64);
        int gx = min(xb + xi, Wi-1);
        int gy = r ? y1 : y0;
        s[(r*64 + c)*67 + xi] = sb[((size_t)c*Hi + gy)*Wi + gx];
    }
    __syncthreads();
    int co = t & 63, xg = t >> 6;
    __half* plane = cat + (size_t)(2*b+1)*PE + (size_t)MR_F*64;
    for (int k = 0; k < 32; k++) {
        int xo = X0 + xg*32 + k;
        if (xo >= Wo) break;
        float fx = fminf(fmaxf(xo*0.5f - 0.25f, 0.f), (float)(Wi-1));
        int x0 = (int)fx; float wx = fx - x0;
        int xi = x0 - xb;
        float v0 = (1.f-wx)*s[co*67+xi]      + wx*s[co*67+xi+1];
        float v1 = (1.f-wx)*s[(64+co)*67+xi] + wx*s[(64+co)*67+xi+1];
        float val = (1.f-wy)*v0 + wy*v1;
        plane[((size_t)(y+1)*Wp + (xo+1))*64 + co] = __float2half_rn(val);
    }
}

// 2D-halo HMMA conv: CTA = 16x16 spatial tile; A halo (18x18x64ch x 2 chunks) loaded ONCE;
// 9 taps reuse it. B streamed via 3-slot pipeline. 16 warps, warp = one y-row x 16 x.
__global__ __launch_bounds__(512, 2)
void conv_mma_kernel(const __half* __restrict__ cat, size_t PE,
                     int Wp, int H, int W,
                     const uint4* __restrict__ wimg, const float* __restrict__ bias,
                     float* __restrict__ out) {
    extern __shared__ __align__(16) char sm[];
    uint32_t smb = smem_u32(sm);
    int t = threadIdx.x, lane = t & 31, w = t >> 5;
    int b = blockIdx.z;
    int tx0 = blockIdx.x * 16;
    int ty0 = blockIdx.y * 16;
    const __half* pl[2];
    #pragma unroll
    for (int c = 0; c < 2; c++)
        pl[c] = cat + (size_t)(2*b + c)*PE + (size_t)MR_F*64;

    float acc[8][4];
    #pragma unroll
    for (int nt = 0; nt < 8; nt++)
        #pragma unroll
        for (int k = 0; k < 4; k++) acc[nt][k] = 0.f;

    int arow_l = (lane & 7) + ((lane >> 3) & 1) * 8;
    int au = (lane >> 4);
    int brow_l = (lane & 7) + ((lane >> 4) & 1) * 8;
    int bu = (lane >> 3) & 1;

    // ---- prologue: A halo (both chunks) + B0 in group0; B1 in group1 ----
    #pragma unroll
    for (int c = 0; c < 2; c++) {
        const __half* base = pl[c];
        for (int i = t; i < 2592; i += 512) {
            int r = i >> 3, cb = i & 7;
            int hy = r / 18, hx = r % 18;
            long long q = (long long)(ty0 + hy)*Wp + (tx0 + hx);
            uint32_t so = (uint32_t)(c*A_CHUNK_BYTES + r*128 + ((cb ^ (r & 7)) << 4));
            cp16(smb + so, (const uint4*)(base + q*64) + cb);
        }
    }
    cp16(smb + OFF_B + t*16, wimg + t);            // B tile s=0 (tap0,chunk0)
    CP_COMMIT();                                    // G0 = A0,A1,B0
    cp16(smb + OFF_B + 8192 + t*16, wimg + 512 + t); // B tile s=1 (tap0,chunk1? see mapping below)
    CP_COMMIT();                                    // G1 = B1
    CP_WAIT1();
    __syncthreads();

    // step s: chunk = s%2? No — mapping: s enumerates (tap,chunk) as tileIdx = s (tap*2+chunk order)
    // wimg tiles are stored [tap*2+chunk]; iterate s = 0..17 in that same order.
    for (int s = 0; s < 18; s++) {
        int tap = s >> 1, chunk = s & 1;
        int dy = tap / 3, dx = tap % 3;
        uint32_t aBase = smb + (uint32_t)chunk*A_CHUNK_BYTES;
        uint32_t bBase = smb + OFF_B + (uint32_t)(s % 3)*8192;
        #pragma unroll
        for (int ks = 0; ks < 4; ks++) {
            uint32_t aH[4];
            {
                int h = (w + dy)*18 + dx + arow_l;
                int u = ks*2 + au;
                ldm_x4(aH, aBase + (uint32_t)(h*128 + ((u ^ (h & 7)) << 4)));
            }
            uint32_t bHf[8][2];
            #pragma unroll
            for (int npair = 0; npair < 4; npair++) {
                int r = npair*16 + brow_l;
                int u = ks*2 + bu;
                uint32_t tmp[4];
                ldm_x4(tmp, bBase + (uint32_t)(r*128 + ((u ^ (r & 7)) << 4)));
                bHf[npair*2][0]=tmp[0]; bHf[npair*2][1]=tmp[1];
                bHf[npair*2+1][0]=tmp[2]; bHf[npair*2+1][1]=tmp[3];
            }
            #pragma unroll
            for (int nt = 0; nt < 8; nt++)
                mma_f16(acc[nt], aH, bHf[nt]);
        }
        __syncthreads();
        if (s + 2 < 18) {
            cp16(smb + OFF_B + (uint32_t)((s+2) % 3)*8192 + t*16, wimg + (size_t)(s+2)*512 + t);
            CP_COMMIT();
            CP_WAIT1();
        } else {
            CP_WAIT0();
        }
        __syncthreads();
    }

    // epilogue: transpose via smem (reuses A region) -> coalesced stores
    int g = lane >> 2, tg = lane & 3;
    float* smf = (float*)sm;
    int rb = w*16 + g;
    #pragma unroll
    for (int nt = 0; nt < 8; nt++) {
        int cb = nt*8 + tg*2;
        smf[(cb+0)*257 + rb]     = acc[nt][0];
        smf[(cb+1)*257 + rb]     = acc[nt][1];
        smf[(cb+0)*257 + rb + 8] = acc[nt][2];
        smf[(cb+1)*257 + rb + 8] = acc[nt][3];
    }
    __syncthreads();
    for (int i = t; i < 16384; i += 512) {
        int oc = i >> 8, r = i & 255;
        int y = ty0 + (r >> 4), x = tx0 + (r & 15);
        if (y < H && x < W)
            out[((size_t)(b*64 + oc)*H + y)*W + x] =
                fmaxf(smf[oc*257 + r] + bias[oc], 0.f);
    }
}

extern "C" void kernel_launch(void* const* d_in, const int* in_sizes, int n_in,
                              void* d_out, int out_size) {
    (void)out_size;
    const float* voxels[3] = {0,0,0};
    const int* numpts[3] = {0,0,0};
    const int* coordsp[3] = {0,0,0};
    const float *w1=0,*w2=0,*fw=0;
    const float* p192[8] = {0};
    const float* p128[4] = {0};
    int n192 = 0, n128 = 0;
    for (int i = 0; i < n_in; i++) {
        int sz = in_sizes[i];
        const void* p = d_in[i];
        switch (sz) {
            case 5120000: voxels[0] = (const float*)p; break;
            case 2560000: voxels[1] = (const float*)p; break;
            case 1024000: voxels[2] = (const float*)p; break;
            case 40000:   numpts[0] = (const int*)p; break;
            case 20000:   numpts[1] = (const int*)p; break;
            case 8000:    numpts[2] = (const int*)p; break;
            case 160000:  coordsp[0] = (const int*)p; break;
            case 80000:   coordsp[1] = (const int*)p; break;
            case 32000:   coordsp[2] = (const int*)p; break;
            case 1728:    w1 = (const float*)p; break;
            case 24576:   w2 = (const float*)p; break;
            case 147456:  fw = (const float*)p; break;
            case 192:     if (n192 < 8) p192[n192++] = (const float*)p; break;
            case 128:     if (n128 < 4) p128[n128++] = (const float*)p; break;
            default: break;
        }
    }
    const float *g1=p192[0], *b1=p192[1], *rm1=p192[2], *rv1=p192[3];
    const float *g2=p192[4], *b2=p192[5], *rm2=p192[6], *rv2=p192[7];
    const float *fg=p128[0], *fb=p128[1], *fm=p128[2], *fv=p128[3];

    __half *cat0, *cat1;
    cudaGetSymbolAddress((void**)&cat0, g_cat0t);
    cudaGetSymbolAddress((void**)&cat1, g_cat1t);
    float *sf2, *f1, *vf0, *vf1, *vf2, *w1f, *b1f, *w2f, *b2f, *fbf;
    int *win0, *win1, *win2;
    unsigned char* wimg;
    cudaGetSymbolAddress((void**)&sf2, g_sf2);
    cudaGetSymbolAddress((void**)&f1,  g_f1);
    cudaGetSymbolAddress((void**)&vf0, g_vf0);
    cudaGetSymbolAddress((void**)&vf1, g_vf1);
    cudaGetSymbolAddress((void**)&vf2, g_vf2);
    cudaGetSymbolAddress((void**)&win0, g_win0);
    cudaGetSymbolAddress((void**)&win1, g_win1);
    cudaGetSymbolAddress((void**)&win2, g_win2);
    cudaGetSymbolAddress((void**)&w1f, g_w1f);
    cudaGetSymbolAddress((void**)&b1f, g_b1f);
    cudaGetSymbolAddress((void**)&w2f, g_w2f);
    cudaGetSymbolAddress((void**)&b2f, g_b2f);
    cudaGetSymbolAddress((void**)&fbf, g_fbf);
    cudaGetSymbolAddress((void**)&wimg, g_wimg);

    static cudaStream_t s1 = 0, s2 = 0;
    static cudaEvent_t eInit = 0, e0 = 0, e1 = 0;
    static int inited = 0;
    if (!inited) {
        cudaStreamCreateWithFlags(&s1, cudaStreamNonBlocking);
        cudaStreamCreateWithFlags(&s2, cudaStreamNonBlocking);
        cudaEventCreateWithFlags(&eInit, cudaEventDisableTiming);
        cudaEventCreateWithFlags(&e0, cudaEventDisableTiming);
        cudaEventCreateWithFlags(&e1, cudaEventDisableTiming);
        cudaFuncSetAttribute(conv_mma_kernel, cudaFuncAttributeMaxDynamicSharedMemorySize, CONV_SMEM);
        cudaFuncSetAttribute(vfe_kernel, cudaFuncAttributeMaxDynamicSharedMemorySize, VFE_SMEM);
        inited = 1;
    }

    fold_kernel<<<1152, 256>>>(w1, g1, b1, rm1, rv1, w2, g2, b2, rm2, rv2, fw, fg, fb, fm, fv);
    zero_u4<<<2048, 256>>>((uint4*)cat0, PE0);
    zero_u4<<<1024, 256>>>((uint4*)cat1, PE1);
    zero_u4<<<512, 256>>>((uint4*)sf2, (size_t)BATCH*64*HW2/4);
    cudaEventRecord(eInit, 0);

    cudaStreamWaitEvent(s1, eInit, 0);
    vfe_kernel<<<(NS_[1]+3)/4, 256, VFE_SMEM, s1>>>(voxels[1], numpts[1], w1f + 576, b1f + 64, w2f + 8192, b2f + 64, vf1, NS_[1]);
    fill_win_kernel<<<(BATCH*HW1 + 255)/256, 256, 0, s1>>>(win1, BATCH*HW1);
    scatter_max_kernel<<<(NS_[1] + 255)/256, 256, 0, s1>>>(coordsp[1], win1, NS_[1], H1, W1);
    scatter_write_f16<<<NS_[1], 64, 0, s1>>>(coordsp[1], win1, vf1, cat1, PE1, H1, W1, WP1);
    cudaEventRecord(e1, s1);

    cudaStreamWaitEvent(s2, eInit, 0);
    vfe_kernel<<<(NS_[0]+3)/4, 256, VFE_SMEM, s2>>>(voxels[0], numpts[0], w1f, b1f, w2f, b2f, vf0, NS_[0]);
    fill_win_kernel<<<(BATCH*HW0 + 255)/256, 256, 0, s2>>>(win0, BATCH*HW0);
    scatter_max_kernel<<<(NS_[0] + 255)/256, 256, 0, s2>>>(coordsp[0], win0, NS_[0], H0, W0);
    scatter_write_f16<<<NS_[0], 64, 0, s2>>>(coordsp[0], win0, vf0, cat0, PE0, H0, W0, WP0);
    cudaEventRecord(e0, s2);

    vfe_kernel<<<(NS_[2]+3)/4, 256, VFE_SMEM>>>(voxels[2], numpts[2], w1f + 1152, b1f + 128, w2f + 16384, b2f + 128, vf2, NS_[2]);
    fill_win_kernel<<<(BATCH*HW2 + 255)/256, 256>>>(win2, BATCH*HW2);
    scatter_max_kernel<<<(NS_[2] + 255)/256, 256>>>(coordsp[2], win2, NS_[2], H2, W2);
    scatter_write_f32<<<NS_[2], 64>>>(coordsp[2], win2, vf2, sf2, H2, W2);

    {
        dim3 g((W1 + 127)/128, H1, BATCH);
        ups_kernel<<<g, 256>>>(sf2, cat1, PE1, H2, W2, H1, W1, WP1);
    }
    cudaStreamWaitEvent(0, e1, 0);
    {
        dim3 g((W1 + 15)/16, (H1 + 15)/16, BATCH);
        conv_mma_kernel<<<g, 512, CONV_SMEM>>>(cat1, PE1, WP1, H1, W1,
            (const uint4*)(wimg + 147456), fbf + 64, f1);
    }
    {
        dim3 g((W0 + 127)/128, H0, BATCH);
        ups_kernel<<<g, 256>>>(f1, cat0, PE0, H1, W1, H0, W0, WP0);
    }
    cudaStreamWaitEvent(0, e0, 0);
    {
        dim3 g((W0 + 15)/16, (H0 + 15)/16, BATCH);
        conv_mma_kernel<<<g, 512, CONV_SMEM>>>(cat0, PE0, WP0, H0, W0,
            (const uint4*)wimg, fbf, (float*)d_out);
    }
}

// round 15
// speedup vs baseline: 4.3396x; 1.0344x over previous
#include <cuda_runtime.h>
#include <cuda_bf16.h>
#include <cuda_fp16.h>
#include <math.h>
#include <stdint.h>

#define EPSBN 1e-3f
static const int NS_[3] = {40000, 20000, 8000};
#define BATCH 4
#define TPTS 32
#define H0 496
#define W0 432
#define H1 248
#define W1 216
#define H2 124
#define W2 108
#define HW0 (H0*W0)
#define HW1 (H1*W1)
#define HW2 (H2*W2)
#define WP0 (W0+2)
#define Q0 ((H0+2)*WP0)
#define WP1 (W1+2)
#define Q1 ((H1+2)*WP1)
#define MR_F 512
#define MR_B 2048
#define P0 (MR_F + Q0 + MR_B)
#define P1 (MR_F + Q1 + MR_B)
#define PE0 ((size_t)P0*64)
#define PE1 ((size_t)P1*64)

__device__ float g_w1f[3*9*64];
__device__ float g_b1f[3*64];
__device__ float g_w2f[3*128*64];
__device__ float g_b2f[3*64];
__device__ float g_fbf[2*64];
__device__ unsigned char g_wimg[2*9*2*8192];
__device__ float g_vf0[40000*64];
__device__ float g_vf1[20000*64];
__device__ float g_vf2[8000*64];
__device__ int   g_win0[BATCH*HW0];
__device__ int   g_win1[BATCH*HW1];
__device__ int   g_win2[BATCH*HW2];
__device__ __half g_cat0t[8*PE0];
__device__ __half g_cat1t[8*PE1];
__device__ float g_sf2[(size_t)BATCH*64*HW2];
__device__ float g_f1 [(size_t)BATCH*64*HW1];

__device__ __forceinline__ uint32_t smem_u32(const void* p) {
    uint32_t a;
    asm("{ .reg .u64 t; cvta.to.shared.u64 t, %1; cvt.u32.u64 %0, t; }" : "=r"(a) : "l"(p));
    return a;
}
__device__ __forceinline__ void mma_f16(float* c, const uint32_t* a, const uint32_t* b) {
    asm volatile("mma.sync.aligned.m16n8k16.row.col.f32.f16.f16.f32 "
                 "{%0,%1,%2,%3}, {%4,%5,%6,%7}, {%8,%9}, {%0,%1,%2,%3};"
                 : "+f"(c[0]), "+f"(c[1]), "+f"(c[2]), "+f"(c[3])
                 : "r"(a[0]), "r"(a[1]), "r"(a[2]), "r"(a[3]), "r"(b[0]), "r"(b[1]));
}
__device__ __forceinline__ void ldm_x4(uint32_t* r, uint32_t addr) {
    asm volatile("ldmatrix.sync.aligned.m8n8.x4.shared.b16 {%0,%1,%2,%3}, [%4];"
                 : "=r"(r[0]), "=r"(r[1]), "=r"(r[2]), "=r"(r[3]) : "r"(addr));
}
__device__ __forceinline__ void cp16(uint32_t d, const void* s) {
    asm volatile("cp.async.cg.shared.global [%0], [%1], 16;" :: "r"(d), "l"(s));
}
#define CP_COMMIT() asm volatile("cp.async.commit_group;" ::: "memory")
#define CP_WAIT1()  asm volatile("cp.async.wait_group 1;" ::: "memory")
#define CP_WAIT0()  asm volatile("cp.async.wait_group 0;" ::: "memory")
#define SWZ(o) ((o) ^ (((o) >> 3) & 0x70))

#define A_CHUNK_BYTES (324*128)
#define OFF_B (2*A_CHUNK_BYTES)        // 82944
#define CONV_SMEM (OFF_B + 3*8192)     // 107520
#define VFE_SMEM (18512*4)

__global__ void fold_kernel(const float* __restrict__ w1, const float* __restrict__ g1,
                            const float* __restrict__ b1, const float* __restrict__ rm1,
                            const float* __restrict__ rv1,
                            const float* __restrict__ w2, const float* __restrict__ g2,
                            const float* __restrict__ b2, const float* __restrict__ rm2,
                            const float* __restrict__ rv2,
                            const float* __restrict__ fw, const float* __restrict__ fg,
                            const float* __restrict__ fb, const float* __restrict__ fm,
                            const float* __restrict__ fv) {
    int idx = blockIdx.x * blockDim.x + threadIdx.x;
    if (idx < 1728) {
        int s = idx / 576; int d = idx % 64;
        g_w1f[idx] = w1[idx] * g1[s*64+d] * rsqrtf(rv1[s*64+d] + EPSBN);
    }
    if (idx < 24576) {
        int s = idx / 8192; int d = idx % 64;
        g_w2f[idx] = w2[idx] * g2[s*64+d] * rsqrtf(rv2[s*64+d] + EPSBN);
    }
    if (idx < 147456) {
        int l = idx / 73728; int r = idx % 73728;
        int oc = r / 1152; int rem = r % 1152;
        int ic = rem / 9; int tap = rem % 9;
        float sc = fg[l*64+oc] * rsqrtf(fv[l*64+oc] + EPSBN);
        float w = fw[(((size_t)(l*64+oc)*128 + ic)*9) + tap] * sc;
        int chunk = ic >> 6, chl = ic & 63;
        size_t tb = (size_t)l*147456 + (size_t)(tap*2+chunk)*8192;
        uint32_t so = SWZ((uint32_t)(oc*128 + chl*2));
        *(__half*)(g_wimg + tb + so) = __float2half_rn(w);
    }
    if (idx < 192) {
        g_b1f[idx] = b1[idx] - rm1[idx] * g1[idx] * rsqrtf(rv1[idx] + EPSBN);
        g_b2f[idx] = b2[idx] - rm2[idx] * g2[idx] * rsqrtf(rv2[idx] + EPSBN);
    }
    if (idx < 128) {
        g_fbf[idx] = fb[idx] - fm[idx] * fg[idx] * rsqrtf(fv[idx] + EPSBN);
    }
}

__global__ void vfe_kernel(const float* __restrict__ voxels, const int* __restrict__ numpts,
                           const float* __restrict__ w1f, const float* __restrict__ b1f,
                           const float* __restrict__ w2f, const float* __restrict__ b2f,
                           float* __restrict__ vfout, int N) {
    extern __shared__ float smf[];
    float* w1s = smf;
    float* w2s = smf + 576;
    float* b1s = smf + 8768;
    float* b2s = smf + 8832;
    int t = threadIdx.x;
    int grp = t >> 6, lt = t & 63;
    float* gb   = smf + 8896 + grp*2404;
    float* feat = gb;
    float* h1s  = gb + 288;
    float* gmaxs= gb + 2336;
    float* mean3= gb + 2400;

    for (int i = t; i < 576; i += 256)  w1s[i] = w1f[i];
    for (int i = t; i < 8192; i += 256) w2s[i] = w2f[i];
    if (t < 64) b1s[t] = b1f[t];
    else if (t < 128) b2s[t-64] = b2f[t-64];

    int v = blockIdx.x*4 + grp;
    bool valid = v < N;
    int np = valid ? numpts[v] : 1;

    float4 p = make_float4(0.f,0.f,0.f,0.f);
    if (lt < 32) {
        if (valid) p = ((const float4*)voxels)[(size_t)v * TPTS + lt];
        float sx = p.x, sy = p.y, sz = p.z;
        #pragma unroll
        for (int o = 16; o > 0; o >>= 1) {
            sx += __shfl_down_sync(0xffffffffu, sx, o);
            sy += __shfl_down_sync(0xffffffffu, sy, o);
            sz += __shfl_down_sync(0xffffffffu, sz, o);
        }
        if (lt == 0) {
            float inv = 1.0f / (float)np;
            mean3[0] = sx*inv; mean3[1] = sy*inv; mean3[2] = sz*inv;
        }
    }
    __syncthreads();
    if (lt < 32) {
        float mx = mean3[0], my = mean3[1], mz = mean3[2];
        float* f = &feat[lt*9];
        f[0]=p.x; f[1]=p.y; f[2]=p.z; f[3]=p.w;
        f[4]=p.x-mx; f[5]=p.y-my; f[6]=p.z-mz; f[7]=p.x-mx; f[8]=p.y-my;
    }
    __syncthreads();
    int c = lt;
    float b1v = b1s[c], gm = -1e30f;
    for (int tt = 0; tt < TPTS; tt++) {
        float a = b1v;
        #pragma unroll
        for (int k = 0; k < 9; k++) a = fmaf(feat[tt*9+k], w1s[k*64+c], a);
        a = fmaxf(a, 0.f);
        h1s[tt*64+c] = a;
        gm = fmaxf(gm, a);
    }
    gmaxs[c] = gm;
    __syncthreads();
    float gterm = b2s[c];
    #pragma unroll 8
    for (int j = 0; j < 64; j++) gterm = fmaf(gmaxs[j], w2s[(64+j)*64+c], gterm);
    float vmax = 0.f;
    int tt = 0;
    for (; tt + 4 <= np; tt += 4) {
        float a0=gterm,a1=gterm,a2=gterm,a3=gterm;
        const float* h0 = &h1s[tt*64];
        #pragma unroll 8
        for (int j = 0; j < 64; j++) {
            float w = w2s[j*64+c];
            a0 = fmaf(h0[j],w,a0); a1 = fmaf(h0[64+j],w,a1);
            a2 = fmaf(h0[128+j],w,a2); a3 = fmaf(h0[192+j],w,a3);
        }
        vmax = fmaxf(vmax, fmaxf(fmaxf(a0,a1), fmaxf(a2,a3)));
    }
    for (; tt < np; tt++) {
        float a = gterm;
        #pragma unroll 8
        for (int j = 0; j < 64; j++) a = fmaf(h1s[tt*64+j], w2s[j*64+c], a);
        vmax = fmaxf(vmax, a);
    }
    if (valid) vfout[(size_t)v*64 + c] = vmax;
}

__global__ void fill_win_kernel(int* __restrict__ p, int n) {
    int i = blockIdx.x * blockDim.x + threadIdx.x;
    if (i < n) p[i] = -1;
}
__global__ void scatter_max_kernel(const int* __restrict__ coords, int* __restrict__ win,
                                   int N, int H, int W) {
    int v = blockIdx.x * blockDim.x + threadIdx.x;
    if (v >= N) return;
    int b = coords[v*4];
    int y = min(max(coords[v*4+2], 0), H-1);
    int x = min(max(coords[v*4+3], 0), W-1);
    atomicMax(&win[(b*H + y)*W + x], v);
}
__global__ void scatter_write_f16(const int* __restrict__ coords, const int* __restrict__ win,
                                  const float* __restrict__ vf, __half* __restrict__ cat,
                                  size_t PE, int H, int W, int Wp) {
    int v = blockIdx.x, c = threadIdx.x;
    int b = coords[v*4];
    int y = min(max(coords[v*4+2], 0), H-1);
    int x = min(max(coords[v*4+3], 0), W-1);
    if (win[(b*H + y)*W + x] != v) return;
    float val = vf[(size_t)v*64 + c];
    cat[(size_t)(b*2)*PE + (size_t)MR_F*64 + (size_t)((y+1)*Wp + (x+1))*64 + c] = __float2half_rn(val);
}
__global__ void scatter_write_f32(const int* __restrict__ coords, const int* __restrict__ win,
                                  const float* __restrict__ vf, float* __restrict__ dst,
                                  int H, int W) {
    int v = blockIdx.x, c = threadIdx.x;
    int b = coords[v*4];
    int y = min(max(coords[v*4+2], 0), H-1);
    int x = min(max(coords[v*4+3], 0), W-1);
    if (win[(b*H + y)*W + x] != v) return;
    dst[((size_t)(b*64 + c)*H + y)*W + x] = vf[(size_t)v*64 + c];
}
__global__ void zero_u4(uint4* __restrict__ p, size_t n) {
    uint4 z = make_uint4(0,0,0,0);
    for (size_t i = (size_t)blockIdx.x*blockDim.x + threadIdx.x; i < n;
         i += (size_t)gridDim.x*blockDim.x) p[i] = z;
}

__global__ void ups_kernel(const float* __restrict__ src, __half* __restrict__ cat,
                           size_t PE, int Hi, int Wi, int Ho, int Wo, int Wp) {
    __shared__ float s[2*64*67];
    int b = blockIdx.z, y = blockIdx.y;
    int X0 = blockIdx.x * 128;
    int t = threadIdx.x;
    float fy = fminf(fmaxf(y*0.5f - 0.25f, 0.f), (float)(Hi-1));
    int y0 = (int)fy; float wy = fy - y0;
    int y1 = min(y0+1, Hi-1);
    int xb = (int)fmaxf(X0*0.5f - 0.25f, 0.f);
    const float* sb = src + (size_t)b*64*Hi*Wi;
    for (int i = t; i < 2*64*66; i += 256) {
        int xi = i % 66, c = (i/66) % 64, r = i/(66*64);
        int gx = min(xb + xi, Wi-1);
        int gy = r ? y1 : y0;
        s[(r*64 + c)*67 + xi] = sb[((size_t)c*Hi + gy)*Wi + gx];
    }
    __syncthreads();
    int co = t & 63, xg = t >> 6;
    __half* plane = cat + (size_t)(2*b+1)*PE + (size_t)MR_F*64;
    for (int k = 0; k < 32; k++) {
        int xo = X0 + xg*32 + k;
        if (xo >= Wo) break;
        float fx = fminf(fmaxf(xo*0.5f - 0.25f, 0.f), (float)(Wi-1));
        int x0 = (int)fx; float wx = fx - x0;
        int xi = x0 - xb;
        float v0 = (1.f-wx)*s[co*67+xi]      + wx*s[co*67+xi+1];
        float v1 = (1.f-wx)*s[(64+co)*67+xi] + wx*s[(64+co)*67+xi+1];
        float val = (1.f-wy)*v0 + wy*v1;
        plane[((size_t)(y+1)*Wp + (xo+1))*64 + co] = __float2half_rn(val);
    }
}

// 2D-halo HMMA conv, single-sync pipeline, chunk-major step order.
__global__ __launch_bounds__(512, 2)
void conv_mma_kernel(const __half* __restrict__ cat, size_t PE,
                     int Wp, int H, int W,
                     const uint4* __restrict__ wimg, const float* __restrict__ bias,
                     float* __restrict__ out) {
    extern __shared__ __align__(16) char sm[];
    uint32_t smb = smem_u32(sm);
    int t = threadIdx.x, lane = t & 31, w = t >> 5;
    int b = blockIdx.z;
    int tx0 = blockIdx.x * 16;
    int ty0 = blockIdx.y * 16;
    const __half* pl[2];
    #pragma unroll
    for (int c = 0; c < 2; c++)
        pl[c] = cat + (size_t)(2*b + c)*PE + (size_t)MR_F*64;

    float acc[8][4];
    #pragma unroll
    for (int nt = 0; nt < 8; nt++)
        #pragma unroll
        for (int k = 0; k < 4; k++) acc[nt][k] = 0.f;

    int arow_l = (lane & 7) + ((lane >> 3) & 1) * 8;
    int au = (lane >> 4);
    int brow_l = (lane & 7) + ((lane >> 4) & 1) * 8;
    int bu = (lane >> 3) & 1;

    // step s: chunk = s/9, tap = s%9; B tile index in wimg = tap*2+chunk
    #define BT(S) ((size_t)((((S) % 9) * 2) + ((S) / 9)) * 512)

    // prologue: G0 = A(c0) + B(0); G1 = A(c1) + B(1)
    #pragma unroll
    for (int c = 0; c < 2; c++) {
        const __half* base = pl[c];
        for (int i = t; i < 2592; i += 512) {
            int r = i >> 3, cb = i & 7;
            int hy = r / 18, hx = r % 18;
            long long q = (long long)(ty0 + hy)*Wp + (tx0 + hx);
            uint32_t so = (uint32_t)(c*A_CHUNK_BYTES + r*128 + ((cb ^ (r & 7)) << 4));
            cp16(smb + so, (const uint4*)(base + q*64) + cb);
        }
        cp16(smb + OFF_B + (uint32_t)c*8192 + t*16, wimg + BT(c) + t);
        CP_COMMIT();
    }

    for (int s = 0; s < 18; s++) {
        CP_WAIT1();
        __syncthreads();
        if (s + 2 < 18) {
            cp16(smb + OFF_B + (uint32_t)((s+2) % 3)*8192 + t*16, wimg + BT(s+2) + t);
            CP_COMMIT();
        } else {
            CP_COMMIT();   // empty group keeps WAIT1 accounting uniform
        }
        int chunk = s / 9, tap = s % 9;
        int dy = tap / 3, dx = tap % 3;
        uint32_t aBase = smb + (uint32_t)chunk*A_CHUNK_BYTES;
        uint32_t bBase = smb + OFF_B + (uint32_t)(s % 3)*8192;
        #pragma unroll
        for (int ks = 0; ks < 4; ks++) {
            uint32_t aH[4];
            {
                int h = (w + dy)*18 + dx + arow_l;
                int u = ks*2 + au;
                ldm_x4(aH, aBase + (uint32_t)(h*128 + ((u ^ (h & 7)) << 4)));
            }
            uint32_t bHf[8][2];
            #pragma unroll
            for (int npair = 0; npair < 4; npair++) {
                int r = npair*16 + brow_l;
                int u = ks*2 + bu;
                uint32_t tmp[4];
                ldm_x4(tmp, bBase + (uint32_t)(r*128 + ((u ^ (r & 7)) << 4)));
                bHf[npair*2][0]=tmp[0]; bHf[npair*2][1]=tmp[1];
                bHf[npair*2+1][0]=tmp[2]; bHf[npair*2+1][1]=tmp[3];
            }
            #pragma unroll
            for (int nt = 0; nt < 8; nt++)
                mma_f16(acc[nt], aH, bHf[nt]);
        }
    }
    #undef BT
    CP_WAIT0();
    __syncthreads();

    // epilogue: conflict-free transpose (stride 260) -> coalesced stores
    int g = lane >> 2, tg = lane & 3;
    float* smf = (float*)sm;
    int rb = w*16 + g;
    #pragma unroll
    for (int nt = 0; nt < 8; nt++) {
        int cb = nt*8 + tg*2;
        smf[(cb+0)*260 + rb]     = acc[nt][0];
        smf[(cb+1)*260 + rb]     = acc[nt][1];
        smf[(cb+0)*260 + rb + 8] = acc[nt][2];
        smf[(cb+1)*260 + rb + 8] = acc[nt][3];
    }
    __syncthreads();
    for (int i = t; i < 16384; i += 512) {
        int oc = i >> 8, r = i & 255;
        int y = ty0 + (r >> 4), x = tx0 + (r & 15);
        if (y < H && x < W)
            out[((size_t)(b*64 + oc)*H + y)*W + x] =
                fmaxf(smf[oc*260 + r] + bias[oc], 0.f);
    }
}

extern "C" void kernel_launch(void* const* d_in, const int* in_sizes, int n_in,
                              void* d_out, int out_size) {
    (void)out_size;
    const float* voxels[3] = {0,0,0};
    const int* numpts[3] = {0,0,0};
    const int* coordsp[3] = {0,0,0};
    const float *w1=0,*w2=0,*fw=0;
    const float* p192[8] = {0};
    const float* p128[4] = {0};
    int n192 = 0, n128 = 0;
    for (int i = 0; i < n_in; i++) {
        int sz = in_sizes[i];
        const void* p = d_in[i];
        switch (sz) {
            case 5120000: voxels[0] = (const float*)p; break;
            case 2560000: voxels[1] = (const float*)p; break;
            case 1024000: voxels[2] = (const float*)p; break;
            case 40000:   numpts[0] = (const int*)p; break;
            case 20000:   numpts[1] = (const int*)p; break;
            case 8000:    numpts[2] = (const int*)p; break;
            case 160000:  coordsp[0] = (const int*)p; break;
            case 80000:   coordsp[1] = (const int*)p; break;
            case 32000:   coordsp[2] = (const int*)p; break;
            case 1728:    w1 = (const float*)p; break;
            case 24576:   w2 = (const float*)p; break;
            case 147456:  fw = (const float*)p; break;
            case 192:     if (n192 < 8) p192[n192++] = (const float*)p; break;
            case 128:     if (n128 < 4) p128[n128++] = (const float*)p; break;
            default: break;
        }
    }
    const float *g1=p192[0], *b1=p192[1], *rm1=p192[2], *rv1=p192[3];
    const float *g2=p192[4], *b2=p192[5], *rm2=p192[6], *rv2=p192[7];
    const float *fg=p128[0], *fb=p128[1], *fm=p128[2], *fv=p128[3];

    __half *cat0, *cat1;
    cudaGetSymbolAddress((void**)&cat0, g_cat0t);
    cudaGetSymbolAddress((void**)&cat1, g_cat1t);
    float *sf2, *f1, *vf0, *vf1, *vf2, *w1f, *b1f, *w2f, *b2f, *fbf;
    int *win0, *win1, *win2;
    unsigned char* wimg;
    cudaGetSymbolAddress((void**)&sf2, g_sf2);
    cudaGetSymbolAddress((void**)&f1,  g_f1);
    cudaGetSymbolAddress((void**)&vf0, g_vf0);
    cudaGetSymbolAddress((void**)&vf1, g_vf1);
    cudaGetSymbolAddress((void**)&vf2, g_vf2);
    cudaGetSymbolAddress((void**)&win0, g_win0);
    cudaGetSymbolAddress((void**)&win1, g_win1);
    cudaGetSymbolAddress((void**)&win2, g_win2);
    cudaGetSymbolAddress((void**)&w1f, g_w1f);
    cudaGetSymbolAddress((void**)&b1f, g_b1f);
    cudaGetSymbolAddress((void**)&w2f, g_w2f);
    cudaGetSymbolAddress((void**)&b2f, g_b2f);
    cudaGetSymbolAddress((void**)&fbf, g_fbf);
    cudaGetSymbolAddress((void**)&wimg, g_wimg);

    static cudaStream_t s1 = 0, s2 = 0;
    static cudaEvent_t eInit = 0, e0 = 0, e1 = 0, eZ0 = 0, eZ1 = 0;
    static int inited = 0;
    if (!inited) {
        cudaStreamCreateWithFlags(&s1, cudaStreamNonBlocking);
        cudaStreamCreateWithFlags(&s2, cudaStreamNonBlocking);
        cudaEventCreateWithFlags(&eInit, cudaEventDisableTiming);
        cudaEventCreateWithFlags(&e0, cudaEventDisableTiming);
        cudaEventCreateWithFlags(&e1, cudaEventDisableTiming);
        cudaEventCreateWithFlags(&eZ0, cudaEventDisableTiming);
        cudaEventCreateWithFlags(&eZ1, cudaEventDisableTiming);
        cudaFuncSetAttribute(conv_mma_kernel, cudaFuncAttributeMaxDynamicSharedMemorySize, CONV_SMEM);
        cudaFuncSetAttribute(vfe_kernel, cudaFuncAttributeMaxDynamicSharedMemorySize, VFE_SMEM);
        inited = 1;
    }

    // ---- main: fold only, then fork ----
    fold_kernel<<<1152, 256>>>(w1, g1, b1, rm1, rv1, w2, g2, b2, rm2, rv2, fw, fg, fb, fm, fv);
    cudaEventRecord(eInit, 0);

    // ---- branch s1: zero cat1 + scale 1 ----
    cudaStreamWaitEvent(s1, eInit, 0);
    zero_u4<<<1024, 256, 0, s1>>>((uint4*)cat1, PE1);
    cudaEventRecord(eZ1, s1);
    vfe_kernel<<<(NS_[1]+3)/4, 256, VFE_SMEM, s1>>>(voxels[1], numpts[1], w1f + 576, b1f + 64, w2f + 8192, b2f + 64, vf1, NS_[1]);
    fill_win_kernel<<<(BATCH*HW1 + 255)/256, 256, 0, s1>>>(win1, BATCH*HW1);
    scatter_max_kernel<<<(NS_[1] + 255)/256, 256, 0, s1>>>(coordsp[1], win1, NS_[1], H1, W1);
    scatter_write_f16<<<NS_[1], 64, 0, s1>>>(coordsp[1], win1, vf1, cat1, PE1, H1, W1, WP1);
    cudaEventRecord(e1, s1);

    // ---- branch s2: zero cat0 + scale 0 ----
    cudaStreamWaitEvent(s2, eInit, 0);
    zero_u4<<<2048, 256, 0, s2>>>((uint4*)cat0, PE0);
    cudaEventRecord(eZ0, s2);
    vfe_kernel<<<(NS_[0]+3)/4, 256, VFE_SMEM, s2>>>(voxels[0], numpts[0], w1f, b1f, w2f, b2f, vf0, NS_[0]);
    fill_win_kernel<<<(BATCH*HW0 + 255)/256, 256, 0, s2>>>(win0, BATCH*HW0);
    scatter_max_kernel<<<(NS_[0] + 255)/256, 256, 0, s2>>>(coordsp[0], win0, NS_[0], H0, W0);
    scatter_write_f16<<<NS_[0], 64, 0, s2>>>(coordsp[0], win0, vf0, cat0, PE0, H0, W0, WP0);
    cudaEventRecord(e0, s2);

    // ---- main: scale 2 (critical path) ----
    zero_u4<<<512, 256>>>((uint4*)sf2, (size_t)BATCH*64*HW2/4);
    vfe_kernel<<<(NS_[2]+3)/4, 256, VFE_SMEM>>>(voxels[2], numpts[2], w1f + 1152, b1f + 128, w2f + 16384, b2f + 128, vf2, NS_[2]);
    fill_win_kernel<<<(BATCH*HW2 + 255)/256, 256>>>(win2, BATCH*HW2);
    scatter_max_kernel<<<(NS_[2] + 255)/256, 256>>>(coordsp[2], win2, NS_[2], H2, W2);
    scatter_write_f32<<<NS_[2], 64>>>(coordsp[2], win2, vf2, sf2, H2, W2);

    cudaStreamWaitEvent(0, eZ1, 0);
    {
        dim3 g((W1 + 127)/128, H1, BATCH);
        ups_kernel<<<g, 256>>>(sf2, cat1, PE1, H2, W2, H1, W1, WP1);
    }
    cudaStreamWaitEvent(0, e1, 0);
    {
        dim3 g((W1 + 15)/16, (H1 + 15)/16, BATCH);
        conv_mma_kernel<<<g, 512, CONV_SMEM>>>(cat1, PE1, WP1, H1, W1,
            (const uint4*)(wimg + 147456), fbf + 64, f1);
    }
    cudaStreamWaitEvent(0, eZ0, 0);
    {
        dim3 g((W0 + 127)/128, H0, BATCH);
        ups_kernel<<<g, 256>>>(f1, cat0, PE0, H1, W1, H0, W0, WP0);
    }
    cudaStreamWaitEvent(0, e0, 0);
    {
        dim3 g((W0 + 15)/16, (H0 + 15)/16, BATCH);
        conv_mma_kernel<<<g, 512, CONV_SMEM>>>(cat0, PE0, WP0, H0, W0,
            (const uint4*)wimg, fbf, (float*)d_out);
    }
}

// round 16
// speedup vs baseline: 4.3706x; 1.0071x over previous
#include <cuda_runtime.h>
#include <cuda_bf16.h>
#include <cuda_fp16.h>
#include <math.h>
#include <stdint.h>

#define EPSBN 1e-3f
static const int NS_[3] = {40000, 20000, 8000};
#define BATCH 4
#define TPTS 32
#define H0 496
#define W0 432
#define H1 248
#define W1 216
#define H2 124
#define W2 108
#define HW0 (H0*W0)
#define HW1 (H1*W1)
#define HW2 (H2*W2)
#define WP0 (W0+2)
#define Q0 ((H0+2)*WP0)
#define WP1 (W1+2)
#define Q1 ((H1+2)*WP1)
#define MR_F 512
#define MR_B 8192
#define P0 (MR_F + Q0 + MR_B)
#define P1 (MR_F + Q1 + MR_B)
#define PE0 ((size_t)P0*64)
#define PE1 ((size_t)P1*64)

__device__ float g_w1f[3*9*64];
__device__ float g_b1f[3*64];
__device__ float g_w2f[3*128*64];
__device__ float g_b2f[3*64];
__device__ float g_fbf[2*64];
__device__ unsigned char g_wimg[2*9*2*8192];
__device__ float g_vf0[40000*64];
__device__ float g_vf1[20000*64];
__device__ float g_vf2[8000*64];
__device__ int   g_win0[BATCH*HW0];
__device__ int   g_win1[BATCH*HW1];
__device__ int   g_win2[BATCH*HW2];
__device__ __half g_cat0t[8*PE0];
__device__ __half g_cat1t[8*PE1];
__device__ float g_sf2[(size_t)BATCH*64*HW2];
__device__ float g_f1 [(size_t)BATCH*64*HW1];

__device__ __forceinline__ uint32_t smem_u32(const void* p) {
    uint32_t a;
    asm("{ .reg .u64 t; cvta.to.shared.u64 t, %1; cvt.u32.u64 %0, t; }" : "=r"(a) : "l"(p));
    return a;
}
__device__ __forceinline__ void mma_f16(float* c, const uint32_t* a, const uint32_t* b) {
    asm volatile("mma.sync.aligned.m16n8k16.row.col.f32.f16.f16.f32 "
                 "{%0,%1,%2,%3}, {%4,%5,%6,%7}, {%8,%9}, {%0,%1,%2,%3};"
                 : "+f"(c[0]), "+f"(c[1]), "+f"(c[2]), "+f"(c[3])
                 : "r"(a[0]), "r"(a[1]), "r"(a[2]), "r"(a[3]), "r"(b[0]), "r"(b[1]));
}
__device__ __forceinline__ void ldm_x4(uint32_t* r, uint32_t addr) {
    asm volatile("ldmatrix.sync.aligned.m8n8.x4.shared.b16 {%0,%1,%2,%3}, [%4];"
                 : "=r"(r[0]), "=r"(r[1]), "=r"(r[2]), "=r"(r[3]) : "r"(addr));
}
__device__ __forceinline__ void cp16(uint32_t d, const void* s) {
    asm volatile("cp.async.cg.shared.global [%0], [%1], 16;" :: "r"(d), "l"(s));
}
#define CP_COMMIT() asm volatile("cp.async.commit_group;" ::: "memory")
#define CP_WAIT1()  asm volatile("cp.async.wait_group 1;" ::: "memory")
#define CP_WAIT0()  asm volatile("cp.async.wait_group 0;" ::: "memory")
#define SWZ(o) ((o) ^ (((o) >> 3) & 0x70))

#define TILE_H 32
#define A_BYTES (612*128)              // (TILE_H+2)*18 rows x 128B
#define OFF_B (2*A_BYTES)              // 156672
#define CONV_SMEM (OFF_B + 3*8192)     // 181248
#define VFE_SMEM (18512*4)

__global__ void fold_kernel(const float* __restrict__ w1, const float* __restrict__ g1,
                            const float* __restrict__ b1, const float* __restrict__ rm1,
                            const float* __restrict__ rv1,
                            const float* __restrict__ w2, const float* __restrict__ g2,
                            const float* __restrict__ b2, const float* __restrict__ rm2,
                            const float* __restrict__ rv2,
                            const float* __restrict__ fw, const float* __restrict__ fg,
                            const float* __restrict__ fb, const float* __restrict__ fm,
                            const float* __restrict__ fv) {
    int idx = blockIdx.x * blockDim.x + threadIdx.x;
    if (idx < 1728) {
        int s = idx / 576; int d = idx % 64;
        g_w1f[idx] = w1[idx] * g1[s*64+d] * rsqrtf(rv1[s*64+d] + EPSBN);
    }
    if (idx < 24576) {
        int s = idx / 8192; int d = idx % 64;
        g_w2f[idx] = w2[idx] * g2[s*64+d] * rsqrtf(rv2[s*64+d] + EPSBN);
    }
    if (idx < 147456) {
        int l = idx / 73728; int r = idx % 73728;
        int oc = r / 1152; int rem = r % 1152;
        int ic = rem / 9; int tap = rem % 9;
        float sc = fg[l*64+oc] * rsqrtf(fv[l*64+oc] + EPSBN);
        float w = fw[(((size_t)(l*64+oc)*128 + ic)*9) + tap] * sc;
        int chunk = ic >> 6, chl = ic & 63;
        size_t tb = (size_t)l*147456 + (size_t)(tap*2+chunk)*8192;
        uint32_t so = SWZ((uint32_t)(oc*128 + chl*2));
        *(__half*)(g_wimg + tb + so) = __float2half_rn(w);
    }
    if (idx < 192) {
        g_b1f[idx] = b1[idx] - rm1[idx] * g1[idx] * rsqrtf(rv1[idx] + EPSBN);
        g_b2f[idx] = b2[idx] - rm2[idx] * g2[idx] * rsqrtf(rv2[idx] + EPSBN);
    }
    if (idx < 128) {
        g_fbf[idx] = fb[idx] - fm[idx] * fg[idx] * rsqrtf(fv[idx] + EPSBN);
    }
}

__global__ void vfe_kernel(const float* __restrict__ voxels, const int* __restrict__ numpts,
                           const float* __restrict__ w1f, const float* __restrict__ b1f,
                           const float* __restrict__ w2f, const float* __restrict__ b2f,
                           float* __restrict__ vfout, int N) {
    extern __shared__ float smf[];
    float* w1s = smf;
    float* w2s = smf + 576;
    float* b1s = smf + 8768;
    float* b2s = smf + 8832;
    int t = threadIdx.x;
    int grp = t >> 6, lt = t & 63;
    float* gb   = smf + 8896 + grp*2404;
    float* feat = gb;
    float* h1s  = gb + 288;
    float* gmaxs= gb + 2336;
    float* mean3= gb + 2400;

    for (int i = t; i < 576; i += 256)  w1s[i] = w1f[i];
    for (int i = t; i < 8192; i += 256) w2s[i] = w2f[i];
    if (t < 64) b1s[t] = b1f[t];
    else if (t < 128) b2s[t-64] = b2f[t-64];

    int v = blockIdx.x*4 + grp;
    bool valid = v < N;
    int np = valid ? numpts[v] : 1;

    float4 p = make_float4(0.f,0.f,0.f,0.f);
    if (lt < 32) {
        if (valid) p = ((const float4*)voxels)[(size_t)v * TPTS + lt];
        float sx = p.x, sy = p.y, sz = p.z;
        #pragma unroll
        for (int o = 16; o > 0; o >>= 1) {
            sx += __shfl_down_sync(0xffffffffu, sx, o);
            sy += __shfl_down_sync(0xffffffffu, sy, o);
            sz += __shfl_down_sync(0xffffffffu, sz, o);
        }
        if (lt == 0) {
            float inv = 1.0f / (float)np;
            mean3[0] = sx*inv; mean3[1] = sy*inv; mean3[2] = sz*inv;
        }
    }
    __syncthreads();
    if (lt < 32) {
        float mx = mean3[0], my = mean3[1], mz = mean3[2];
        float* f = &feat[lt*9];
        f[0]=p.x; f[1]=p.y; f[2]=p.z; f[3]=p.w;
        f[4]=p.x-mx; f[5]=p.y-my; f[6]=p.z-mz; f[7]=p.x-mx; f[8]=p.y-my;
    }
    __syncthreads();
    int c = lt;
    float b1v = b1s[c], gm = -1e30f;
    for (int tt = 0; tt < TPTS; tt++) {
        float a = b1v;
        #pragma unroll
        for (int k = 0; k < 9; k++) a = fmaf(feat[tt*9+k], w1s[k*64+c], a);
        a = fmaxf(a, 0.f);
        h1s[tt*64+c] = a;
        gm = fmaxf(gm, a);
    }
    gmaxs[c] = gm;
    __syncthreads();
    float gterm = b2s[c];
    #pragma unroll 8
    for (int j = 0; j < 64; j++) gterm = fmaf(gmaxs[j], w2s[(64+j)*64+c], gterm);
    float vmax = 0.f;
    int tt = 0;
    for (; tt + 4 <= np; tt += 4) {
        float a0=gterm,a1=gterm,a2=gterm,a3=gterm;
        const float* h0 = &h1s[tt*64];
        #pragma unroll 8
        for (int j = 0; j < 64; j++) {
            float w = w2s[j*64+c];
            a0 = fmaf(h0[j],w,a0); a1 = fmaf(h0[64+j],w,a1);
            a2 = fmaf(h0[128+j],w,a2); a3 = fmaf(h0[192+j],w,a3);
        }
        vmax = fmaxf(vmax, fmaxf(fmaxf(a0,a1), fmaxf(a2,a3)));
    }
    for (; tt < np; tt++) {
        float a = gterm;
        #pragma unroll 8
        for (int j = 0; j < 64; j++) a = fmaf(h1s[tt*64+j], w2s[j*64+c], a);
        vmax = fmaxf(vmax, a);
    }
    if (valid) vfout[(size_t)v*64 + c] = vmax;
}

__global__ void fill_win_kernel(int* __restrict__ p, int n) {
    int i = blockIdx.x * blockDim.x + threadIdx.x;
    if (i < n) p[i] = -1;
}
// fused: zero sf2 (as uint4) + fill win2 with -1
__global__ void init_sf2_win2(uint4* __restrict__ sf2, size_t n4, int* __restrict__ win, int nw) {
    uint4 z = make_uint4(0,0,0,0);
    for (size_t i = (size_t)blockIdx.x*blockDim.x + threadIdx.x; i < n4;
         i += (size_t)gridDim.x*blockDim.x) {
        sf2[i] = z;
        if (i < (size_t)nw) win[i] = -1;
    }
}
__global__ void scatter_max_kernel(const int* __restrict__ coords, int* __restrict__ win,
                                   int N, int H, int W) {
    int v = blockIdx.x * blockDim.x + threadIdx.x;
    if (v >= N) return;
    int b = coords[v*4];
    int y = min(max(coords[v*4+2], 0), H-1);
    int x = min(max(coords[v*4+3], 0), W-1);
    atomicMax(&win[(b*H + y)*W + x], v);
}
__global__ void scatter_write_f16(const int* __restrict__ coords, const int* __restrict__ win,
                                  const float* __restrict__ vf, __half* __restrict__ cat,
                                  size_t PE, int H, int W, int Wp) {
    int v = blockIdx.x, c = threadIdx.x;
    int b = coords[v*4];
    int y = min(max(coords[v*4+2], 0), H-1);
    int x = min(max(coords[v*4+3], 0), W-1);
    if (win[(b*H + y)*W + x] != v) return;
    float val = vf[(size_t)v*64 + c];
    cat[(size_t)(b*2)*PE + (size_t)MR_F*64 + (size_t)((y+1)*Wp + (x+1))*64 + c] = __float2half_rn(val);
}
__global__ void scatter_write_f32(const int* __restrict__ coords, const int* __restrict__ win,
                                  const float* __restrict__ vf, float* __restrict__ dst,
                                  int H, int W) {
    int v = blockIdx.x, c = threadIdx.x;
    int b = coords[v*4];
    int y = min(max(coords[v*4+2], 0), H-1);
    int x = min(max(coords[v*4+3], 0), W-1);
    if (win[(b*H + y)*W + x] != v) return;
    dst[((size_t)(b*64 + c)*H + y)*W + x] = vf[(size_t)v*64 + c];
}
__global__ void zero_u4(uint4* __restrict__ p, size_t n) {
    uint4 z = make_uint4(0,0,0,0);
    for (size_t i = (size_t)blockIdx.x*blockDim.x + threadIdx.x; i < n;
         i += (size_t)gridDim.x*blockDim.x) p[i] = z;
}

__global__ void ups_kernel(const float* __restrict__ src, __half* __restrict__ cat,
                           size_t PE, int Hi, int Wi, int Ho, int Wo, int Wp) {
    __shared__ float s[2*64*67];
    int b = blockIdx.z, y = blockIdx.y;
    int X0 = blockIdx.x * 128;
    int t = threadIdx.x;
    float fy = fminf(fmaxf(y*0.5f - 0.25f, 0.f), (float)(Hi-1));
    int y0 = (int)fy; float wy = fy - y0;
    int y1 = min(y0+1, Hi-1);
    int xb = (int)fmaxf(X0*0.5f - 0.25f, 0.f);
    const float* sb = src + (size_t)b*64*Hi*Wi;
    for (int i = t; i < 2*64*66; i += 256) {
        int xi = i % 66, c = (i/66) % 64, r = i/(66*64);
        int gx = min(xb + xi, Wi-1);
        int gy = r ? y1 : y0;
        s[(r*64 + c)*67 + xi] = sb[((size_t)c*Hi + gy)*Wi + gx];
    }
    __syncthreads();
    int co = t & 63, xg = t >> 6;
    __half* plane = cat + (size_t)(2*b+1)*PE + (size_t)MR_F*64;
    for (int k = 0; k < 32; k++) {
        int xo = X0 + xg*32 + k;
        if (xo >= Wo) break;
        float fx = fminf(fmaxf(xo*0.5f - 0.25f, 0.f), (float)(Wi-1));
        int x0 = (int)fx; float wx = fx - x0;
        int xi = x0 - xb;
        float v0 = (1.f-wx)*s[co*67+xi]      + wx*s[co*67+xi+1];
        float v1 = (1.f-wx)*s[(64+co)*67+xi] + wx*s[(64+co)*67+xi+1];
        float val = (1.f-wy)*v0 + wy*v1;
        plane[((size_t)(y+1)*Wp + (xo+1))*64 + co] = __float2half_rn(val);
    }
}

// 2D-halo HMMA conv: CTA = 16x32 tile (512 outputs); 16 warps x 2 m-tiles;
// double-buffered A halo per chunk (no mid-kernel stall); single-sync B pipeline.
__global__ __launch_bounds__(512, 1)
void conv_mma_kernel(const __half* __restrict__ cat, size_t PE,
                     int Wp, int H, int W,
                     const uint4* __restrict__ wimg, const float* __restrict__ bias,
                     float* __restrict__ out) {
    extern __shared__ __align__(16) char sm[];
    uint32_t smb = smem_u32(sm);
    int t = threadIdx.x, lane = t & 31, w = t >> 5;
    int b = blockIdx.z;
    int tx0 = blockIdx.x * 16;
    int ty0 = blockIdx.y * TILE_H;
    const __half* pl[2];
    #pragma unroll
    for (int c = 0; c < 2; c++)
        pl[c] = cat + (size_t)(2*b + c)*PE + (size_t)MR_F*64;

    float acc[2][8][4];
    #pragma unroll
    for (int mt = 0; mt < 2; mt++)
        #pragma unroll
        for (int nt = 0; nt < 8; nt++)
            #pragma unroll
            for (int k = 0; k < 4; k++) acc[mt][nt][k] = 0.f;

    int arow_l = (lane & 7) + ((lane >> 3) & 1) * 8;
    int au = (lane >> 4);
    int brow_l = (lane & 7) + ((lane >> 4) & 1) * 8;
    int bu = (lane >> 3) & 1;

    #define BT(S) ((size_t)((((S) % 9) * 2) + ((S) / 9)) * 512)

    // prologue: G0 = A(c0)+B(0); G1 = A(c1)+B(1)
    #pragma unroll
    for (int c = 0; c < 2; c++) {
        const __half* base = pl[c];
        for (int i = t; i < 4896; i += 512) {     // 612 rows x 8 cb
            int r = i >> 3, cb = i & 7;
            int hy = r / 18, hx = r % 18;
            long long q = (long long)(ty0 + hy)*Wp + (tx0 + hx);
            uint32_t so = (uint32_t)(c*A_BYTES + r*128 + ((cb ^ (r & 7)) << 4));
            cp16(smb + so, (const uint4*)(base + q*64) + cb);
        }
        cp16(smb + OFF_B + (uint32_t)c*8192 + t*16, wimg + BT(c) + t);
        CP_COMMIT();
    }

    for (int s = 0; s < 18; s++) {
        CP_WAIT1();
        __syncthreads();
        if (s + 2 < 18) {
            cp16(smb + OFF_B + (uint32_t)((s+2) % 3)*8192 + t*16, wimg + BT(s+2) + t);
            CP_COMMIT();
        } else {
            CP_COMMIT();
        }
        int chunk = s / 9, tap = s % 9;
        int dy = tap / 3, dx = tap % 3;
        uint32_t aBase = smb + (uint32_t)chunk*A_BYTES;
        uint32_t bBase = smb + OFF_B + (uint32_t)(s % 3)*8192;
        #pragma unroll
        for (int ks = 0; ks < 4; ks++) {
            uint32_t aH[2][4];
            #pragma unroll
            for (int mt = 0; mt < 2; mt++) {
                int h = (w*2 + mt + dy)*18 + dx + arow_l;
                int u = ks*2 + au;
                ldm_x4(aH[mt], aBase + (uint32_t)(h*128 + ((u ^ (h & 7)) << 4)));
            }
            uint32_t bHf[8][2];
            #pragma unroll
            for (int npair = 0; npair < 4; npair++) {
                int r = npair*16 + brow_l;
                int u = ks*2 + bu;
                uint32_t tmp[4];
                ldm_x4(tmp, bBase + (uint32_t)(r*128 + ((u ^ (r & 7)) << 4)));
                bHf[npair*2][0]=tmp[0]; bHf[npair*2][1]=tmp[1];
                bHf[npair*2+1][0]=tmp[2]; bHf[npair*2+1][1]=tmp[3];
            }
            #pragma unroll
            for (int mt = 0; mt < 2; mt++)
                #pragma unroll
                for (int nt = 0; nt < 8; nt++)
                    mma_f16(acc[mt][nt], aH[mt], bHf[nt]);
        }
    }
    #undef BT
    CP_WAIT0();

    // epilogue: two 256-output passes; conflict-free transpose stride 260
    int g = lane >> 2, tg = lane & 3;
    float* smf = (float*)sm;
    #pragma unroll
    for (int p = 0; p < 2; p++) {
        __syncthreads();
        if ((w >> 3) == p) {
            int wl = w & 7;
            #pragma unroll
            for (int mt = 0; mt < 2; mt++) {
                int rb = (wl*2 + mt)*16 + g;
                #pragma unroll
                for (int nt = 0; nt < 8; nt++) {
                    int cb = nt*8 + tg*2;
                    smf[(cb+0)*260 + rb]     = acc[mt][nt][0];
                    smf[(cb+1)*260 + rb]     = acc[mt][nt][1];
                    smf[(cb+0)*260 + rb + 8] = acc[mt][nt][2];
                    smf[(cb+1)*260 + rb + 8] = acc[mt][nt][3];
                }
            }
        }
        __syncthreads();
        for (int i = t; i < 16384; i += 512) {
            int oc = i >> 8, r = i & 255;
            int y = ty0 + p*16 + (r >> 4), x = tx0 + (r & 15);
            if (y < H && x < W)
                out[((size_t)(b*64 + oc)*H + y)*W + x] =
                    fmaxf(smf[oc*260 + r] + bias[oc], 0.f);
        }
    }
}

extern "C" void kernel_launch(void* const* d_in, const int* in_sizes, int n_in,
                              void* d_out, int out_size) {
    (void)out_size;
    const float* voxels[3] = {0,0,0};
    const int* numpts[3] = {0,0,0};
    const int* coordsp[3] = {0,0,0};
    const float *w1=0,*w2=0,*fw=0;
    const float* p192[8] = {0};
    const float* p128[4] = {0};
    int n192 = 0, n128 = 0;
    for (int i = 0; i < n_in; i++) {
        int sz = in_sizes[i];
        const void* p = d_in[i];
        switch (sz) {
            case 5120000: voxels[0] = (const float*)p; break;
            case 2560000: voxels[1] = (const float*)p; break;
            case 1024000: voxels[2] = (const float*)p; break;
            case 40000:   numpts[0] = (const int*)p; break;
            case 20000:   numpts[1] = (const int*)p; break;
            case 8000:    numpts[2] = (const int*)p; break;
            case 160000:  coordsp[0] = (const int*)p; break;
            case 80000:   coordsp[1] = (const int*)p; break;
            case 32000:   coordsp[2] = (const int*)p; break;
            case 1728:    w1 = (const float*)p; break;
            case 24576:   w2 = (const float*)p; break;
            case 147456:  fw = (const float*)p; break;
            case 192:     if (n192 < 8) p192[n192++] = (const float*)p; break;
            case 128:     if (n128 < 4) p128[n128++] = (const float*)p; break;
            default: break;
        }
    }
    const float *g1=p192[0], *b1=p192[1], *rm1=p192[2], *rv1=p192[3];
    const float *g2=p192[4], *b2=p192[5], *rm2=p192[6], *rv2=p192[7];
    const float *fg=p128[0], *fb=p128[1], *fm=p128[2], *fv=p128[3];

    __half *cat0, *cat1;
    cudaGetSymbolAddress((void**)&cat0, g_cat0t);
    cudaGetSymbolAddress((void**)&cat1, g_cat1t);
    float *sf2, *f1, *vf0, *vf1, *vf2, *w1f, *b1f, *w2f, *b2f, *fbf;
    int *win0, *win1, *win2;
    unsigned char* wimg;
    cudaGetSymbolAddress((void**)&sf2, g_sf2);
    cudaGetSymbolAddress((void**)&f1,  g_f1);
    cudaGetSymbolAddress((void**)&vf0, g_vf0);
    cudaGetSymbolAddress((void**)&vf1, g_vf1);
    cudaGetSymbolAddress((void**)&vf2, g_vf2);
    cudaGetSymbolAddress((void**)&win0, g_win0);
    cudaGetSymbolAddress((void**)&win1, g_win1);
    cudaGetSymbolAddress((void**)&win2, g_win2);
    cudaGetSymbolAddress((void**)&w1f, g_w1f);
    cudaGetSymbolAddress((void**)&b1f, g_b1f);
    cudaGetSymbolAddress((void**)&w2f, g_w2f);
    cudaGetSymbolAddress((void**)&b2f, g_b2f);
    cudaGetSymbolAddress((void**)&fbf, g_fbf);
    cudaGetSymbolAddress((void**)&wimg, g_wimg);

    static cudaStream_t s1 = 0, s2 = 0;
    static cudaEvent_t eInit = 0, e0 = 0, e1 = 0, eZ0 = 0, eZ1 = 0;
    static int inited = 0;
    if (!inited) {
        cudaStreamCreateWithFlags(&s1, cudaStreamNonBlocking);
        cudaStreamCreateWithFlags(&s2, cudaStreamNonBlocking);
        cudaEventCreateWithFlags(&eInit, cudaEventDisableTiming);
        cudaEventCreateWithFlags(&e0, cudaEventDisableTiming);
        cudaEventCreateWithFlags(&e1, cudaEventDisableTiming);
        cudaEventCreateWithFlags(&eZ0, cudaEventDisableTiming);
        cudaEventCreateWithFlags(&eZ1, cudaEventDisableTiming);
        cudaFuncSetAttribute(conv_mma_kernel, cudaFuncAttributeMaxDynamicSharedMemorySize, CONV_SMEM);
        cudaFuncSetAttribute(vfe_kernel, cudaFuncAttributeMaxDynamicSharedMemorySize, VFE_SMEM);
        inited = 1;
    }

    fold_kernel<<<1152, 256>>>(w1, g1, b1, rm1, rv1, w2, g2, b2, rm2, rv2, fw, fg, fb, fm, fv);
    cudaEventRecord(eInit, 0);

    cudaStreamWaitEvent(s1, eInit, 0);
    zero_u4<<<1024, 256, 0, s1>>>((uint4*)cat1, PE1);
    cudaEventRecord(eZ1, s1);
    vfe_kernel<<<(NS_[1]+3)/4, 256, VFE_SMEM, s1>>>(voxels[1], numpts[1], w1f + 576, b1f + 64, w2f + 8192, b2f + 64, vf1, NS_[1]);
    fill_win_kernel<<<(BATCH*HW1 + 255)/256, 256, 0, s1>>>(win1, BATCH*HW1);
    scatter_max_kernel<<<(NS_[1] + 255)/256, 256, 0, s1>>>(coordsp[1], win1, NS_[1], H1, W1);
    scatter_write_f16<<<NS_[1], 64, 0, s1>>>(coordsp[1], win1, vf1, cat1, PE1, H1, W1, WP1);
    cudaEventRecord(e1, s1);

    cudaStreamWaitEvent(s2, eInit, 0);
    zero_u4<<<2048, 256, 0, s2>>>((uint4*)cat0, PE0);
    cudaEventRecord(eZ0, s2);
    vfe_kernel<<<(NS_[0]+3)/4, 256, VFE_SMEM, s2>>>(voxels[0], numpts[0], w1f, b1f, w2f, b2f, vf0, NS_[0]);
    fill_win_kernel<<<(BATCH*HW0 + 255)/256, 256, 0, s2>>>(win0, BATCH*HW0);
    scatter_max_kernel<<<(NS_[0] + 255)/256, 256, 0, s2>>>(coordsp[0], win0, NS_[0], H0, W0);
    scatter_write_f16<<<NS_[0], 64, 0, s2>>>(coordsp[0], win0, vf0, cat0, PE0, H0, W0, WP0);
    cudaEventRecord(e0, s2);

    // main: scale 2 critical path (sf2 zero + win2 fill fused)
    init_sf2_win2<<<512, 256>>>((uint4*)sf2, (size_t)BATCH*64*HW2/4, win2, BATCH*HW2);
    vfe_kernel<<<(NS_[2]+3)/4, 256, VFE_SMEM>>>(voxels[2], numpts[2], w1f + 1152, b1f + 128, w2f + 16384, b2f + 128, vf2, NS_[2]);
    scatter_max_kernel<<<(NS_[2] + 255)/256, 256>>>(coordsp[2], win2, NS_[2], H2, W2);
    scatter_write_f32<<<NS_[2], 64>>>(coordsp[2], win2, vf2, sf2, H2, W2);

    cudaStreamWaitEvent(0, eZ1, 0);
    {
        dim3 g((W1 + 127)/128, H1, BATCH);
        ups_kernel<<<g, 256>>>(sf2, cat1, PE1, H2, W2, H1, W1, WP1);
    }
    cudaStreamWaitEvent(0, e1, 0);
    {
        dim3 g((W1 + 15)/16, (H1 + TILE_H - 1)/TILE_H, BATCH);
        conv_mma_kernel<<<g, 512, CONV_SMEM>>>(cat1, PE1, WP1, H1, W1,
            (const uint4*)(wimg + 147456), fbf + 64, f1);
    }
    cudaStreamWaitEvent(0, eZ0, 0);
    {
        dim3 g((W0 + 127)/128, H0, BATCH);
        ups_kernel<<<g, 256>>>(f1, cat0, PE0, H1, W1, H0, W0, WP0);
    }
    cudaStreamWaitEvent(0, e0, 0);
    {
        dim3 g((W0 + 15)/16, (H0 + TILE_H - 1)/TILE_H, BATCH);
        conv_mma_kernel<<<g, 512, CONV_SMEM>>>(cat0, PE0, WP0, H0, W0,
            (const uint4*)wimg, fbf, (float*)d_out);
    }
}

// round 17
// speedup vs baseline: 4.8567x; 1.1112x over previous
#include <cuda_runtime.h>
#include <cuda_bf16.h>
#include <cuda_fp16.h>
#include <math.h>
#include <stdint.h>

#define EPSBN 1e-3f
static const int NS_[3] = {40000, 20000, 8000};
#define BATCH 4
#define TPTS 32
#define H0 496
#define W0 432
#define H1 248
#define W1 216
#define H2 124
#define W2 108
#define HW0 (H0*W0)
#define HW1 (H1*W1)
#define HW2 (H2*W2)
#define WP0 (W0+2)
#define Q0 ((H0+2)*WP0)
#define WP1 (W1+2)
#define Q1 ((H1+2)*WP1)
#define MR_F 512
#define MR_B 8192
#define P0 (MR_F + Q0 + MR_B)
#define P1 (MR_F + Q1 + MR_B)
#define PE0 ((size_t)P0*64)
#define PE1 ((size_t)P1*64)

__device__ float g_w1f[3*9*64];
__device__ float g_b1f[3*64];
__device__ float g_w2f[3*128*64];
__device__ float g_b2f[3*64];
__device__ float g_fbf[2*64];
__device__ unsigned char g_wimg[2*9*2*8192];
__device__ float g_vf0[40000*64];
__device__ float g_vf1[20000*64];
__device__ float g_vf2[8000*64];
__device__ int   g_win0[BATCH*HW0];
__device__ int   g_win1[BATCH*HW1];
__device__ int   g_win2[BATCH*HW2];
__device__ __half g_cat0t[4*PE0];              // chunk0 only
__device__ __half g_cat1t[4*PE1];
__device__ __half g_sf2t[(size_t)BATCH*HW2*64];   // transposed fp16 [b][q][ch]
__device__ __half g_f1t [(size_t)BATCH*HW1*64];

__device__ __forceinline__ uint32_t smem_u32(const void* p) {
    uint32_t a;
    asm("{ .reg .u64 t; cvta.to.shared.u64 t, %1; cvt.u32.u64 %0, t; }" : "=r"(a) : "l"(p));
    return a;
}
__device__ __forceinline__ void mma_f16(float* c, const uint32_t* a, const uint32_t* b) {
    asm volatile("mma.sync.aligned.m16n8k16.row.col.f32.f16.f16.f32 "
                 "{%0,%1,%2,%3}, {%4,%5,%6,%7}, {%8,%9}, {%0,%1,%2,%3};"
                 : "+f"(c[0]), "+f"(c[1]), "+f"(c[2]), "+f"(c[3])
                 : "r"(a[0]), "r"(a[1]), "r"(a[2]), "r"(a[3]), "r"(b[0]), "r"(b[1]));
}
__device__ __forceinline__ void ldm_x4(uint32_t* r, uint32_t addr) {
    asm volatile("ldmatrix.sync.aligned.m8n8.x4.shared.b16 {%0,%1,%2,%3}, [%4];"
                 : "=r"(r[0]), "=r"(r[1]), "=r"(r[2]), "=r"(r[3]) : "r"(addr));
}
__device__ __forceinline__ void cp16(uint32_t d, const void* s) {
    asm volatile("cp.async.cg.shared.global [%0], [%1], 16;" :: "r"(d), "l"(s));
}
#define CP_COMMIT() asm volatile("cp.async.commit_group;" ::: "memory")
#define CP_WAIT1()  asm volatile("cp.async.wait_group 1;" ::: "memory")
#define CP_WAIT0()  asm volatile("cp.async.wait_group 0;" ::: "memory")
#define SWZ(o) ((o) ^ (((o) >> 3) & 0x70))

#define TILE_H 32
#define A_BYTES (612*128)
#define OFF_B (2*A_BYTES)
#define CONV_SMEM (OFF_B + 3*8192)
#define VFE_SMEM (18512*4)

__global__ void fold_kernel(const float* __restrict__ w1, const float* __restrict__ g1,
                            const float* __restrict__ b1, const float* __restrict__ rm1,
                            const float* __restrict__ rv1,
                            const float* __restrict__ w2, const float* __restrict__ g2,
                            const float* __restrict__ b2, const float* __restrict__ rm2,
                            const float* __restrict__ rv2,
                            const float* __restrict__ fw, const float* __restrict__ fg,
                            const float* __restrict__ fb, const float* __restrict__ fm,
                            const float* __restrict__ fv) {
    int idx = blockIdx.x * blockDim.x + threadIdx.x;
    if (idx < 1728) {
        int s = idx / 576; int d = idx % 64;
        g_w1f[idx] = w1[idx] * g1[s*64+d] * rsqrtf(rv1[s*64+d] + EPSBN);
    }
    if (idx < 24576) {
        int s = idx / 8192; int d = idx % 64;
        g_w2f[idx] = w2[idx] * g2[s*64+d] * rsqrtf(rv2[s*64+d] + EPSBN);
    }
    if (idx < 147456) {
        int l = idx / 73728; int r = idx % 73728;
        int oc = r / 1152; int rem = r % 1152;
        int ic = rem / 9; int tap = rem % 9;
        float sc = fg[l*64+oc] * rsqrtf(fv[l*64+oc] + EPSBN);
        float w = fw[(((size_t)(l*64+oc)*128 + ic)*9) + tap] * sc;
        int chunk = ic >> 6, chl = ic & 63;
        size_t tb = (size_t)l*147456 + (size_t)(tap*2+chunk)*8192;
        uint32_t so = SWZ((uint32_t)(oc*128 + chl*2));
        *(__half*)(g_wimg + tb + so) = __float2half_rn(w);
    }
    if (idx < 192) {
        g_b1f[idx] = b1[idx] - rm1[idx] * g1[idx] * rsqrtf(rv1[idx] + EPSBN);
        g_b2f[idx] = b2[idx] - rm2[idx] * g2[idx] * rsqrtf(rv2[idx] + EPSBN);
    }
    if (idx < 128) {
        g_fbf[idx] = fb[idx] - fm[idx] * fg[idx] * rsqrtf(fv[idx] + EPSBN);
    }
}

__global__ void vfe_kernel(const float* __restrict__ voxels, const int* __restrict__ numpts,
                           const float* __restrict__ w1f, const float* __restrict__ b1f,
                           const float* __restrict__ w2f, const float* __restrict__ b2f,
                           float* __restrict__ vfout, int N) {
    extern __shared__ float smf[];
    float* w1s = smf;
    float* w2s = smf + 576;
    float* b1s = smf + 8768;
    float* b2s = smf + 8832;
    int t = threadIdx.x;
    int grp = t >> 6, lt = t & 63;
    float* gb   = smf + 8896 + grp*2404;
    float* feat = gb;
    float* h1s  = gb + 288;
    float* gmaxs= gb + 2336;
    float* mean3= gb + 2400;

    for (int i = t; i < 576; i += 256)  w1s[i] = w1f[i];
    for (int i = t; i < 8192; i += 256) w2s[i] = w2f[i];
    if (t < 64) b1s[t] = b1f[t];
    else if (t < 128) b2s[t-64] = b2f[t-64];

    int v = blockIdx.x*4 + grp;
    bool valid = v < N;
    int np = valid ? numpts[v] : 1;

    float4 p = make_float4(0.f,0.f,0.f,0.f);
    if (lt < 32) {
        if (valid) p = ((const float4*)voxels)[(size_t)v * TPTS + lt];
        float sx = p.x, sy = p.y, sz = p.z;
        #pragma unroll
        for (int o = 16; o > 0; o >>= 1) {
            sx += __shfl_down_sync(0xffffffffu, sx, o);
            sy += __shfl_down_sync(0xffffffffu, sy, o);
            sz += __shfl_down_sync(0xffffffffu, sz, o);
        }
        if (lt == 0) {
            float inv = 1.0f / (float)np;
            mean3[0] = sx*inv; mean3[1] = sy*inv; mean3[2] = sz*inv;
        }
    }
    __syncthreads();
    if (lt < 32) {
        float mx = mean3[0], my = mean3[1], mz = mean3[2];
        float* f = &feat[lt*9];
        f[0]=p.x; f[1]=p.y; f[2]=p.z; f[3]=p.w;
        f[4]=p.x-mx; f[5]=p.y-my; f[6]=p.z-mz; f[7]=p.x-mx; f[8]=p.y-my;
    }
    __syncthreads();
    int c = lt;
    float b1v = b1s[c], gm = -1e30f;
    for (int tt = 0; tt < TPTS; tt++) {
        float a = b1v;
        #pragma unroll
        for (int k = 0; k < 9; k++) a = fmaf(feat[tt*9+k], w1s[k*64+c], a);
        a = fmaxf(a, 0.f);
        h1s[tt*64+c] = a;
        gm = fmaxf(gm, a);
    }
    gmaxs[c] = gm;
    __syncthreads();
    float gterm = b2s[c];
    #pragma unroll 8
    for (int j = 0; j < 64; j++) gterm = fmaf(gmaxs[j], w2s[(64+j)*64+c], gterm);
    float vmax = 0.f;
    int tt = 0;
    for (; tt + 4 <= np; tt += 4) {
        float a0=gterm,a1=gterm,a2=gterm,a3=gterm;
        const float* h0 = &h1s[tt*64];
        #pragma unroll 8
        for (int j = 0; j < 64; j++) {
            float w = w2s[j*64+c];
            a0 = fmaf(h0[j],w,a0); a1 = fmaf(h0[64+j],w,a1);
            a2 = fmaf(h0[128+j],w,a2); a3 = fmaf(h0[192+j],w,a3);
        }
        vmax = fmaxf(vmax, fmaxf(fmaxf(a0,a1), fmaxf(a2,a3)));
    }
    for (; tt < np; tt++) {
        float a = gterm;
        #pragma unroll 8
        for (int j = 0; j < 64; j++) a = fmaf(h1s[tt*64+j], w2s[j*64+c], a);
        vmax = fmaxf(vmax, a);
    }
    if (valid) vfout[(size_t)v*64 + c] = vmax;
}

__global__ void fill_win_kernel(int* __restrict__ p, int n) {
    int i = blockIdx.x * blockDim.x + threadIdx.x;
    if (i < n) p[i] = -1;
}
// fused: zero sf2t + fill win2
__global__ void init_sf2t_win2(uint4* __restrict__ sf2t, size_t n4, int* __restrict__ win, int nw) {
    uint4 z = make_uint4(0,0,0,0);
    for (size_t i = (size_t)blockIdx.x*blockDim.x + threadIdx.x; i < n4;
         i += (size_t)gridDim.x*blockDim.x) {
        sf2t[i] = z;
        if (i < (size_t)nw) win[i] = -1;
    }
}
__global__ void scatter_max_kernel(const int* __restrict__ coords, int* __restrict__ win,
                                   int N, int H, int W) {
    int v = blockIdx.x * blockDim.x + threadIdx.x;
    if (v >= N) return;
    int b = coords[v*4];
    int y = min(max(coords[v*4+2], 0), H-1);
    int x = min(max(coords[v*4+3], 0), W-1);
    atomicMax(&win[(b*H + y)*W + x], v);
}
__global__ void scatter_write_f16(const int* __restrict__ coords, const int* __restrict__ win,
                                  const float* __restrict__ vf, __half* __restrict__ cat,
                                  size_t PE, int H, int W, int Wp) {
    int v = blockIdx.x, c = threadIdx.x;
    int b = coords[v*4];
    int y = min(max(coords[v*4+2], 0), H-1);
    int x = min(max(coords[v*4+3], 0), W-1);
    if (win[(b*H + y)*W + x] != v) return;
    float val = vf[(size_t)v*64 + c];
    cat[(size_t)b*PE + (size_t)MR_F*64 + (size_t)((y+1)*Wp + (x+1))*64 + c] = __float2half_rn(val);
}
// scale-2 scatter into transposed fp16 sf2t [b][q][ch]
__global__ void scatter_write_sf2t(const int* __restrict__ coords, const int* __restrict__ win,
                                   const float* __restrict__ vf, __half* __restrict__ dst) {
    int v = blockIdx.x, c = threadIdx.x;
    int b = coords[v*4];
    int y = min(max(coords[v*4+2], 0), H2-1);
    int x = min(max(coords[v*4+3], 0), W2-1);
    if (win[(b*H2 + y)*W2 + x] != v) return;
    dst[((size_t)(b*H2 + y)*W2 + x)*64 + c] = __float2half_rn(vf[(size_t)v*64 + c]);
}
__global__ void zero_u4(uint4* __restrict__ p, size_t n) {
    uint4 z = make_uint4(0,0,0,0);
    for (size_t i = (size_t)blockIdx.x*blockDim.x + threadIdx.x; i < n;
         i += (size_t)gridDim.x*blockDim.x) p[i] = z;
}

// 2D-halo HMMA conv with FUSED bilinear upsample for chunk1.
// cat: chunk0 padded plane; srcT: lower-res transposed fp16 source (Hi x Wi) for chunk1.
// outF (f32 NCHW) or outT (transposed fp16 [q][ch]) — exactly one non-null.
__global__ __launch_bounds__(512, 1)
void conv_mma_kernel(const __half* __restrict__ cat, size_t PE,
                     const __half* __restrict__ srcT, int Hi, int Wi,
                     int Wp, int H, int W,
                     const uint4* __restrict__ wimg, const float* __restrict__ bias,
                     float* __restrict__ outF, __half* __restrict__ outT) {
    extern __shared__ __align__(16) char sm[];
    uint32_t smb = smem_u32(sm);
    int t = threadIdx.x, lane = t & 31, w = t >> 5;
    int b = blockIdx.z;
    int tx0 = blockIdx.x * 16;
    int ty0 = blockIdx.y * TILE_H;

    float acc[2][8][4];
    #pragma unroll
    for (int mt = 0; mt < 2; mt++)
        #pragma unroll
        for (int nt = 0; nt < 8; nt++)
            #pragma unroll
            for (int k = 0; k < 4; k++) acc[mt][nt][k] = 0.f;

    int arow_l = (lane & 7) + ((lane >> 3) & 1) * 8;
    int au = (lane >> 4);
    int brow_l = (lane & 7) + ((lane >> 4) & 1) * 8;
    int bu = (lane >> 3) & 1;

    #define BT(S) ((size_t)((((S) % 9) * 2) + ((S) / 9)) * 512)

    // G0: chunk0 A (cp.async) + B(0)
    {
        const __half* base = cat + (size_t)b*PE + (size_t)MR_F*64;
        for (int i = t; i < 4896; i += 512) {
            int r = i >> 3, cb = i & 7;
            int hy = r / 18, hx = r % 18;
            long long q = (long long)(ty0 + hy)*Wp + (tx0 + hx);
            uint32_t so = (uint32_t)(r*128 + ((cb ^ (r & 7)) << 4));
            cp16(smb + so, (const uint4*)(base + q*64) + cb);
        }
        cp16(smb + OFF_B + t*16, wimg + BT(0) + t);
        CP_COMMIT();
    }
    // G1: B(1)
    cp16(smb + OFF_B + 8192 + t*16, wimg + BT(1) + t);
    CP_COMMIT();

    // chunk1 A: fused bilinear from srcT (plain LDG/STS; visible after first barrier)
    {
        const __half* sT = srcT + (size_t)b*Hi*Wi*64;
        for (int i = t; i < 4896; i += 512) {
            int r = i >> 3, cb = i & 7;
            int hy = r / 18, hx = r % 18;
            int oy = ty0 + hy - 1, ox = tx0 + hx - 1;
            union { uint4 u; __half2 h[4]; } v00, v01, v10, v11, res;
            res.u = make_uint4(0,0,0,0);
            if (oy >= 0 && oy < H && ox >= 0 && ox < W) {
                float fy = fminf(fmaxf(oy*0.5f - 0.25f, 0.f), (float)(Hi-1));
                float fx = fminf(fmaxf(ox*0.5f - 0.25f, 0.f), (float)(Wi-1));
                int y0 = (int)fy; float wy = fy - y0;
                int x0 = (int)fx; float wx = fx - x0;
                int y1 = min(y0+1, Hi-1), x1 = min(x0+1, Wi-1);
                v00.u = *((const uint4*)(sT + ((size_t)y0*Wi + x0)*64) + cb);
                v01.u = *((const uint4*)(sT + ((size_t)y0*Wi + x1)*64) + cb);
                v10.u = *((const uint4*)(sT + ((size_t)y1*Wi + x0)*64) + cb);
                v11.u = *((const uint4*)(sT + ((size_t)y1*Wi + x1)*64) + cb);
                __half2 W00 = __float2half2_rn((1.f-wy)*(1.f-wx));
                __half2 W01 = __float2half2_rn((1.f-wy)*wx);
                __half2 W10 = __float2half2_rn(wy*(1.f-wx));
                __half2 W11 = __float2half2_rn(wy*wx);
                #pragma unroll
                for (int j = 0; j < 4; j++)
                    res.h[j] = __hfma2(W00, v00.h[j],
                               __hfma2(W01, v01.h[j],
                               __hfma2(W10, v10.h[j], __hmul2(W11, v11.h[j]))));
            }
            *(uint4*)(sm + A_BYTES + r*128 + ((cb ^ (r & 7)) << 4)) = res.u;
        }
    }

    for (int s = 0; s < 18; s++) {
        CP_WAIT1();
        __syncthreads();
        if (s + 2 < 18) {
            cp16(smb + OFF_B + (uint32_t)((s+2) % 3)*8192 + t*16, wimg + BT(s+2) + t);
            CP_COMMIT();
        } else {
            CP_COMMIT();
        }
        int chunk = s / 9, tap = s % 9;
        int dy = tap / 3, dx = tap % 3;
        uint32_t aBase = smb + (uint32_t)chunk*A_BYTES;
        uint32_t bBase = smb + OFF_B + (uint32_t)(s % 3)*8192;
        #pragma unroll
        for (int ks = 0; ks < 4; ks++) {
            uint32_t aH[2][4];
            #pragma unroll
            for (int mt = 0; mt < 2; mt++) {
                int h = (w*2 + mt + dy)*18 + dx + arow_l;
                int u = ks*2 + au;
                ldm_x4(aH[mt], aBase + (uint32_t)(h*128 + ((u ^ (h & 7)) << 4)));
            }
            uint32_t bHf[8][2];
            #pragma unroll
            for (int npair = 0; npair < 4; npair++) {
                int r = npair*16 + brow_l;
                int u = ks*2 + bu;
                uint32_t tmp[4];
                ldm_x4(tmp, bBase + (uint32_t)(r*128 + ((u ^ (r & 7)) << 4)));
                bHf[npair*2][0]=tmp[0]; bHf[npair*2][1]=tmp[1];
                bHf[npair*2+1][0]=tmp[2]; bHf[npair*2+1][1]=tmp[3];
            }
            #pragma unroll
            for (int mt = 0; mt < 2; mt++)
                #pragma unroll
                for (int nt = 0; nt < 8; nt++)
                    mma_f16(acc[mt][nt], aH[mt], bHf[nt]);
        }
    }
    #undef BT
    CP_WAIT0();

    int g = lane >> 2, tg = lane & 3;
    if (outT) {
        // direct transposed fp16 stores: thread owns rows y=ty0+w*2+mt, x=tx0+g(+8), oc=nt*8+tg*2(+1)
        #pragma unroll
        for (int mt = 0; mt < 2; mt++) {
            int y = ty0 + w*2 + mt;
            if (y >= H) continue;
            #pragma unroll
            for (int xo = 0; xo < 2; xo++) {
                int x = tx0 + g + xo*8;
                if (x >= W) continue;
                __half* dst = outT + ((size_t)(b*H + y)*W + x)*64;
                #pragma unroll
                for (int nt = 0; nt < 8; nt++) {
                    int oc = nt*8 + tg*2;
                    float c0 = fmaxf(acc[mt][nt][xo*2+0] + bias[oc],   0.f);
                    float c1 = fmaxf(acc[mt][nt][xo*2+1] + bias[oc+1], 0.f);
                    *(__half2*)(dst + oc) = __floats2half2_rn(c0, c1);
                }
            }
        }
    } else {
        float* smf = (float*)sm;
        #pragma unroll
        for (int p = 0; p < 2; p++) {
            __syncthreads();
            if ((w >> 3) == p) {
                int wl = w & 7;
                #pragma unroll
                for (int mt = 0; mt < 2; mt++) {
                    int rb = (wl*2 + mt)*16 + g;
                    #pragma unroll
                    for (int nt = 0; nt < 8; nt++) {
                        int cb = nt*8 + tg*2;
                        smf[(cb+0)*260 + rb]     = acc[mt][nt][0];
                        smf[(cb+1)*260 + rb]     = acc[mt][nt][1];
                        smf[(cb+0)*260 + rb + 8] = acc[mt][nt][2];
                        smf[(cb+1)*260 + rb + 8] = acc[mt][nt][3];
                    }
                }
            }
            __syncthreads();
            for (int i = t; i < 16384; i += 512) {
                int oc = i >> 8, r = i & 255;
                int y = ty0 + p*16 + (r >> 4), x = tx0 + (r & 15);
                if (y < H && x < W)
                    outF[((size_t)(b*64 + oc)*H + y)*W + x] =
                        fmaxf(smf[oc*260 + r] + bias[oc], 0.f);
            }
        }
    }
}

extern "C" void kernel_launch(void* const* d_in, const int* in_sizes, int n_in,
                              void* d_out, int out_size) {
    (void)out_size;
    const float* voxels[3] = {0,0,0};
    const int* numpts[3] = {0,0,0};
    const int* coordsp[3] = {0,0,0};
    const float *w1=0,*w2=0,*fw=0;
    const float* p192[8] = {0};
    const float* p128[4] = {0};
    int n192 = 0, n128 = 0;
    for (int i = 0; i < n_in; i++) {
        int sz = in_sizes[i];
        const void* p = d_in[i];
        switch (sz) {
            case 5120000: voxels[0] = (const float*)p; break;
            case 2560000: voxels[1] = (const float*)p; break;
            case 1024000: voxels[2] = (const float*)p; break;
            case 40000:   numpts[0] = (const int*)p; break;
            case 20000:   numpts[1] = (const int*)p; break;
            case 8000:    numpts[2] = (const int*)p; break;
            case 160000:  coordsp[0] = (const int*)p; break;
            case 80000:   coordsp[1] = (const int*)p; break;
            case 32000:   coordsp[2] = (const int*)p; break;
            case 1728:    w1 = (const float*)p; break;
            case 24576:   w2 = (const float*)p; break;
            case 147456:  fw = (const float*)p; break;
            case 192:     if (n192 < 8) p192[n192++] = (const float*)p; break;
            case 128:     if (n128 < 4) p128[n128++] = (const float*)p; break;
            default: break;
        }
    }
    const float *g1=p192[0], *b1=p192[1], *rm1=p192[2], *rv1=p192[3];
    const float *g2=p192[4], *b2=p192[5], *rm2=p192[6], *rv2=p192[7];
    const float *fg=p128[0], *fb=p128[1], *fm=p128[2], *fv=p128[3];

    __half *cat0, *cat1, *sf2t, *f1t;
    cudaGetSymbolAddress((void**)&cat0, g_cat0t);
    cudaGetSymbolAddress((void**)&cat1, g_cat1t);
    cudaGetSymbolAddress((void**)&sf2t, g_sf2t);
    cudaGetSymbolAddress((void**)&f1t,  g_f1t);
    float *vf0, *vf1, *vf2, *w1f, *b1f, *w2f, *b2f, *fbf;
    int *win0, *win1, *win2;
    unsigned char* wimg;
    cudaGetSymbolAddress((void**)&vf0, g_vf0);
    cudaGetSymbolAddress((void**)&vf1, g_vf1);
    cudaGetSymbolAddress((void**)&vf2, g_vf2);
    cudaGetSymbolAddress((void**)&win0, g_win0);
    cudaGetSymbolAddress((void**)&win1, g_win1);
    cudaGetSymbolAddress((void**)&win2, g_win2);
    cudaGetSymbolAddress((void**)&w1f, g_w1f);
    cudaGetSymbolAddress((void**)&b1f, g_b1f);
    cudaGetSymbolAddress((void**)&w2f, g_w2f);
    cudaGetSymbolAddress((void**)&b2f, g_b2f);
    cudaGetSymbolAddress((void**)&fbf, g_fbf);
    cudaGetSymbolAddress((void**)&wimg, g_wimg);

    static cudaStream_t s1 = 0, s2 = 0;
    static cudaEvent_t eInit = 0, e0 = 0, e1 = 0;
    static int inited = 0;
    if (!inited) {
        cudaStreamCreateWithFlags(&s1, cudaStreamNonBlocking);
        cudaStreamCreateWithFlags(&s2, cudaStreamNonBlocking);
        cudaEventCreateWithFlags(&eInit, cudaEventDisableTiming);
        cudaEventCreateWithFlags(&e0, cudaEventDisableTiming);
        cudaEventCreateWithFlags(&e1, cudaEventDisableTiming);
        cudaFuncSetAttribute(conv_mma_kernel, cudaFuncAttributeMaxDynamicSharedMemorySize, CONV_SMEM);
        cudaFuncSetAttribute(vfe_kernel, cudaFuncAttributeMaxDynamicSharedMemorySize, VFE_SMEM);
        inited = 1;
    }

    fold_kernel<<<1152, 256>>>(w1, g1, b1, rm1, rv1, w2, g2, b2, rm2, rv2, fw, fg, fb, fm, fv);
    cudaEventRecord(eInit, 0);

    // branch s1: zero cat1 chunk0 + scale 1
    cudaStreamWaitEvent(s1, eInit, 0);
    zero_u4<<<1024, 256, 0, s1>>>((uint4*)cat1, PE1/2);
    vfe_kernel<<<(NS_[1]+3)/4, 256, VFE_SMEM, s1>>>(voxels[1], numpts[1], w1f + 576, b1f + 64, w2f + 8192, b2f + 64, vf1, NS_[1]);
    fill_win_kernel<<<(BATCH*HW1 + 255)/256, 256, 0, s1>>>(win1, BATCH*HW1);
    scatter_max_kernel<<<(NS_[1] + 255)/256, 256, 0, s1>>>(coordsp[1], win1, NS_[1], H1, W1);
    scatter_write_f16<<<NS_[1], 64, 0, s1>>>(coordsp[1], win1, vf1, cat1, PE1, H1, W1, WP1);
    cudaEventRecord(e1, s1);

    // branch s2: zero cat0 chunk0 + scale 0
    cudaStreamWaitEvent(s2, eInit, 0);
    zero_u4<<<2048, 256, 0, s2>>>((uint4*)cat0, PE0/2);
    vfe_kernel<<<(NS_[0]+3)/4, 256, VFE_SMEM, s2>>>(voxels[0], numpts[0], w1f, b1f, w2f, b2f, vf0, NS_[0]);
    fill_win_kernel<<<(BATCH*HW0 + 255)/256, 256, 0, s2>>>(win0, BATCH*HW0);
    scatter_max_kernel<<<(NS_[0] + 255)/256, 256, 0, s2>>>(coordsp[0], win0, NS_[0], H0, W0);
    scatter_write_f16<<<NS_[0], 64, 0, s2>>>(coordsp[0], win0, vf0, cat0, PE0, H0, W0, WP0);
    cudaEventRecord(e0, s2);

    // main: scale 2 critical path -> sf2t
    init_sf2t_win2<<<512, 256>>>((uint4*)sf2t, (size_t)BATCH*HW2*8, win2, BATCH*HW2);
    vfe_kernel<<<(NS_[2]+3)/4, 256, VFE_SMEM>>>(voxels[2], numpts[2], w1f + 1152, b1f + 128, w2f + 16384, b2f + 128, vf2, NS_[2]);
    scatter_max_kernel<<<(NS_[2] + 255)/256, 256>>>(coordsp[2], win2, NS_[2], H2, W2);
    scatter_write_sf2t<<<NS_[2], 64>>>(coordsp[2], win2, vf2, sf2t);

    // conv1: cat1 chunk0 + bilinear(sf2t) -> f1t (transposed fp16)
    cudaStreamWaitEvent(0, e1, 0);
    {
        dim3 g((W1 + 15)/16, (H1 + TILE_H - 1)/TILE_H, BATCH);
        conv_mma_kernel<<<g, 512, CONV_SMEM>>>(cat1, PE1, sf2t, H2, W2, WP1, H1, W1,
            (const uint4*)(wimg + 147456), fbf + 64, (float*)0, f1t);
    }
    // conv0: cat0 chunk0 + bilinear(f1t) -> d_out (f32 NCHW)
    cudaStreamWaitEvent(0, e0, 0);
    {
        dim3 g((W0 + 15)/16, (H0 + TILE_H - 1)/TILE_H, BATCH);
        conv_mma_kernel<<<g, 512, CONV_SMEM>>>(cat0, PE0, f1t, H1, W1, WP0, H0, W0,
            (const uint4*)wimg, fbf, (float*)d_out, (__half*)0);
    }
}